// round 1
// baseline (speedup 1.0000x reference)
#include <cuda_runtime.h>
#include <math.h>
#include <stdint.h>

#define BATCH   2
#define SEQLEN  4096
#define DMODEL  1024
#define DINNER  2048
#define HEADDIM 64
#define NHEADS  32
#define DSTATE  128
#define DCONV   4
#define CHUNK   256
#define NCHUNK  (SEQLEN / CHUNK)   // 16
#define NBC     (BATCH * NCHUNK)   // 32
#define DPROJ   4384               // 2*DINNER + 2*DSTATE + NHEADS
#define CONVDIM 2304               // DINNER + 2*DSTATE
#define DT_OFF  4352               // 2*DINNER + 2*DSTATE
#define ROWS    (BATCH * SEQLEN)   // 8192

// ---------------- scratch (device globals; no allocation allowed) ----------
__device__ float g_zxbcdt[(size_t)ROWS * DPROJ];                 // 143.6 MB
__device__ float g_xBC[(size_t)ROWS * CONVDIM];                  // 75.5 MB
__device__ float g_dt[ROWS * NHEADS];                            // 1 MB
__device__ float g_acs[NBC * NHEADS * CHUNK];                    // 1 MB
__device__ float g_asum[NBC * NHEADS];
__device__ float g_CB[(size_t)NBC * CHUNK * CHUNK];              // 8.4 MB
__device__ float g_Y[(size_t)ROWS * DINNER];                     // 67 MB
__device__ float g_S[(size_t)NBC * NHEADS * HEADDIM * DSTATE];   // 33.5 MB
__device__ float g_Sinit[(size_t)NBC * NHEADS * HEADDIM * DSTATE];
__device__ float g_yg[(size_t)ROWS * DINNER];                    // 67 MB

// ---------------- generic fp32 SGEMM: C[M,N] = A[M,K] * B[K,N] -------------
// 128x128 block tile, BK=8, 256 threads, 8x8 microtile. M%128==0, K%8==0.
__global__ __launch_bounds__(256) void sgemm_kernel(
    const float* __restrict__ A, const float* __restrict__ B,
    float* __restrict__ C, int M, int N, int K)
{
    __shared__ float As[8][128];
    __shared__ float Bs[8][128];
    const int tid  = threadIdx.x;
    const int trow = tid >> 4;        // 0..15
    const int tcol = tid & 15;        // 0..15
    const int rowBase = blockIdx.y * 128;
    const int colBase = blockIdx.x * 128;
    const int aRow = tid >> 1;
    const int aCol = (tid & 1) << 2;
    const int bRow = tid >> 5;
    const int bCol = (tid & 31) << 2;

    float acc[8][8];
#pragma unroll
    for (int i = 0; i < 8; i++)
#pragma unroll
        for (int j = 0; j < 8; j++) acc[i][j] = 0.f;

    for (int k0 = 0; k0 < K; k0 += 8) {
        float4 av = *(const float4*)(A + (size_t)(rowBase + aRow) * K + k0 + aCol);
        As[aCol + 0][aRow] = av.x;
        As[aCol + 1][aRow] = av.y;
        As[aCol + 2][aRow] = av.z;
        As[aCol + 3][aRow] = av.w;
        int bc = colBase + bCol;
        float4 bv = make_float4(0.f, 0.f, 0.f, 0.f);
        if (bc < N) bv = *(const float4*)(B + (size_t)(k0 + bRow) * N + bc);
        *(float4*)&Bs[bRow][bCol] = bv;
        __syncthreads();
#pragma unroll
        for (int k = 0; k < 8; k++) {
            float ra[8], rb[8];
            *(float4*)&ra[0] = *(const float4*)&As[k][trow * 8];
            *(float4*)&ra[4] = *(const float4*)&As[k][trow * 8 + 4];
            *(float4*)&rb[0] = *(const float4*)&Bs[k][tcol * 8];
            *(float4*)&rb[4] = *(const float4*)&Bs[k][tcol * 8 + 4];
#pragma unroll
            for (int i = 0; i < 8; i++)
#pragma unroll
                for (int j = 0; j < 8; j++)
                    acc[i][j] += ra[i] * rb[j];
        }
        __syncthreads();
    }
#pragma unroll
    for (int i = 0; i < 8; i++) {
        int row = rowBase + trow * 8 + i;
#pragma unroll
        for (int j4 = 0; j4 < 2; j4++) {
            int col = colBase + tcol * 8 + j4 * 4;
            if (col < N) {
                float4 o = make_float4(acc[i][j4*4+0], acc[i][j4*4+1],
                                       acc[i][j4*4+2], acc[i][j4*4+3]);
                *(float4*)(C + (size_t)row * N + col) = o;
            }
        }
    }
}

// ---------------- causal depthwise conv1d (width 4) + SiLU -----------------
__global__ void conv_silu_kernel(const float* __restrict__ conv_w,
                                 const float* __restrict__ conv_b)
{
    int idx = blockIdx.x * blockDim.x + threadIdx.x;
    if (idx >= ROWS * CONVDIM) return;
    int c   = idx % CONVDIM;
    int row = idx / CONVDIM;
    int l   = row & (SEQLEN - 1);
    const float* base = g_zxbcdt + (size_t)row * DPROJ + DINNER + c;
    float acc = conv_b[c];
#pragma unroll
    for (int j = 0; j < DCONV; j++) {
        int ls = l - (DCONV - 1) + j;
        if (ls >= 0) acc += base[(long)(j - (DCONV - 1)) * DPROJ] * conv_w[c * DCONV + j];
    }
    g_xBC[(size_t)row * CONVDIM + c] = acc / (1.f + expf(-acc));
}

// ---------------- dt = softplus(dt_raw + dt_bias) --------------------------
__global__ void dt_kernel(const float* __restrict__ dt_bias)
{
    int idx = blockIdx.x * blockDim.x + threadIdx.x;
    if (idx >= ROWS * NHEADS) return;
    int h   = idx & (NHEADS - 1);
    int row = idx >> 5;
    float v = g_zxbcdt[(size_t)row * DPROJ + DT_OFF + h] + dt_bias[h];
    g_dt[idx] = (v > 20.f) ? v : log1pf(expf(v));
}

// ---------------- per-chunk inclusive cumsum of a = A*dt -------------------
__global__ void ascan_kernel(const float* __restrict__ A_log)
{
    int bc = blockIdx.x;           // 0..NBC-1
    int h  = blockIdx.y;
    int t  = threadIdx.x;          // 0..255
    int b = bc >> 4, c = bc & 15;
    __shared__ float sa[CHUNK];
    int row = b * SEQLEN + c * CHUNK + t;
    float A = -expf(A_log[h]);
    sa[t] = A * g_dt[row * NHEADS + h];
    __syncthreads();
    for (int off = 1; off < CHUNK; off <<= 1) {
        float v = (t >= off) ? sa[t - off] : 0.f;
        __syncthreads();
        sa[t] += v;
        __syncthreads();
    }
    g_acs[(bc * NHEADS + h) * CHUNK + t] = sa[t];
    if (t == CHUNK - 1) g_asum[bc * NHEADS + h] = sa[t];
}

// ---------------- CB[l,s] = sum_n C[l,n] * B[s,n]  (head-independent!) -----
__global__ __launch_bounds__(256) void cb_kernel()
{
    int bc = blockIdx.x;
    int lt = blockIdx.y;   // 64-row l-tile
    int st = blockIdx.z;   // 64-row s-tile
    if (st > lt) return;   // strictly-upper tiles never read (causal)
    int b = bc >> 4, c = bc & 15;
    int t = threadIdx.x;
    int ty = t >> 4, tx = t & 15;
    __shared__ float Ct[32][68];
    __shared__ float Bt[32][68];
    size_t rowB = (size_t)b * SEQLEN + c * CHUNK;
    float acc[4][4];
#pragma unroll
    for (int i = 0; i < 4; i++)
#pragma unroll
        for (int j = 0; j < 4; j++) acc[i][j] = 0.f;

    for (int n0 = 0; n0 < DSTATE; n0 += 32) {
        for (int v = t; v < 512; v += 256) {
            int r = v >> 3, n4 = v & 7;
            float4 cv = *(const float4*)(g_xBC + (rowB + lt*64 + r) * CONVDIM
                                         + (DINNER + DSTATE) + n0 + n4*4);
            Ct[n4*4+0][r]=cv.x; Ct[n4*4+1][r]=cv.y; Ct[n4*4+2][r]=cv.z; Ct[n4*4+3][r]=cv.w;
            float4 bvv = *(const float4*)(g_xBC + (rowB + st*64 + r) * CONVDIM
                                          + DINNER + n0 + n4*4);
            Bt[n4*4+0][r]=bvv.x; Bt[n4*4+1][r]=bvv.y; Bt[n4*4+2][r]=bvv.z; Bt[n4*4+3][r]=bvv.w;
        }
        __syncthreads();
#pragma unroll
        for (int n = 0; n < 32; n++) {
            float4 ca = *(const float4*)&Ct[n][ty*4];
            float4 bb = *(const float4*)&Bt[n][tx*4];
            float ra[4] = {ca.x, ca.y, ca.z, ca.w};
            float rb[4] = {bb.x, bb.y, bb.z, bb.w};
#pragma unroll
            for (int i = 0; i < 4; i++)
#pragma unroll
                for (int j = 0; j < 4; j++) acc[i][j] += ra[i] * rb[j];
        }
        __syncthreads();
    }
#pragma unroll
    for (int i = 0; i < 4; i++) {
        int l = lt*64 + ty*4 + i;
        float4 o = make_float4(acc[i][0], acc[i][1], acc[i][2], acc[i][3]);
        *(float4*)(g_CB + ((size_t)bc * CHUNK + l) * CHUNK + st*64 + tx*4) = o;
    }
}

// ---------------- Y_diag per (b,c,h): thread = row l, 64 accumulators ------
__global__ __launch_bounds__(256, 1) void ydiag_kernel()
{
    int bc = blockIdx.x, h = blockIdx.y;
    int b = bc >> 4, c = bc & 15;
    int t = threadIdx.x;                   // l within chunk
    __shared__ float Xw[128][68];          // X * dt, staged tile [s][p]
    __shared__ float sacs[CHUNK];
    __shared__ float sdt[CHUNK];
    size_t rowB = (size_t)b * SEQLEN + c * CHUNK;
    sacs[t] = g_acs[((size_t)bc * NHEADS + h) * CHUNK + t];
    sdt[t]  = g_dt[(rowB + t) * NHEADS + h];
    float acc[64];
#pragma unroll
    for (int i = 0; i < 64; i++) acc[i] = 0.f;
    const float* CBrow = g_CB + ((size_t)bc * CHUNK + t) * CHUNK;
    __syncthreads();
    float acs_l = sacs[t];

    for (int stile = 0; stile < CHUNK; stile += 128) {
        int r  = t >> 1;
        int f0 = (t & 1) * 8;
        const float4* src = (const float4*)(g_xBC + (rowB + stile + r) * CONVDIM
                                            + h * HEADDIM) + f0;
        float dts = sdt[stile + r];
#pragma unroll
        for (int i = 0; i < 8; i++) {
            float4 v = src[i];
            int cc = (f0 + i) * 4;
            Xw[r][cc+0] = v.x * dts;
            Xw[r][cc+1] = v.y * dts;
            Xw[r][cc+2] = v.z * dts;
            Xw[r][cc+3] = v.w * dts;
        }
        __syncthreads();
        int smax = t - stile + 1;
        if (smax > 128) smax = 128;
        for (int s = 0; s < smax; s++) {
            float coef = __ldg(CBrow + stile + s) * __expf(acs_l - sacs[stile + s]);
            const float4* xr = (const float4*)&Xw[s][0];
#pragma unroll
            for (int i = 0; i < 16; i++) {
                float4 xv = xr[i];
                acc[4*i+0] += coef * xv.x;
                acc[4*i+1] += coef * xv.y;
                acc[4*i+2] += coef * xv.z;
                acc[4*i+3] += coef * xv.w;
            }
        }
        __syncthreads();
    }
    float* yout = g_Y + (rowB + t) * DINNER + h * HEADDIM;
#pragma unroll
    for (int i = 0; i < 16; i++)
        *(float4*)(yout + 4*i) = make_float4(acc[4*i], acc[4*i+1], acc[4*i+2], acc[4*i+3]);
}

// ---------------- per-chunk state S[p,n] = sum_s w[s] x[s,p] B[s,n] --------
__global__ __launch_bounds__(256, 1) void state_kernel()
{
    int bc = blockIdx.x, h = blockIdx.y;
    int b = bc >> 4, c = bc & 15;
    int t = threadIdx.x;
    __shared__ float Bs[64][132];
    __shared__ float warr[64];
    size_t rowB = (size_t)b * SEQLEN + c * CHUNK;
    float asum = g_asum[bc * NHEADS + h];
    int p  = t >> 2;             // 0..63
    int nq = (t & 3) * 4;        // interleaved n base
    const float* xptr = g_xBC + rowB * CONVDIM + h * HEADDIM + p;
    float4 acc4[8];
#pragma unroll
    for (int i = 0; i < 8; i++) acc4[i] = make_float4(0.f, 0.f, 0.f, 0.f);

    for (int stile = 0; stile < CHUNK; stile += 64) {
        {
            int r = t >> 2, q = (t & 3) * 32;
            const float4* src = (const float4*)(g_xBC + (rowB + stile + r) * CONVDIM
                                                + DINNER + q);
#pragma unroll
            for (int i = 0; i < 8; i++)
                *(float4*)&Bs[r][q + i*4] = src[i];
        }
        if (t < 64) {
            int gl = stile + t;
            warr[t] = g_dt[(rowB + gl) * NHEADS + h] *
                      __expf(asum - g_acs[((size_t)bc * NHEADS + h) * CHUNK + gl]);
        }
        __syncthreads();
        for (int s = 0; s < 64; s++) {
            float xv = __ldg(xptr + (size_t)(stile + s) * CONVDIM) * warr[s];
#pragma unroll
            for (int i = 0; i < 8; i++) {
                float4 bv = *(const float4*)&Bs[s][nq + 16*i];
                acc4[i].x += xv * bv.x;
                acc4[i].y += xv * bv.y;
                acc4[i].z += xv * bv.z;
                acc4[i].w += xv * bv.w;
            }
        }
        __syncthreads();
    }
    float* Sout = g_S + (((size_t)bc * NHEADS + h) * HEADDIM + p) * DSTATE;
#pragma unroll
    for (int i = 0; i < 8; i++)
        *(float4*)(Sout + nq + 16*i) = acc4[i];
}

// ---------------- sequential inter-chunk recurrence over 16 chunks ---------
__global__ void chunkrec_kernel()
{
    int b = blockIdx.x, h = blockIdx.y;
    int t = threadIdx.x;
    float cur[32];
#pragma unroll
    for (int k = 0; k < 32; k++) cur[k] = 0.f;
    for (int c = 0; c < NCHUNK; c++) {
        int bc = b * NCHUNK + c;
        size_t base = ((size_t)bc * NHEADS + h) * (HEADDIM * DSTATE);
        float d = __expf(g_asum[bc * NHEADS + h]);
#pragma unroll
        for (int k = 0; k < 32; k++) {
            size_t e = base + t + 256 * k;
            g_Sinit[e] = cur[k];
            cur[k] = cur[k] * d + g_S[e];
        }
    }
}

// ---------------- Y += exp(acs[l]) * C[l,:] . Sinit[:, :] ------------------
__global__ __launch_bounds__(256, 1) void yoff_kernel()
{
    int bc = blockIdx.x, h = blockIdx.y;
    int b = bc >> 4, c = bc & 15;
    int t = threadIdx.x;                   // l
    __shared__ float St[DSTATE][68];       // transposed Sinit: [n][p]
    __shared__ float sacs[CHUNK];
    sacs[t] = g_acs[((size_t)bc * NHEADS + h) * CHUNK + t];
    const float* S0 = g_Sinit + ((size_t)bc * NHEADS + h) * (HEADDIM * DSTATE);
    {
        int p = t >> 2, nb = (t & 3) * 32;
#pragma unroll
        for (int i = 0; i < 32; i += 4) {
            float4 v = *(const float4*)(S0 + p * DSTATE + nb + i);
            St[nb+i+0][p] = v.x;
            St[nb+i+1][p] = v.y;
            St[nb+i+2][p] = v.z;
            St[nb+i+3][p] = v.w;
        }
    }
    __syncthreads();
    float off[64];
#pragma unroll
    for (int i = 0; i < 64; i++) off[i] = 0.f;
    size_t rowI = (size_t)b * SEQLEN + c * CHUNK + t;
    const float* Crow = g_xBC + rowI * CONVDIM + (DINNER + DSTATE);
    for (int n = 0; n < DSTATE; n++) {
        float cl = __ldg(Crow + n);
        const float4* sr = (const float4*)&St[n][0];
#pragma unroll
        for (int i = 0; i < 16; i++) {
            float4 sv = sr[i];
            off[4*i+0] += cl * sv.x;
            off[4*i+1] += cl * sv.y;
            off[4*i+2] += cl * sv.z;
            off[4*i+3] += cl * sv.w;
        }
    }
    float el = __expf(sacs[t]);
    float* yout = g_Y + rowI * DINNER + h * HEADDIM;
#pragma unroll
    for (int i = 0; i < 16; i++) {
        float4 yd = *(const float4*)(yout + 4*i);
        yd.x += el * off[4*i+0];
        yd.y += el * off[4*i+1];
        yd.z += el * off[4*i+2];
        yd.w += el * off[4*i+3];
        *(float4*)(yout + 4*i) = yd;
    }
}

// ---------------- layernorm (mean/var) + z-gate ----------------------------
__global__ __launch_bounds__(256) void normgate_kernel(const float* __restrict__ norm_w)
{
    int row = blockIdx.x;
    int t = threadIdx.x;
    const float* yrow = g_Y + (size_t)row * DINNER;
    const float* zrow = g_zxbcdt + (size_t)row * DPROJ;
    float v[8];
    float s = 0.f;
#pragma unroll
    for (int i = 0; i < 8; i++) { v[i] = yrow[t + 256*i]; s += v[i]; }
    __shared__ float red[256];
    red[t] = s; __syncthreads();
    for (int o = 128; o > 0; o >>= 1) { if (t < o) red[t] += red[t+o]; __syncthreads(); }
    float mu = red[0] * (1.f / DINNER);
    __syncthreads();
    float s2 = 0.f;
#pragma unroll
    for (int i = 0; i < 8; i++) { float d = v[i] - mu; s2 += d * d; }
    red[t] = s2; __syncthreads();
    for (int o = 128; o > 0; o >>= 1) { if (t < o) red[t] += red[t+o]; __syncthreads(); }
    float inv = rsqrtf(red[0] * (1.f / DINNER) + 1e-5f);
    float* orow = g_yg + (size_t)row * DINNER;
#pragma unroll
    for (int i = 0; i < 8; i++) {
        int idx = t + 256*i;
        float z = zrow[idx];
        float g = z / (1.f + expf(-z));
        orow[idx] = (v[i] - mu) * inv * norm_w[idx] * g;
    }
}

// ---------------- launch ---------------------------------------------------
extern "C" void kernel_launch(void* const* d_in, const int* in_sizes, int n_in,
                              void* d_out, int out_size)
{
    const float* u       = (const float*)d_in[0];
    const float* W_in    = (const float*)d_in[1];
    const float* conv_w  = (const float*)d_in[2];
    const float* conv_b  = (const float*)d_in[3];
    const float* dt_bias = (const float*)d_in[4];
    const float* A_log   = (const float*)d_in[5];
    const float* norm_w  = (const float*)d_in[6];
    const float* W_out   = (const float*)d_in[7];
    float* out = (float*)d_out;

    float *p_zx = nullptr, *p_yg = nullptr;
    cudaGetSymbolAddress((void**)&p_zx, g_zxbcdt);
    cudaGetSymbolAddress((void**)&p_yg, g_yg);

    // 1. zxbcdt = u @ W_in   (8192 x 4384 x 1024)
    sgemm_kernel<<<dim3((DPROJ + 127) / 128, ROWS / 128), 256>>>(
        u, W_in, p_zx, ROWS, DPROJ, DMODEL);
    // 2. causal conv1d + SiLU on xBC slice
    conv_silu_kernel<<<(ROWS * CONVDIM + 255) / 256, 256>>>(conv_w, conv_b);
    // 3. dt softplus
    dt_kernel<<<(ROWS * NHEADS + 255) / 256, 256>>>(dt_bias);
    // 4. per-chunk cumsum of A*dt
    ascan_kernel<<<dim3(NBC, NHEADS), CHUNK>>>(A_log);
    // 5. head-independent CB gram matrices
    cb_kernel<<<dim3(NBC, 4, 4), 256>>>();
    // 6. intra-chunk causal Y_diag
    ydiag_kernel<<<dim3(NBC, NHEADS), 256>>>();
    // 7. per-chunk end states
    state_kernel<<<dim3(NBC, NHEADS), 256>>>();
    // 8. inter-chunk recurrence (sequential over 16 chunks)
    chunkrec_kernel<<<dim3(BATCH, NHEADS), 256>>>();
    // 9. inter-chunk contribution Y_off
    yoff_kernel<<<dim3(NBC, NHEADS), 256>>>();
    // 10. layernorm + silu(z) gate
    normgate_kernel<<<ROWS, 256>>>(norm_w);
    // 11. out = yg @ W_out   (8192 x 1024 x 2048)
    sgemm_kernel<<<dim3(DMODEL / 128, ROWS / 128), 256>>>(
        p_yg, W_out, out, ROWS, DMODEL, DINNER);
}

// round 2
// speedup vs baseline: 1.5883x; 1.5883x over previous
#include <cuda_runtime.h>
#include <cuda_bf16.h>
#include <math.h>
#include <stdint.h>

#define BATCH   2
#define SEQLEN  4096
#define DMODEL  1024
#define DINNER  2048
#define HEADDIM 64
#define NHEADS  32
#define DSTATE  128
#define DCONV   4
#define CHUNK   256
#define NCHUNK  (SEQLEN / CHUNK)   // 16
#define NBC     (BATCH * NCHUNK)   // 32
#define DPROJ   4384               // 2*DINNER + 2*DSTATE + NHEADS
#define CONVDIM 2304               // DINNER + 2*DSTATE
#define DT_OFF  4352               // 2*DINNER + 2*DSTATE
#define ROWS    (BATCH * SEQLEN)   // 8192
#define NPAD1   4480               // DPROJ padded to multiple of 128

// ---------------- scratch (device globals; no allocation allowed) ----------
__device__ float g_zxbcdt[(size_t)ROWS * DPROJ];
__device__ float g_xBC[(size_t)ROWS * CONVDIM];
__device__ float g_dt[ROWS * NHEADS];
__device__ float g_acs[NBC * NHEADS * CHUNK];
__device__ float g_asum[NBC * NHEADS];
__device__ float g_CB[(size_t)NBC * CHUNK * CHUNK];
__device__ float g_Y[(size_t)ROWS * DINNER];
__device__ float g_S[(size_t)NBC * NHEADS * HEADDIM * DSTATE];
__device__ float g_Sinit[(size_t)NBC * NHEADS * HEADDIM * DSTATE];

// split bf16 operands
__device__ __nv_bfloat16 g_uh[(size_t)ROWS * DMODEL];
__device__ __nv_bfloat16 g_ul[(size_t)ROWS * DMODEL];
__device__ __nv_bfloat16 g_wih[(size_t)DMODEL * NPAD1];
__device__ __nv_bfloat16 g_wil[(size_t)DMODEL * NPAD1];
__device__ __nv_bfloat16 g_woh[(size_t)DINNER * DMODEL];
__device__ __nv_bfloat16 g_wol[(size_t)DINNER * DMODEL];
__device__ __nv_bfloat16 g_ygh[(size_t)ROWS * DINNER];
__device__ __nv_bfloat16 g_ygl[(size_t)ROWS * DINNER];

// ---------------- helpers ---------------------------------------------------
__device__ __forceinline__ uint32_t s2u(const void* p) {
    return (uint32_t)__cvta_generic_to_shared(p);
}
#define CP16(dst, src) \
    asm volatile("cp.async.cg.shared.global [%0], [%1], 16;\n" :: "r"(dst), "l"(src))
#define CP_COMMIT() asm volatile("cp.async.commit_group;\n")
#define CP_WAIT1()  asm volatile("cp.async.wait_group 1;\n")
#define CP_WAIT0()  asm volatile("cp.async.wait_group 0;\n")

__device__ __forceinline__ void ldsm4(uint32_t& r0, uint32_t& r1, uint32_t& r2,
                                      uint32_t& r3, uint32_t addr) {
    asm volatile("ldmatrix.sync.aligned.m8n8.x4.shared.b16 {%0,%1,%2,%3}, [%4];"
                 : "=r"(r0), "=r"(r1), "=r"(r2), "=r"(r3) : "r"(addr));
}
__device__ __forceinline__ void ldsm4t(uint32_t& r0, uint32_t& r1, uint32_t& r2,
                                       uint32_t& r3, uint32_t addr) {
    asm volatile("ldmatrix.sync.aligned.m8n8.x4.trans.shared.b16 {%0,%1,%2,%3}, [%4];"
                 : "=r"(r0), "=r"(r1), "=r"(r2), "=r"(r3) : "r"(addr));
}
__device__ __forceinline__ void mma16816(float* d, const uint32_t* a, const uint32_t* b) {
    asm volatile(
        "mma.sync.aligned.m16n8k16.row.col.f32.bf16.bf16.f32 "
        "{%0,%1,%2,%3}, {%4,%5,%6,%7}, {%8,%9}, {%0,%1,%2,%3};"
        : "+f"(d[0]), "+f"(d[1]), "+f"(d[2]), "+f"(d[3])
        : "r"(a[0]), "r"(a[1]), "r"(a[2]), "r"(a[3]), "r"(b[0]), "r"(b[1]));
}

// ---------------- split-bf16 convert kernels --------------------------------
__global__ void split_kernel(const float* __restrict__ x, __nv_bfloat16* __restrict__ hi,
                             __nv_bfloat16* __restrict__ lo, size_t n)
{
    size_t i = (size_t)blockIdx.x * blockDim.x + threadIdx.x;
    if (i >= n) return;
    float v = x[i];
    __nv_bfloat16 h = __float2bfloat16(v);
    hi[i] = h;
    lo[i] = __float2bfloat16(v - __bfloat162float(h));
}

__global__ void split_pad_kernel(const float* __restrict__ x, __nv_bfloat16* __restrict__ hi,
                                 __nv_bfloat16* __restrict__ lo, int K, int N, int Np)
{
    size_t i = (size_t)blockIdx.x * blockDim.x + threadIdx.x;
    if (i >= (size_t)K * Np) return;
    int r = (int)(i / Np), c = (int)(i % Np);
    float v = (c < N) ? x[(size_t)r * N + c] : 0.f;
    __nv_bfloat16 h = __float2bfloat16(v);
    hi[i] = h;
    lo[i] = __float2bfloat16(v - __bfloat162float(h));
}

// ---------------- split-bf16 tensor-core GEMM -------------------------------
// C[M,N] = (Ah+Al)[M,K] * (Bh+Bl)[K,N] (3-term), A row-major lda=K,
// B row-major ldb (>=N, tile-padded), C fp32 row-major ldc, guard col<N.
// 128x128 block tile, BK=16, 512 threads (16 warps, 4x4), warp tile 32x32.
__global__ __launch_bounds__(512, 1) void mma_gemm(
    const __nv_bfloat16* __restrict__ Ah, const __nv_bfloat16* __restrict__ Al,
    const __nv_bfloat16* __restrict__ Bh, const __nv_bfloat16* __restrict__ Bl,
    float* __restrict__ C, int M, int N, int K, int ldb, int ldc)
{
    __shared__ __nv_bfloat16 sA[2 * 2 * 128 * 24];   // [stage][hi/lo][row][k(16)+pad8]
    __shared__ __nv_bfloat16 sB[2 * 2 * 16 * 136];   // [stage][hi/lo][k][n(128)+pad8]

    const int rowBase = blockIdx.y * 128;
    const int colBase = blockIdx.x * 128;
    const int t = threadIdx.x;

    // --- async-load mapping: each thread owns one 16B A-chunk + one 16B B-chunk
    const int sel = t >> 8;          // 0 = hi, 1 = lo
    const int q   = t & 255;
    const int ar = q >> 1, ahalf = q & 1;
    const __nv_bfloat16* aS = (sel ? Al : Ah) + (size_t)(rowBase + ar) * K + ahalf * 8;
    const int br = q >> 4, bc = q & 15;
    const __nv_bfloat16* bS = (sel ? Bl : Bh) + (size_t)br * ldb + colBase + bc * 8;
    const uint32_t aD0 = s2u(&sA[((0 * 2 + sel) * 128 + ar) * 24 + ahalf * 8]);
    const uint32_t bD0 = s2u(&sB[((0 * 2 + sel) * 16 + br) * 136 + bc * 8]);
    const uint32_t aStride = 2 * 128 * 24 * 2;  // bytes per stage
    const uint32_t bStride = 2 * 16 * 136 * 2;

    float d[2][4][4];
#pragma unroll
    for (int mi = 0; mi < 2; mi++)
#pragma unroll
        for (int ni = 0; ni < 4; ni++)
#pragma unroll
            for (int k = 0; k < 4; k++) d[mi][ni][k] = 0.f;

    const int lane = t & 31, warp = t >> 5;
    const int wm = warp >> 2, wn = warp & 3;
    const int grp = lane >> 3, rr = lane & 7;

    const int nk = K / 16;
    // prologue: stage 0
    CP16(aD0, aS);
    CP16(bD0, bS);
    CP_COMMIT();

    for (int kt = 0; kt < nk; kt++) {
        if (kt + 1 < nk) {
            const uint32_t st = (kt + 1) & 1;
            const int kp = (kt + 1) * 16;
            CP16(aD0 + st * aStride, aS + kp);
            CP16(bD0 + st * bStride, bS + (size_t)kp * ldb);
            CP_COMMIT();
            CP_WAIT1();
        } else {
            CP_WAIT0();
        }
        __syncthreads();

        const int stage = kt & 1;
        uint32_t a_h[2][4], a_l[2][4], b_h[4][2], b_l[4][2];
#pragma unroll
        for (int mi = 0; mi < 2; mi++) {
            int row = wm * 32 + mi * 16 + (grp & 1) * 8 + rr;
            int kc  = (grp >> 1) * 8;
            ldsm4(a_h[mi][0], a_h[mi][1], a_h[mi][2], a_h[mi][3],
                  s2u(&sA[((stage * 2 + 0) * 128 + row) * 24 + kc]));
            ldsm4(a_l[mi][0], a_l[mi][1], a_l[mi][2], a_l[mi][3],
                  s2u(&sA[((stage * 2 + 1) * 128 + row) * 24 + kc]));
        }
#pragma unroll
        for (int pi = 0; pi < 2; pi++) {
            int kk = (grp & 1) * 8 + rr;
            int nn = wn * 32 + pi * 16 + (grp >> 1) * 8;
            ldsm4t(b_h[2 * pi][0], b_h[2 * pi][1], b_h[2 * pi + 1][0], b_h[2 * pi + 1][1],
                   s2u(&sB[((stage * 2 + 0) * 16 + kk) * 136 + nn]));
            ldsm4t(b_l[2 * pi][0], b_l[2 * pi][1], b_l[2 * pi + 1][0], b_l[2 * pi + 1][1],
                   s2u(&sB[((stage * 2 + 1) * 16 + kk) * 136 + nn]));
        }
#pragma unroll
        for (int mi = 0; mi < 2; mi++)
#pragma unroll
            for (int ni = 0; ni < 4; ni++) {
                mma16816(d[mi][ni], a_h[mi], b_h[ni]);
                mma16816(d[mi][ni], a_h[mi], b_l[ni]);
                mma16816(d[mi][ni], a_l[mi], b_h[ni]);
            }
        __syncthreads();
    }

    // epilogue
    const int r0 = rowBase + wm * 32 + (lane >> 2);
    const int c0 = colBase + wn * 32 + (lane & 3) * 2;
#pragma unroll
    for (int mi = 0; mi < 2; mi++)
#pragma unroll
        for (int ni = 0; ni < 4; ni++) {
            int col = c0 + ni * 8;
            if (col < N) {
                float2 v0 = make_float2(d[mi][ni][0], d[mi][ni][1]);
                float2 v1 = make_float2(d[mi][ni][2], d[mi][ni][3]);
                *(float2*)&C[(size_t)(r0 + mi * 16) * ldc + col] = v0;
                *(float2*)&C[(size_t)(r0 + mi * 16 + 8) * ldc + col] = v1;
            }
        }
}

// ---------------- causal depthwise conv1d (width 4) + SiLU -----------------
__global__ void conv_silu_kernel(const float* __restrict__ conv_w,
                                 const float* __restrict__ conv_b)
{
    int idx = blockIdx.x * blockDim.x + threadIdx.x;
    if (idx >= ROWS * CONVDIM) return;
    int c   = idx % CONVDIM;
    int row = idx / CONVDIM;
    int l   = row & (SEQLEN - 1);
    const float* base = g_zxbcdt + (size_t)row * DPROJ + DINNER + c;
    float acc = conv_b[c];
#pragma unroll
    for (int j = 0; j < DCONV; j++) {
        int ls = l - (DCONV - 1) + j;
        if (ls >= 0) acc += base[(long)(j - (DCONV - 1)) * DPROJ] * conv_w[c * DCONV + j];
    }
    g_xBC[(size_t)row * CONVDIM + c] = acc / (1.f + expf(-acc));
}

// ---------------- dt = softplus(dt_raw + dt_bias) --------------------------
__global__ void dt_kernel(const float* __restrict__ dt_bias)
{
    int idx = blockIdx.x * blockDim.x + threadIdx.x;
    if (idx >= ROWS * NHEADS) return;
    int h   = idx & (NHEADS - 1);
    int row = idx >> 5;
    float v = g_zxbcdt[(size_t)row * DPROJ + DT_OFF + h] + dt_bias[h];
    g_dt[idx] = (v > 20.f) ? v : log1pf(expf(v));
}

// ---------------- per-chunk inclusive cumsum of a = A*dt -------------------
__global__ void ascan_kernel(const float* __restrict__ A_log)
{
    int bc = blockIdx.x;
    int h  = blockIdx.y;
    int t  = threadIdx.x;
    int b = bc >> 4, c = bc & 15;
    __shared__ float sa[CHUNK];
    int row = b * SEQLEN + c * CHUNK + t;
    float A = -expf(A_log[h]);
    sa[t] = A * g_dt[row * NHEADS + h];
    __syncthreads();
    for (int off = 1; off < CHUNK; off <<= 1) {
        float v = (t >= off) ? sa[t - off] : 0.f;
        __syncthreads();
        sa[t] += v;
        __syncthreads();
    }
    g_acs[(bc * NHEADS + h) * CHUNK + t] = sa[t];
    if (t == CHUNK - 1) g_asum[bc * NHEADS + h] = sa[t];
}

// ---------------- CB[l,s] = sum_n C[l,n] * B[s,n]  (head-independent) ------
__global__ __launch_bounds__(256) void cb_kernel()
{
    int bc = blockIdx.x;
    int lt = blockIdx.y;
    int st = blockIdx.z;
    if (st > lt) return;
    int b = bc >> 4, c = bc & 15;
    int t = threadIdx.x;
    int ty = t >> 4, tx = t & 15;
    __shared__ float Ct[32][68];
    __shared__ float Bt[32][68];
    size_t rowB = (size_t)b * SEQLEN + c * CHUNK;
    float acc[4][4];
#pragma unroll
    for (int i = 0; i < 4; i++)
#pragma unroll
        for (int j = 0; j < 4; j++) acc[i][j] = 0.f;

    for (int n0 = 0; n0 < DSTATE; n0 += 32) {
        for (int v = t; v < 512; v += 256) {
            int r = v >> 3, n4 = v & 7;
            float4 cv = *(const float4*)(g_xBC + (rowB + lt*64 + r) * CONVDIM
                                         + (DINNER + DSTATE) + n0 + n4*4);
            Ct[n4*4+0][r]=cv.x; Ct[n4*4+1][r]=cv.y; Ct[n4*4+2][r]=cv.z; Ct[n4*4+3][r]=cv.w;
            float4 bvv = *(const float4*)(g_xBC + (rowB + st*64 + r) * CONVDIM
                                          + DINNER + n0 + n4*4);
            Bt[n4*4+0][r]=bvv.x; Bt[n4*4+1][r]=bvv.y; Bt[n4*4+2][r]=bvv.z; Bt[n4*4+3][r]=bvv.w;
        }
        __syncthreads();
#pragma unroll
        for (int n = 0; n < 32; n++) {
            float4 ca = *(const float4*)&Ct[n][ty*4];
            float4 bb = *(const float4*)&Bt[n][tx*4];
            float ra[4] = {ca.x, ca.y, ca.z, ca.w};
            float rb[4] = {bb.x, bb.y, bb.z, bb.w};
#pragma unroll
            for (int i = 0; i < 4; i++)
#pragma unroll
                for (int j = 0; j < 4; j++) acc[i][j] += ra[i] * rb[j];
        }
        __syncthreads();
    }
#pragma unroll
    for (int i = 0; i < 4; i++) {
        int l = lt*64 + ty*4 + i;
        float4 o = make_float4(acc[i][0], acc[i][1], acc[i][2], acc[i][3]);
        *(float4*)(g_CB + ((size_t)bc * CHUNK + l) * CHUNK + st*64 + tx*4) = o;
    }
}

// ---------------- Y_diag per (b,c,h) ---------------------------------------
__global__ __launch_bounds__(256, 1) void ydiag_kernel()
{
    int bc = blockIdx.x, h = blockIdx.y;
    int b = bc >> 4, c = bc & 15;
    int t = threadIdx.x;
    __shared__ float Xw[128][68];
    __shared__ float sacs[CHUNK];
    __shared__ float sdt[CHUNK];
    size_t rowB = (size_t)b * SEQLEN + c * CHUNK;
    sacs[t] = g_acs[((size_t)bc * NHEADS + h) * CHUNK + t];
    sdt[t]  = g_dt[(rowB + t) * NHEADS + h];
    float acc[64];
#pragma unroll
    for (int i = 0; i < 64; i++) acc[i] = 0.f;
    const float* CBrow = g_CB + ((size_t)bc * CHUNK + t) * CHUNK;
    __syncthreads();
    float acs_l = sacs[t];

    for (int stile = 0; stile < CHUNK; stile += 128) {
        int r  = t >> 1;
        int f0 = (t & 1) * 8;
        const float4* src = (const float4*)(g_xBC + (rowB + stile + r) * CONVDIM
                                            + h * HEADDIM) + f0;
        float dts = sdt[stile + r];
#pragma unroll
        for (int i = 0; i < 8; i++) {
            float4 v = src[i];
            int cc = (f0 + i) * 4;
            Xw[r][cc+0] = v.x * dts;
            Xw[r][cc+1] = v.y * dts;
            Xw[r][cc+2] = v.z * dts;
            Xw[r][cc+3] = v.w * dts;
        }
        __syncthreads();
        int smax = t - stile + 1;
        if (smax > 128) smax = 128;
        for (int s = 0; s < smax; s++) {
            float coef = __ldg(CBrow + stile + s) * __expf(acs_l - sacs[stile + s]);
            const float4* xr = (const float4*)&Xw[s][0];
#pragma unroll
            for (int i = 0; i < 16; i++) {
                float4 xv = xr[i];
                acc[4*i+0] += coef * xv.x;
                acc[4*i+1] += coef * xv.y;
                acc[4*i+2] += coef * xv.z;
                acc[4*i+3] += coef * xv.w;
            }
        }
        __syncthreads();
    }
    float* yout = g_Y + (rowB + t) * DINNER + h * HEADDIM;
#pragma unroll
    for (int i = 0; i < 16; i++)
        *(float4*)(yout + 4*i) = make_float4(acc[4*i], acc[4*i+1], acc[4*i+2], acc[4*i+3]);
}

// ---------------- per-chunk state S[p,n] -----------------------------------
__global__ __launch_bounds__(256, 1) void state_kernel()
{
    int bc = blockIdx.x, h = blockIdx.y;
    int b = bc >> 4, c = bc & 15;
    int t = threadIdx.x;
    __shared__ float Bs[64][132];
    __shared__ float warr[64];
    size_t rowB = (size_t)b * SEQLEN + c * CHUNK;
    float asum = g_asum[bc * NHEADS + h];
    int p  = t >> 2;
    int nq = (t & 3) * 4;
    const float* xptr = g_xBC + rowB * CONVDIM + h * HEADDIM + p;
    float4 acc4[8];
#pragma unroll
    for (int i = 0; i < 8; i++) acc4[i] = make_float4(0.f, 0.f, 0.f, 0.f);

    for (int stile = 0; stile < CHUNK; stile += 64) {
        {
            int r = t >> 2, qq = (t & 3) * 32;
            const float4* src = (const float4*)(g_xBC + (rowB + stile + r) * CONVDIM
                                                + DINNER + qq);
#pragma unroll
            for (int i = 0; i < 8; i++)
                *(float4*)&Bs[r][qq + i*4] = src[i];
        }
        if (t < 64) {
            int gl = stile + t;
            warr[t] = g_dt[(rowB + gl) * NHEADS + h] *
                      __expf(asum - g_acs[((size_t)bc * NHEADS + h) * CHUNK + gl]);
        }
        __syncthreads();
        for (int s = 0; s < 64; s++) {
            float xv = __ldg(xptr + (size_t)(stile + s) * CONVDIM) * warr[s];
#pragma unroll
            for (int i = 0; i < 8; i++) {
                float4 bv = *(const float4*)&Bs[s][nq + 16*i];
                acc4[i].x += xv * bv.x;
                acc4[i].y += xv * bv.y;
                acc4[i].z += xv * bv.z;
                acc4[i].w += xv * bv.w;
            }
        }
        __syncthreads();
    }
    float* Sout = g_S + (((size_t)bc * NHEADS + h) * HEADDIM + p) * DSTATE;
#pragma unroll
    for (int i = 0; i < 8; i++)
        *(float4*)(Sout + nq + 16*i) = acc4[i];
}

// ---------------- sequential inter-chunk recurrence ------------------------
__global__ void chunkrec_kernel()
{
    int b = blockIdx.x, h = blockIdx.y;
    int t = threadIdx.x;
    float cur[32];
#pragma unroll
    for (int k = 0; k < 32; k++) cur[k] = 0.f;
    for (int c = 0; c < NCHUNK; c++) {
        int bc = b * NCHUNK + c;
        size_t base = ((size_t)bc * NHEADS + h) * (HEADDIM * DSTATE);
        float dd = __expf(g_asum[bc * NHEADS + h]);
#pragma unroll
        for (int k = 0; k < 32; k++) {
            size_t e = base + t + 256 * k;
            g_Sinit[e] = cur[k];
            cur[k] = cur[k] * dd + g_S[e];
        }
    }
}

// ---------------- Y += exp(acs[l]) * C[l,:] . Sinit ------------------------
__global__ __launch_bounds__(256, 1) void yoff_kernel()
{
    int bc = blockIdx.x, h = blockIdx.y;
    int b = bc >> 4, c = bc & 15;
    int t = threadIdx.x;
    __shared__ float St[DSTATE][68];
    __shared__ float sacs[CHUNK];
    sacs[t] = g_acs[((size_t)bc * NHEADS + h) * CHUNK + t];
    const float* S0 = g_Sinit + ((size_t)bc * NHEADS + h) * (HEADDIM * DSTATE);
    {
        int p = t >> 2, nb = (t & 3) * 32;
#pragma unroll
        for (int i = 0; i < 32; i += 4) {
            float4 v = *(const float4*)(S0 + p * DSTATE + nb + i);
            St[nb+i+0][p] = v.x;
            St[nb+i+1][p] = v.y;
            St[nb+i+2][p] = v.z;
            St[nb+i+3][p] = v.w;
        }
    }
    __syncthreads();
    float off[64];
#pragma unroll
    for (int i = 0; i < 64; i++) off[i] = 0.f;
    size_t rowI = (size_t)b * SEQLEN + c * CHUNK + t;
    const float* Crow = g_xBC + rowI * CONVDIM + (DINNER + DSTATE);
    for (int n = 0; n < DSTATE; n++) {
        float cl = __ldg(Crow + n);
        const float4* sr = (const float4*)&St[n][0];
#pragma unroll
        for (int i = 0; i < 16; i++) {
            float4 sv = sr[i];
            off[4*i+0] += cl * sv.x;
            off[4*i+1] += cl * sv.y;
            off[4*i+2] += cl * sv.z;
            off[4*i+3] += cl * sv.w;
        }
    }
    float el = __expf(sacs[t]);
    float* yout = g_Y + rowI * DINNER + h * HEADDIM;
#pragma unroll
    for (int i = 0; i < 16; i++) {
        float4 yd = *(const float4*)(yout + 4*i);
        yd.x += el * off[4*i+0];
        yd.y += el * off[4*i+1];
        yd.z += el * off[4*i+2];
        yd.w += el * off[4*i+3];
        *(float4*)(yout + 4*i) = yd;
    }
}

// ---------------- layernorm + z-gate -> split bf16 yg ----------------------
__global__ __launch_bounds__(256) void normgate_kernel(const float* __restrict__ norm_w)
{
    int row = blockIdx.x;
    int t = threadIdx.x;
    const float* yrow = g_Y + (size_t)row * DINNER;
    const float* zrow = g_zxbcdt + (size_t)row * DPROJ;
    float v[8];
    float s = 0.f;
#pragma unroll
    for (int i = 0; i < 8; i++) { v[i] = yrow[t + 256*i]; s += v[i]; }
    __shared__ float red[256];
    red[t] = s; __syncthreads();
    for (int o = 128; o > 0; o >>= 1) { if (t < o) red[t] += red[t+o]; __syncthreads(); }
    float mu = red[0] * (1.f / DINNER);
    __syncthreads();
    float s2 = 0.f;
#pragma unroll
    for (int i = 0; i < 8; i++) { float dv = v[i] - mu; s2 += dv * dv; }
    red[t] = s2; __syncthreads();
    for (int o = 128; o > 0; o >>= 1) { if (t < o) red[t] += red[t+o]; __syncthreads(); }
    float inv = rsqrtf(red[0] * (1.f / DINNER) + 1e-5f);
    __nv_bfloat16* oh = g_ygh + (size_t)row * DINNER;
    __nv_bfloat16* ol = g_ygl + (size_t)row * DINNER;
#pragma unroll
    for (int i = 0; i < 8; i++) {
        int idx = t + 256*i;
        float z = zrow[idx];
        float g = z / (1.f + expf(-z));
        float o = (v[i] - mu) * inv * norm_w[idx] * g;
        __nv_bfloat16 h = __float2bfloat16(o);
        oh[idx] = h;
        ol[idx] = __float2bfloat16(o - __bfloat162float(h));
    }
}

// ---------------- launch ---------------------------------------------------
extern "C" void kernel_launch(void* const* d_in, const int* in_sizes, int n_in,
                              void* d_out, int out_size)
{
    const float* u       = (const float*)d_in[0];
    const float* W_in    = (const float*)d_in[1];
    const float* conv_w  = (const float*)d_in[2];
    const float* conv_b  = (const float*)d_in[3];
    const float* dt_bias = (const float*)d_in[4];
    const float* A_log   = (const float*)d_in[5];
    const float* norm_w  = (const float*)d_in[6];
    const float* W_out   = (const float*)d_in[7];
    float* out = (float*)d_out;

    float* p_zx = nullptr;
    __nv_bfloat16 *p_uh, *p_ul, *p_wih, *p_wil, *p_woh, *p_wol, *p_ygh, *p_ygl;
    cudaGetSymbolAddress((void**)&p_zx,  g_zxbcdt);
    cudaGetSymbolAddress((void**)&p_uh,  g_uh);
    cudaGetSymbolAddress((void**)&p_ul,  g_ul);
    cudaGetSymbolAddress((void**)&p_wih, g_wih);
    cudaGetSymbolAddress((void**)&p_wil, g_wil);
    cudaGetSymbolAddress((void**)&p_woh, g_woh);
    cudaGetSymbolAddress((void**)&p_wol, g_wol);
    cudaGetSymbolAddress((void**)&p_ygh, g_ygh);
    cudaGetSymbolAddress((void**)&p_ygl, g_ygl);

    // 0. split-bf16 conversions
    {
        size_t n = (size_t)ROWS * DMODEL;
        split_kernel<<<(unsigned)((n + 255) / 256), 256>>>(u, p_uh, p_ul, n);
    }
    split_pad_kernel<<<(unsigned)(((size_t)DMODEL * NPAD1 + 255) / 256), 256>>>(
        W_in, p_wih, p_wil, DMODEL, DPROJ, NPAD1);
    {
        size_t n = (size_t)DINNER * DMODEL;
        split_kernel<<<(unsigned)((n + 255) / 256), 256>>>(W_out, p_woh, p_wol, n);
    }

    // 1. zxbcdt = u @ W_in  (8192 x 4384 x 1024), split-bf16 tensor cores
    mma_gemm<<<dim3(NPAD1 / 128, ROWS / 128), 512>>>(
        p_uh, p_ul, p_wih, p_wil, p_zx, ROWS, DPROJ, DMODEL, NPAD1, DPROJ);
    // 2. causal conv1d + SiLU
    conv_silu_kernel<<<(ROWS * CONVDIM + 255) / 256, 256>>>(conv_w, conv_b);
    // 3. dt softplus
    dt_kernel<<<(ROWS * NHEADS + 255) / 256, 256>>>(dt_bias);
    // 4. per-chunk cumsum of A*dt
    ascan_kernel<<<dim3(NBC, NHEADS), CHUNK>>>(A_log);
    // 5. head-independent CB gram matrices
    cb_kernel<<<dim3(NBC, 4, 4), 256>>>();
    // 6. intra-chunk causal Y_diag
    ydiag_kernel<<<dim3(NBC, NHEADS), 256>>>();
    // 7. per-chunk end states
    state_kernel<<<dim3(NBC, NHEADS), 256>>>();
    // 8. inter-chunk recurrence
    chunkrec_kernel<<<dim3(BATCH, NHEADS), 256>>>();
    // 9. inter-chunk contribution Y_off
    yoff_kernel<<<dim3(NBC, NHEADS), 256>>>();
    // 10. layernorm + silu(z) gate -> split bf16
    normgate_kernel<<<ROWS, 256>>>(norm_w);
    // 11. out = yg @ W_out  (8192 x 1024 x 2048)
    mma_gemm<<<dim3(DMODEL / 128, ROWS / 128), 512>>>(
        p_ygh, p_ygl, p_woh, p_wol, out, ROWS, DMODEL, DINNER, DMODEL, DMODEL);
}

// round 4
// speedup vs baseline: 1.6536x; 1.0411x over previous
#include <cuda_runtime.h>
#include <cuda_bf16.h>
#include <math.h>
#include <stdint.h>

#define BATCH   2
#define SEQLEN  4096
#define DMODEL  1024
#define DINNER  2048
#define HEADDIM 64
#define NHEADS  32
#define DSTATE  128
#define DCONV   4
#define CHUNK   256
#define NCHUNK  (SEQLEN / CHUNK)   // 16
#define NBC     (BATCH * NCHUNK)   // 32
#define DPROJ   4384               // 2*DINNER + 2*DSTATE + NHEADS
#define CONVDIM 2304               // DINNER + 2*DSTATE
#define DT_OFF  4352               // 2*DINNER + 2*DSTATE
#define ROWS    (BATCH * SEQLEN)   // 8192
#define NPAD1   4480               // DPROJ padded to multiple of 128

// ---------------- scratch (device globals; no allocation allowed) ----------
__device__ float g_zxbcdt[(size_t)ROWS * DPROJ];
__device__ float g_xBC[(size_t)ROWS * CONVDIM];
__device__ float g_dt[ROWS * NHEADS];
__device__ float g_acs[NBC * NHEADS * CHUNK];
__device__ float g_asum[NBC * NHEADS];
__device__ float g_CB[(size_t)NBC * CHUNK * CHUNK];
__device__ float g_Y[(size_t)ROWS * DINNER];
__device__ float g_S[(size_t)NBC * NHEADS * HEADDIM * DSTATE];
__device__ float g_Sinit[(size_t)NBC * NHEADS * HEADDIM * DSTATE];

// split bf16 operands
__device__ __nv_bfloat16 g_uh[(size_t)ROWS * DMODEL];
__device__ __nv_bfloat16 g_ul[(size_t)ROWS * DMODEL];
__device__ __nv_bfloat16 g_wih[(size_t)DMODEL * NPAD1];
__device__ __nv_bfloat16 g_wil[(size_t)DMODEL * NPAD1];
__device__ __nv_bfloat16 g_woh[(size_t)DINNER * DMODEL];
__device__ __nv_bfloat16 g_wol[(size_t)DINNER * DMODEL];
__device__ __nv_bfloat16 g_ygh[(size_t)ROWS * DINNER];
__device__ __nv_bfloat16 g_ygl[(size_t)ROWS * DINNER];

// ---------------- helpers ---------------------------------------------------
__device__ __forceinline__ uint32_t s2u(const void* p) {
    return (uint32_t)__cvta_generic_to_shared(p);
}
#define CP16(dst, src) \
    asm volatile("cp.async.cg.shared.global [%0], [%1], 16;\n" :: "r"(dst), "l"(src))
#define CP_COMMIT() asm volatile("cp.async.commit_group;\n")
#define CP_WAIT2()  asm volatile("cp.async.wait_group 2;\n")

__device__ __forceinline__ void ldsm4(uint32_t& r0, uint32_t& r1, uint32_t& r2,
                                      uint32_t& r3, uint32_t addr) {
    asm volatile("ldmatrix.sync.aligned.m8n8.x4.shared.b16 {%0,%1,%2,%3}, [%4];"
                 : "=r"(r0), "=r"(r1), "=r"(r2), "=r"(r3) : "r"(addr));
}
__device__ __forceinline__ void ldsm4t(uint32_t& r0, uint32_t& r1, uint32_t& r2,
                                       uint32_t& r3, uint32_t addr) {
    asm volatile("ldmatrix.sync.aligned.m8n8.x4.trans.shared.b16 {%0,%1,%2,%3}, [%4];"
                 : "=r"(r0), "=r"(r1), "=r"(r2), "=r"(r3) : "r"(addr));
}
__device__ __forceinline__ void mma16816(float* d, const uint32_t* a, const uint32_t* b) {
    asm volatile(
        "mma.sync.aligned.m16n8k16.row.col.f32.bf16.bf16.f32 "
        "{%0,%1,%2,%3}, {%4,%5,%6,%7}, {%8,%9}, {%0,%1,%2,%3};"
        : "+f"(d[0]), "+f"(d[1]), "+f"(d[2]), "+f"(d[3])
        : "r"(a[0]), "r"(a[1]), "r"(a[2]), "r"(a[3]), "r"(b[0]), "r"(b[1]));
}

// ---------------- smem layout constants (bytes) -----------------------------
// per stage: Ah[128][24] | Al[128][24] | Bh[16][136] | Bl[16][136]
#define A_HALF_B   6144          // 128*24*2
#define B_HALF_B   4352          // 16*136*2
#define OFF_AL     A_HALF_B
#define OFF_BH     (2 * A_HALF_B)
#define OFF_BL     (2 * A_HALF_B + B_HALF_B)
#define STAGE_B    (2 * A_HALF_B + 2 * B_HALF_B)   // 20992
#define NSTAGE     4
#define GEMM_SMEM  (NSTAGE * STAGE_B)              // 83968

// ---------------- split-bf16 tensor-core GEMM (mma.sync, 4-stage) -----------
// C[M,N] = (Ah+Al)[M,K] * (Bh+Bl)[K,N] (3-term). A row-major lda=K,
// B row-major ldb (tile-padded), C fp32 ldc, guard col<N.
// 128x128 block, BK=16, 512 threads (16 warps, 4x4), warp tile 32x32.
__global__ __launch_bounds__(512, 1) void mma_gemm(
    const __nv_bfloat16* __restrict__ Ah, const __nv_bfloat16* __restrict__ Al,
    const __nv_bfloat16* __restrict__ Bh, const __nv_bfloat16* __restrict__ Bl,
    float* __restrict__ C, int M, int N, int K, int ldb, int ldc)
{
    extern __shared__ __nv_bfloat16 smem[];
    const uint32_t sbase = s2u(smem);
    const int rowBase = blockIdx.y * 128;
    const int colBase = blockIdx.x * 128;
    const int t = threadIdx.x;

    // async-load mapping: thread -> one 16B A chunk + one 16B B chunk (hi or lo)
    const int sel = t >> 8;          // 0 = hi, 1 = lo
    const int q   = t & 255;
    const int ar = q >> 1, ahalf = q & 1;
    const __nv_bfloat16* aS = (sel ? Al : Ah) + (size_t)(rowBase + ar) * K + ahalf * 8;
    const int br = q >> 4, bcc = q & 15;
    const __nv_bfloat16* bS = (sel ? Bl : Bh) + (size_t)br * ldb + colBase + bcc * 8;
    const uint32_t aD = sbase + (sel ? OFF_AL : 0) + (ar * 24 + ahalf * 8) * 2;
    const uint32_t bD = sbase + (sel ? OFF_BL : OFF_BH) + (br * 136 + bcc * 8) * 2;

    const int lane = t & 31, warp = t >> 5;
    const int wm = warp >> 2, wn = warp & 3;
    const int grp = lane >> 3, rr = lane & 7;

    // fragment smem addresses (hi; lo = +A_HALF_B / +B_HALF_B)
    uint32_t aAddr[2], bAddr[2];
#pragma unroll
    for (int mi = 0; mi < 2; mi++)
        aAddr[mi] = sbase + ((wm * 32 + mi * 16 + (grp & 1) * 8 + rr) * 24
                             + (grp >> 1) * 8) * 2;
#pragma unroll
    for (int pi = 0; pi < 2; pi++)
        bAddr[pi] = sbase + OFF_BH + (((grp & 1) * 8 + rr) * 136
                             + wn * 32 + pi * 16 + (grp >> 1) * 8) * 2;

    float d[2][4][4];
#pragma unroll
    for (int mi = 0; mi < 2; mi++)
#pragma unroll
        for (int ni = 0; ni < 4; ni++)
#pragma unroll
            for (int k = 0; k < 4; k++) d[mi][ni][k] = 0.f;

    uint32_t a_h[2][2][4], a_l[2][2][4], b_h[2][4][2], b_l[2][4][2];

    const int nk = K / 16;

#define LOAD_SLAB(st, kt) do {                                                  \
    const uint32_t _d = (st) * STAGE_B;                                         \
    const int _k = (kt) * 16;                                                   \
    CP16(aD + _d, aS + _k);                                                     \
    CP16(bD + _d, bS + (size_t)_k * ldb);                                       \
} while (0)

#define LOAD_FRAG(st, bf) do {                                                  \
    const uint32_t _d = (st) * STAGE_B;                                         \
    _Pragma("unroll")                                                           \
    for (int mi = 0; mi < 2; mi++) {                                            \
        ldsm4(a_h[bf][mi][0], a_h[bf][mi][1], a_h[bf][mi][2], a_h[bf][mi][3],   \
              aAddr[mi] + _d);                                                  \
        ldsm4(a_l[bf][mi][0], a_l[bf][mi][1], a_l[bf][mi][2], a_l[bf][mi][3],   \
              aAddr[mi] + _d + A_HALF_B);                                       \
    }                                                                           \
    _Pragma("unroll")                                                           \
    for (int pi = 0; pi < 2; pi++) {                                            \
        ldsm4t(b_h[bf][2*pi][0], b_h[bf][2*pi][1],                              \
               b_h[bf][2*pi+1][0], b_h[bf][2*pi+1][1], bAddr[pi] + _d);         \
        ldsm4t(b_l[bf][2*pi][0], b_l[bf][2*pi][1],                              \
               b_l[bf][2*pi+1][0], b_l[bf][2*pi+1][1],                          \
               bAddr[pi] + _d + B_HALF_B);                                      \
    }                                                                           \
} while (0)

    // prologue: stages 0..2
    LOAD_SLAB(0, 0); CP_COMMIT();
    LOAD_SLAB(1, 1); CP_COMMIT();
    LOAD_SLAB(2, 2); CP_COMMIT();
    CP_WAIT2();
    __syncthreads();
    LOAD_FRAG(0, 0);

    for (int kt = 0; kt < nk; kt++) {
        const int bf = kt & 1;
        if (kt + 3 < nk) LOAD_SLAB((kt + 3) & 3, kt + 3);
        CP_COMMIT();                       // always: uniform group accounting
        if (kt + 1 < nk) {
            CP_WAIT2();                    // k-tile kt+1 resident; kt+2/kt+3 stream
            __syncthreads();
            LOAD_FRAG((kt + 1) & 3, bf ^ 1);
        }
#pragma unroll
        for (int mi = 0; mi < 2; mi++)
#pragma unroll
            for (int ni = 0; ni < 4; ni++) {
                mma16816(d[mi][ni], a_h[bf][mi], b_h[bf][ni]);
                mma16816(d[mi][ni], a_h[bf][mi], b_l[bf][ni]);
                mma16816(d[mi][ni], a_l[bf][mi], b_h[bf][ni]);
            }
    }

    // epilogue
    const int r0 = rowBase + wm * 32 + (lane >> 2);
    const int c0 = colBase + wn * 32 + (lane & 3) * 2;
#pragma unroll
    for (int mi = 0; mi < 2; mi++)
#pragma unroll
        for (int ni = 0; ni < 4; ni++) {
            int col = c0 + ni * 8;
            if (col < N) {
                float2 v0 = make_float2(d[mi][ni][0], d[mi][ni][1]);
                float2 v1 = make_float2(d[mi][ni][2], d[mi][ni][3]);
                *(float2*)&C[(size_t)(r0 + mi * 16) * ldc + col] = v0;
                *(float2*)&C[(size_t)(r0 + mi * 16 + 8) * ldc + col] = v1;
            }
        }
#undef LOAD_SLAB
#undef LOAD_FRAG
}

// ---------------- split-bf16 convert kernels --------------------------------
__global__ void split_kernel(const float* __restrict__ x, __nv_bfloat16* __restrict__ hi,
                             __nv_bfloat16* __restrict__ lo, size_t n)
{
    size_t i = (size_t)blockIdx.x * blockDim.x + threadIdx.x;
    if (i >= n) return;
    float v = x[i];
    __nv_bfloat16 h = __float2bfloat16(v);
    hi[i] = h;
    lo[i] = __float2bfloat16(v - __bfloat162float(h));
}

__global__ void split_pad_kernel(const float* __restrict__ x, __nv_bfloat16* __restrict__ hi,
                                 __nv_bfloat16* __restrict__ lo, int K, int N, int Np)
{
    size_t i = (size_t)blockIdx.x * blockDim.x + threadIdx.x;
    if (i >= (size_t)K * Np) return;
    int r = (int)(i / Np), c = (int)(i % Np);
    float v = (c < N) ? x[(size_t)r * N + c] : 0.f;
    __nv_bfloat16 h = __float2bfloat16(v);
    hi[i] = h;
    lo[i] = __float2bfloat16(v - __bfloat162float(h));
}

// ---------------- causal depthwise conv1d (width 4) + SiLU -----------------
__global__ void conv_silu_kernel(const float* __restrict__ conv_w,
                                 const float* __restrict__ conv_b)
{
    int idx = blockIdx.x * blockDim.x + threadIdx.x;
    if (idx >= ROWS * CONVDIM) return;
    int c   = idx % CONVDIM;
    int row = idx / CONVDIM;
    int l   = row & (SEQLEN - 1);
    const float* base = g_zxbcdt + (size_t)row * DPROJ + DINNER + c;
    float acc = conv_b[c];
#pragma unroll
    for (int j = 0; j < DCONV; j++) {
        int ls = l - (DCONV - 1) + j;
        if (ls >= 0) acc += base[(long)(j - (DCONV - 1)) * DPROJ] * conv_w[c * DCONV + j];
    }
    g_xBC[(size_t)row * CONVDIM + c] = acc / (1.f + expf(-acc));
}

// ---------------- dt = softplus(dt_raw + dt_bias) --------------------------
__global__ void dt_kernel(const float* __restrict__ dt_bias)
{
    int idx = blockIdx.x * blockDim.x + threadIdx.x;
    if (idx >= ROWS * NHEADS) return;
    int h   = idx & (NHEADS - 1);
    int row = idx >> 5;
    float v = g_zxbcdt[(size_t)row * DPROJ + DT_OFF + h] + dt_bias[h];
    g_dt[idx] = (v > 20.f) ? v : log1pf(expf(v));
}

// ---------------- per-chunk inclusive cumsum of a = A*dt -------------------
__global__ void ascan_kernel(const float* __restrict__ A_log)
{
    int bc = blockIdx.x;
    int h  = blockIdx.y;
    int t  = threadIdx.x;
    int b = bc >> 4, c = bc & 15;
    __shared__ float sa[CHUNK];
    int row = b * SEQLEN + c * CHUNK + t;
    float A = -expf(A_log[h]);
    sa[t] = A * g_dt[row * NHEADS + h];
    __syncthreads();
    for (int off = 1; off < CHUNK; off <<= 1) {
        float v = (t >= off) ? sa[t - off] : 0.f;
        __syncthreads();
        sa[t] += v;
        __syncthreads();
    }
    g_acs[(bc * NHEADS + h) * CHUNK + t] = sa[t];
    if (t == CHUNK - 1) g_asum[bc * NHEADS + h] = sa[t];
}

// ---------------- CB[l,s] = sum_n C[l,n] * B[s,n]  (head-independent) ------
__global__ __launch_bounds__(256) void cb_kernel()
{
    int bc = blockIdx.x;
    int lt = blockIdx.y;
    int st = blockIdx.z;
    if (st > lt) return;
    int b = bc >> 4, c = bc & 15;
    int t = threadIdx.x;
    int ty = t >> 4, tx = t & 15;
    __shared__ float Ct[32][68];
    __shared__ float Bt[32][68];
    size_t rowB = (size_t)b * SEQLEN + c * CHUNK;
    float acc[4][4];
#pragma unroll
    for (int i = 0; i < 4; i++)
#pragma unroll
        for (int j = 0; j < 4; j++) acc[i][j] = 0.f;

    for (int n0 = 0; n0 < DSTATE; n0 += 32) {
        for (int v = t; v < 512; v += 256) {
            int r = v >> 3, n4 = v & 7;
            float4 cv = *(const float4*)(g_xBC + (rowB + lt*64 + r) * CONVDIM
                                         + (DINNER + DSTATE) + n0 + n4*4);
            Ct[n4*4+0][r]=cv.x; Ct[n4*4+1][r]=cv.y; Ct[n4*4+2][r]=cv.z; Ct[n4*4+3][r]=cv.w;
            float4 bvv = *(const float4*)(g_xBC + (rowB + st*64 + r) * CONVDIM
                                          + DINNER + n0 + n4*4);
            Bt[n4*4+0][r]=bvv.x; Bt[n4*4+1][r]=bvv.y; Bt[n4*4+2][r]=bvv.z; Bt[n4*4+3][r]=bvv.w;
        }
        __syncthreads();
#pragma unroll
        for (int n = 0; n < 32; n++) {
            float4 ca = *(const float4*)&Ct[n][ty*4];
            float4 bb = *(const float4*)&Bt[n][tx*4];
            float ra[4] = {ca.x, ca.y, ca.z, ca.w};
            float rb[4] = {bb.x, bb.y, bb.z, bb.w};
#pragma unroll
            for (int i = 0; i < 4; i++)
#pragma unroll
                for (int j = 0; j < 4; j++) acc[i][j] += ra[i] * rb[j];
        }
        __syncthreads();
    }
#pragma unroll
    for (int i = 0; i < 4; i++) {
        int l = lt*64 + ty*4 + i;
        float4 o = make_float4(acc[i][0], acc[i][1], acc[i][2], acc[i][3]);
        *(float4*)(g_CB + ((size_t)bc * CHUNK + l) * CHUNK + st*64 + tx*4) = o;
    }
}

// ---------------- Y_diag per (b,c,h) ---------------------------------------
__global__ __launch_bounds__(256, 1) void ydiag_kernel()
{
    int bc = blockIdx.x, h = blockIdx.y;
    int b = bc >> 4, c = bc & 15;
    int t = threadIdx.x;
    __shared__ float Xw[128][68];
    __shared__ float sacs[CHUNK];
    __shared__ float sdt[CHUNK];
    size_t rowB = (size_t)b * SEQLEN + c * CHUNK;
    sacs[t] = g_acs[((size_t)bc * NHEADS + h) * CHUNK + t];
    sdt[t]  = g_dt[(rowB + t) * NHEADS + h];
    float acc[64];
#pragma unroll
    for (int i = 0; i < 64; i++) acc[i] = 0.f;
    const float* CBrow = g_CB + ((size_t)bc * CHUNK + t) * CHUNK;
    __syncthreads();
    float acs_l = sacs[t];

    for (int stile = 0; stile < CHUNK; stile += 128) {
        int r  = t >> 1;
        int f0 = (t & 1) * 8;
        const float4* src = (const float4*)(g_xBC + (rowB + stile + r) * CONVDIM
                                            + h * HEADDIM) + f0;
        float dts = sdt[stile + r];
#pragma unroll
        for (int i = 0; i < 8; i++) {
            float4 v = src[i];
            int cc = (f0 + i) * 4;
            Xw[r][cc+0] = v.x * dts;
            Xw[r][cc+1] = v.y * dts;
            Xw[r][cc+2] = v.z * dts;
            Xw[r][cc+3] = v.w * dts;
        }
        __syncthreads();
        int smax = t - stile + 1;
        if (smax > 128) smax = 128;
        for (int s = 0; s < smax; s++) {
            float coef = __ldg(CBrow + stile + s) * __expf(acs_l - sacs[stile + s]);
            const float4* xr = (const float4*)&Xw[s][0];
#pragma unroll
            for (int i = 0; i < 16; i++) {
                float4 xv = xr[i];
                acc[4*i+0] += coef * xv.x;
                acc[4*i+1] += coef * xv.y;
                acc[4*i+2] += coef * xv.z;
                acc[4*i+3] += coef * xv.w;
            }
        }
        __syncthreads();
    }
    float* yout = g_Y + (rowB + t) * DINNER + h * HEADDIM;
#pragma unroll
    for (int i = 0; i < 16; i++)
        *(float4*)(yout + 4*i) = make_float4(acc[4*i], acc[4*i+1], acc[4*i+2], acc[4*i+3]);
}

// ---------------- per-chunk state S[p,n] -----------------------------------
__global__ __launch_bounds__(256, 1) void state_kernel()
{
    int bc = blockIdx.x, h = blockIdx.y;
    int b = bc >> 4, c = bc & 15;
    int t = threadIdx.x;
    __shared__ float Bs[64][132];
    __shared__ float warr[64];
    size_t rowB = (size_t)b * SEQLEN + c * CHUNK;
    float asum = g_asum[bc * NHEADS + h];
    int p  = t >> 2;
    int nq = (t & 3) * 4;
    const float* xptr = g_xBC + rowB * CONVDIM + h * HEADDIM + p;
    float4 acc4[8];
#pragma unroll
    for (int i = 0; i < 8; i++) acc4[i] = make_float4(0.f, 0.f, 0.f, 0.f);

    for (int stile = 0; stile < CHUNK; stile += 64) {
        {
            int r = t >> 2, qq = (t & 3) * 32;
            const float4* src = (const float4*)(g_xBC + (rowB + stile + r) * CONVDIM
                                                + DINNER + qq);
#pragma unroll
            for (int i = 0; i < 8; i++)
                *(float4*)&Bs[r][qq + i*4] = src[i];
        }
        if (t < 64) {
            int gl = stile + t;
            warr[t] = g_dt[(rowB + gl) * NHEADS + h] *
                      __expf(asum - g_acs[((size_t)bc * NHEADS + h) * CHUNK + gl]);
        }
        __syncthreads();
        for (int s = 0; s < 64; s++) {
            float xv = __ldg(xptr + (size_t)(stile + s) * CONVDIM) * warr[s];
#pragma unroll
            for (int i = 0; i < 8; i++) {
                float4 bv = *(const float4*)&Bs[s][nq + 16*i];
                acc4[i].x += xv * bv.x;
                acc4[i].y += xv * bv.y;
                acc4[i].z += xv * bv.z;
                acc4[i].w += xv * bv.w;
            }
        }
        __syncthreads();
    }
    float* Sout = g_S + (((size_t)bc * NHEADS + h) * HEADDIM + p) * DSTATE;
#pragma unroll
    for (int i = 0; i < 8; i++)
        *(float4*)(Sout + nq + 16*i) = acc4[i];
}

// ---------------- sequential inter-chunk recurrence ------------------------
__global__ void chunkrec_kernel()
{
    int b = blockIdx.x, h = blockIdx.y;
    int t = threadIdx.x;
    float cur[32];
#pragma unroll
    for (int k = 0; k < 32; k++) cur[k] = 0.f;
    for (int c = 0; c < NCHUNK; c++) {
        int bc = b * NCHUNK + c;
        size_t base = ((size_t)bc * NHEADS + h) * (HEADDIM * DSTATE);
        float dd = __expf(g_asum[bc * NHEADS + h]);
#pragma unroll
        for (int k = 0; k < 32; k++) {
            size_t e = base + t + 256 * k;
            g_Sinit[e] = cur[k];
            cur[k] = cur[k] * dd + g_S[e];
        }
    }
}

// ---------------- Y += exp(acs[l]) * C[l,:] . Sinit ------------------------
__global__ __launch_bounds__(256, 1) void yoff_kernel()
{
    int bc = blockIdx.x, h = blockIdx.y;
    int b = bc >> 4, c = bc & 15;
    int t = threadIdx.x;
    __shared__ float St[DSTATE][68];
    __shared__ float sacs[CHUNK];
    sacs[t] = g_acs[((size_t)bc * NHEADS + h) * CHUNK + t];
    const float* S0 = g_Sinit + ((size_t)bc * NHEADS + h) * (HEADDIM * DSTATE);
    {
        int p = t >> 2, nb = (t & 3) * 32;
#pragma unroll
        for (int i = 0; i < 32; i += 4) {
            float4 v = *(const float4*)(S0 + p * DSTATE + nb + i);
            St[nb+i+0][p] = v.x;
            St[nb+i+1][p] = v.y;
            St[nb+i+2][p] = v.z;
            St[nb+i+3][p] = v.w;
        }
    }
    __syncthreads();
    float off[64];
#pragma unroll
    for (int i = 0; i < 64; i++) off[i] = 0.f;
    size_t rowI = (size_t)b * SEQLEN + c * CHUNK + t;
    const float* Crow = g_xBC + rowI * CONVDIM + (DINNER + DSTATE);
    for (int n = 0; n < DSTATE; n++) {
        float cl = __ldg(Crow + n);
        const float4* sr = (const float4*)&St[n][0];
#pragma unroll
        for (int i = 0; i < 16; i++) {
            float4 sv = sr[i];
            off[4*i+0] += cl * sv.x;
            off[4*i+1] += cl * sv.y;
            off[4*i+2] += cl * sv.z;
            off[4*i+3] += cl * sv.w;
        }
    }
    float el = __expf(sacs[t]);
    float* yout = g_Y + rowI * DINNER + h * HEADDIM;
#pragma unroll
    for (int i = 0; i < 16; i++) {
        float4 yd = *(const float4*)(yout + 4*i);
        yd.x += el * off[4*i+0];
        yd.y += el * off[4*i+1];
        yd.z += el * off[4*i+2];
        yd.w += el * off[4*i+3];
        *(float4*)(yout + 4*i) = yd;
    }
}

// ---------------- layernorm + z-gate -> split bf16 yg ----------------------
__global__ __launch_bounds__(256) void normgate_kernel(const float* __restrict__ norm_w)
{
    int row = blockIdx.x;
    int t = threadIdx.x;
    const float* yrow = g_Y + (size_t)row * DINNER;
    const float* zrow = g_zxbcdt + (size_t)row * DPROJ;
    float v[8];
    float s = 0.f;
#pragma unroll
    for (int i = 0; i < 8; i++) { v[i] = yrow[t + 256*i]; s += v[i]; }
    __shared__ float red[256];
    red[t] = s; __syncthreads();
    for (int o = 128; o > 0; o >>= 1) { if (t < o) red[t] += red[t+o]; __syncthreads(); }
    float mu = red[0] * (1.f / DINNER);
    __syncthreads();
    float s2 = 0.f;
#pragma unroll
    for (int i = 0; i < 8; i++) { float dv = v[i] - mu; s2 += dv * dv; }
    red[t] = s2; __syncthreads();
    for (int o = 128; o > 0; o >>= 1) { if (t < o) red[t] += red[t+o]; __syncthreads(); }
    float inv = rsqrtf(red[0] * (1.f / DINNER) + 1e-5f);
    __nv_bfloat16* oh = g_ygh + (size_t)row * DINNER;
    __nv_bfloat16* ol = g_ygl + (size_t)row * DINNER;
#pragma unroll
    for (int i = 0; i < 8; i++) {
        int idx = t + 256*i;
        float z = zrow[idx];
        float g = z / (1.f + expf(-z));
        float o = (v[i] - mu) * inv * norm_w[idx] * g;
        __nv_bfloat16 h = __float2bfloat16(o);
        oh[idx] = h;
        ol[idx] = __float2bfloat16(o - __bfloat162float(h));
    }
}

// ---------------- launch ---------------------------------------------------
extern "C" void kernel_launch(void* const* d_in, const int* in_sizes, int n_in,
                              void* d_out, int out_size)
{
    const float* u       = (const float*)d_in[0];
    const float* W_in    = (const float*)d_in[1];
    const float* conv_w  = (const float*)d_in[2];
    const float* conv_b  = (const float*)d_in[3];
    const float* dt_bias = (const float*)d_in[4];
    const float* A_log   = (const float*)d_in[5];
    const float* norm_w  = (const float*)d_in[6];
    const float* W_out   = (const float*)d_in[7];
    float* out = (float*)d_out;

    float* p_zx = nullptr;
    __nv_bfloat16 *p_uh, *p_ul, *p_wih, *p_wil, *p_woh, *p_wol, *p_ygh, *p_ygl;
    cudaGetSymbolAddress((void**)&p_zx,  g_zxbcdt);
    cudaGetSymbolAddress((void**)&p_uh,  g_uh);
    cudaGetSymbolAddress((void**)&p_ul,  g_ul);
    cudaGetSymbolAddress((void**)&p_wih, g_wih);
    cudaGetSymbolAddress((void**)&p_wil, g_wil);
    cudaGetSymbolAddress((void**)&p_woh, g_woh);
    cudaGetSymbolAddress((void**)&p_wol, g_wol);
    cudaGetSymbolAddress((void**)&p_ygh, g_ygh);
    cudaGetSymbolAddress((void**)&p_ygl, g_ygl);

    cudaFuncSetAttribute(mma_gemm, cudaFuncAttributeMaxDynamicSharedMemorySize, GEMM_SMEM);

    // 0. split-bf16 conversions
    {
        size_t n = (size_t)ROWS * DMODEL;
        split_kernel<<<(unsigned)((n + 255) / 256), 256>>>(u, p_uh, p_ul, n);
    }
    split_pad_kernel<<<(unsigned)(((size_t)DMODEL * NPAD1 + 255) / 256), 256>>>(
        W_in, p_wih, p_wil, DMODEL, DPROJ, NPAD1);
    {
        size_t n = (size_t)DINNER * DMODEL;
        split_kernel<<<(unsigned)((n + 255) / 256), 256>>>(W_out, p_woh, p_wol, n);
    }

    // 1. zxbcdt = u @ W_in  (8192 x 4384 x 1024)
    mma_gemm<<<dim3(NPAD1 / 128, ROWS / 128), 512, GEMM_SMEM>>>(
        p_uh, p_ul, p_wih, p_wil, p_zx, ROWS, DPROJ, DMODEL, NPAD1, DPROJ);
    // 2. causal conv1d + SiLU
    conv_silu_kernel<<<(ROWS * CONVDIM + 255) / 256, 256>>>(conv_w, conv_b);
    // 3. dt softplus
    dt_kernel<<<(ROWS * NHEADS + 255) / 256, 256>>>(dt_bias);
    // 4. per-chunk cumsum of A*dt
    ascan_kernel<<<dim3(NBC, NHEADS), CHUNK>>>(A_log);
    // 5. head-independent CB gram matrices
    cb_kernel<<<dim3(NBC, 4, 4), 256>>>();
    // 6. intra-chunk causal Y_diag
    ydiag_kernel<<<dim3(NBC, NHEADS), 256>>>();
    // 7. per-chunk end states
    state_kernel<<<dim3(NBC, NHEADS), 256>>>();
    // 8. inter-chunk recurrence
    chunkrec_kernel<<<dim3(BATCH, NHEADS), 256>>>();
    // 9. inter-chunk contribution Y_off
    yoff_kernel<<<dim3(NBC, NHEADS), 256>>>();
    // 10. layernorm + silu(z) gate -> split bf16
    normgate_kernel<<<ROWS, 256>>>(norm_w);
    // 11. out = yg @ W_out  (8192 x 1024 x 2048)
    mma_gemm<<<dim3(DMODEL / 128, ROWS / 128), 512, GEMM_SMEM>>>(
        p_ygh, p_ygl, p_woh, p_wol, out, ROWS, DMODEL, DINNER, DMODEL, DMODEL);
}

// round 5
// speedup vs baseline: 1.7399x; 1.0522x over previous
#include <cuda_runtime.h>
#include <cuda_bf16.h>
#include <math.h>
#include <stdint.h>

#define BATCH   2
#define SEQLEN  4096
#define DMODEL  1024
#define DINNER  2048
#define HEADDIM 64
#define NHEADS  32
#define DSTATE  128
#define DCONV   4
#define CHUNK   256
#define NCHUNK  (SEQLEN / CHUNK)   // 16
#define NBC     (BATCH * NCHUNK)   // 32
#define DPROJ   4384               // 2*DINNER + 2*DSTATE + NHEADS
#define CONVDIM 2304               // DINNER + 2*DSTATE
#define DT_OFF  4352               // 2*DINNER + 2*DSTATE
#define ROWS    (BATCH * SEQLEN)   // 8192
#define NPAD1   4480               // DPROJ padded to multiple of 64

// ---------------- scratch (device globals; no allocation allowed) ----------
__device__ float g_zxbcdt[(size_t)ROWS * DPROJ];
__device__ float g_xBC[(size_t)ROWS * CONVDIM];
__device__ float g_dt[ROWS * NHEADS];
__device__ float g_acs[NBC * NHEADS * CHUNK];
__device__ float g_asum[NBC * NHEADS];
__device__ float g_CB[(size_t)NBC * CHUNK * CHUNK];
__device__ float g_Y[(size_t)ROWS * DINNER];
__device__ float g_S[(size_t)NBC * NHEADS * HEADDIM * DSTATE];
__device__ float g_Sinit[(size_t)NBC * NHEADS * HEADDIM * DSTATE];

// split bf16 operands
__device__ __nv_bfloat16 g_uh[(size_t)ROWS * DMODEL];
__device__ __nv_bfloat16 g_ul[(size_t)ROWS * DMODEL];
__device__ __nv_bfloat16 g_wih[(size_t)DMODEL * NPAD1];
__device__ __nv_bfloat16 g_wil[(size_t)DMODEL * NPAD1];
__device__ __nv_bfloat16 g_woh[(size_t)DINNER * DMODEL];
__device__ __nv_bfloat16 g_wol[(size_t)DINNER * DMODEL];
__device__ __nv_bfloat16 g_ygh[(size_t)ROWS * DINNER];
__device__ __nv_bfloat16 g_ygl[(size_t)ROWS * DINNER];

// ---------------- helpers ---------------------------------------------------
__device__ __forceinline__ uint32_t s2u(const void* p) {
    return (uint32_t)__cvta_generic_to_shared(p);
}
#define CP16(dst, src) \
    asm volatile("cp.async.cg.shared.global [%0], [%1], 16;\n" :: "r"(dst), "l"(src))
#define CP_COMMIT() asm volatile("cp.async.commit_group;\n")
#define CP_WAIT2()  asm volatile("cp.async.wait_group 2;\n")

__device__ __forceinline__ void ldsm4(uint32_t& r0, uint32_t& r1, uint32_t& r2,
                                      uint32_t& r3, uint32_t addr) {
    asm volatile("ldmatrix.sync.aligned.m8n8.x4.shared.b16 {%0,%1,%2,%3}, [%4];"
                 : "=r"(r0), "=r"(r1), "=r"(r2), "=r"(r3) : "r"(addr));
}
__device__ __forceinline__ void ldsm4t(uint32_t& r0, uint32_t& r1, uint32_t& r2,
                                       uint32_t& r3, uint32_t addr) {
    asm volatile("ldmatrix.sync.aligned.m8n8.x4.trans.shared.b16 {%0,%1,%2,%3}, [%4];"
                 : "=r"(r0), "=r"(r1), "=r"(r2), "=r"(r3) : "r"(addr));
}
__device__ __forceinline__ void mma16816(float* d, const uint32_t* a, const uint32_t* b) {
    asm volatile(
        "mma.sync.aligned.m16n8k16.row.col.f32.bf16.bf16.f32 "
        "{%0,%1,%2,%3}, {%4,%5,%6,%7}, {%8,%9}, {%0,%1,%2,%3};"
        : "+f"(d[0]), "+f"(d[1]), "+f"(d[2]), "+f"(d[3])
        : "r"(a[0]), "r"(a[1]), "r"(a[2]), "r"(a[3]), "r"(b[0]), "r"(b[1]));
}

// ---------------- smem layout (bytes), tile 128x64, BK=16 -------------------
// per stage: Ah[128][24] | Al[128][24] | Bh[16][72] | Bl[16][72]
#define A_HALF_B   6144          // 128*24*2
#define B_HALF_B   2304          // 16*72*2
#define OFF_AL     A_HALF_B
#define OFF_BH     (2 * A_HALF_B)
#define OFF_BL     (2 * A_HALF_B + B_HALF_B)
#define STAGE_B    (2 * A_HALF_B + 2 * B_HALF_B)   // 16896
#define NSTAGE     4
#define GEMM_SMEM  (NSTAGE * STAGE_B)              // 67584

// ---------------- split-bf16 tensor-core GEMM (2 CTAs/SM) -------------------
// C[M,N] = (Ah+Al)[M,K] * (Bh+Bl)[K,N] (3-term). 128x64 block, BK=16,
// 256 threads (8 warps, 4x2), warp tile 32x32.
__global__ __launch_bounds__(256, 2) void mma_gemm(
    const __nv_bfloat16* __restrict__ Ah, const __nv_bfloat16* __restrict__ Al,
    const __nv_bfloat16* __restrict__ Bh, const __nv_bfloat16* __restrict__ Bl,
    float* __restrict__ C, int M, int N, int K, int ldb, int ldc)
{
    extern __shared__ __nv_bfloat16 smem[];
    const uint32_t sbase = s2u(smem);
    const int rowBase = blockIdx.y * 128;
    const int colBase = blockIdx.x * 64;
    const int t = threadIdx.x;

    // A mapping: thread -> one 16B hi chunk + one 16B lo chunk
    const int ar = t >> 1, ahalf = t & 1;
    const __nv_bfloat16* aSh = Ah + (size_t)(rowBase + ar) * K + ahalf * 8;
    const __nv_bfloat16* aSl = Al + (size_t)(rowBase + ar) * K + ahalf * 8;
    const uint32_t aDh = sbase + (ar * 24 + ahalf * 8) * 2;
    const uint32_t aDl = aDh + OFF_AL;
    // B mapping: threads 0-127 hi, 128-255 lo; each one 16B chunk
    const int bsel = t >> 7;
    const int q = t & 127;
    const int br = q >> 3, bcol = q & 7;
    const __nv_bfloat16* bS = (bsel ? Bl : Bh) + (size_t)br * ldb + colBase + bcol * 8;
    const uint32_t bD = sbase + (bsel ? OFF_BL : OFF_BH) + (br * 72 + bcol * 8) * 2;

    const int lane = t & 31, warp = t >> 5;
    const int wm = warp >> 1, wn = warp & 1;
    const int grp = lane >> 3, rr = lane & 7;

    uint32_t aAddr[2], bAddr[2];
#pragma unroll
    for (int mi = 0; mi < 2; mi++)
        aAddr[mi] = sbase + ((wm * 32 + mi * 16 + (grp & 1) * 8 + rr) * 24
                             + (grp >> 1) * 8) * 2;
#pragma unroll
    for (int pi = 0; pi < 2; pi++)
        bAddr[pi] = sbase + OFF_BH + (((grp & 1) * 8 + rr) * 72
                             + wn * 32 + pi * 16 + (grp >> 1) * 8) * 2;

    float d[2][4][4];
#pragma unroll
    for (int mi = 0; mi < 2; mi++)
#pragma unroll
        for (int ni = 0; ni < 4; ni++)
#pragma unroll
            for (int k = 0; k < 4; k++) d[mi][ni][k] = 0.f;

    const int nk = K / 16;

#define LOAD_SLAB(st, kt) do {                                                  \
    const uint32_t _d = (st) * STAGE_B;                                         \
    const int _k = (kt) * 16;                                                   \
    CP16(aDh + _d, aSh + _k);                                                   \
    CP16(aDl + _d, aSl + _k);                                                   \
    CP16(bD + _d, bS + (size_t)_k * ldb);                                       \
} while (0)

    // prologue: stages 0..2
    LOAD_SLAB(0, 0); CP_COMMIT();
    LOAD_SLAB(1, 1); CP_COMMIT();
    LOAD_SLAB(2, 2); CP_COMMIT();
    CP_WAIT2();
    __syncthreads();

    for (int kt = 0; kt < nk; kt++) {
        const uint32_t sd = (kt & 3) * STAGE_B;

        // fragments for this k-tile
        uint32_t a_h[2][4], a_l[2][4], b_h[4][2], b_l[4][2];
#pragma unroll
        for (int mi = 0; mi < 2; mi++) {
            ldsm4(a_h[mi][0], a_h[mi][1], a_h[mi][2], a_h[mi][3], aAddr[mi] + sd);
            ldsm4(a_l[mi][0], a_l[mi][1], a_l[mi][2], a_l[mi][3],
                  aAddr[mi] + sd + A_HALF_B);
        }
#pragma unroll
        for (int pi = 0; pi < 2; pi++) {
            ldsm4t(b_h[2*pi][0], b_h[2*pi][1], b_h[2*pi+1][0], b_h[2*pi+1][1],
                   bAddr[pi] + sd);
            ldsm4t(b_l[2*pi][0], b_l[2*pi][1], b_l[2*pi+1][0], b_l[2*pi+1][1],
                   bAddr[pi] + sd + B_HALF_B);
        }

        // prefetch slab kt+3
        if (kt + 3 < nk) LOAD_SLAB((kt + 3) & 3, kt + 3);
        CP_COMMIT();

#pragma unroll
        for (int mi = 0; mi < 2; mi++)
#pragma unroll
            for (int ni = 0; ni < 4; ni++) {
                mma16816(d[mi][ni], a_h[mi], b_h[ni]);
                mma16816(d[mi][ni], a_h[mi], b_l[ni]);
                mma16816(d[mi][ni], a_l[mi], b_h[ni]);
            }

        if (kt + 1 < nk) {
            CP_WAIT2();
            __syncthreads();
        }
    }

    // epilogue
    const int r0 = rowBase + wm * 32 + (lane >> 2);
    const int c0 = colBase + wn * 32 + (lane & 3) * 2;
#pragma unroll
    for (int mi = 0; mi < 2; mi++)
#pragma unroll
        for (int ni = 0; ni < 4; ni++) {
            int col = c0 + ni * 8;
            if (col < N) {
                float2 v0 = make_float2(d[mi][ni][0], d[mi][ni][1]);
                float2 v1 = make_float2(d[mi][ni][2], d[mi][ni][3]);
                *(float2*)&C[(size_t)(r0 + mi * 16) * ldc + col] = v0;
                *(float2*)&C[(size_t)(r0 + mi * 16 + 8) * ldc + col] = v1;
            }
        }
#undef LOAD_SLAB
}

// ---------------- split-bf16 convert kernels --------------------------------
__global__ void split_kernel(const float* __restrict__ x, __nv_bfloat16* __restrict__ hi,
                             __nv_bfloat16* __restrict__ lo, size_t n)
{
    size_t i = (size_t)blockIdx.x * blockDim.x + threadIdx.x;
    if (i >= n) return;
    float v = x[i];
    __nv_bfloat16 h = __float2bfloat16(v);
    hi[i] = h;
    lo[i] = __float2bfloat16(v - __bfloat162float(h));
}

__global__ void split_pad_kernel(const float* __restrict__ x, __nv_bfloat16* __restrict__ hi,
                                 __nv_bfloat16* __restrict__ lo, int K, int N, int Np)
{
    size_t i = (size_t)blockIdx.x * blockDim.x + threadIdx.x;
    if (i >= (size_t)K * Np) return;
    int r = (int)(i / Np), c = (int)(i % Np);
    float v = (c < N) ? x[(size_t)r * N + c] : 0.f;
    __nv_bfloat16 h = __float2bfloat16(v);
    hi[i] = h;
    lo[i] = __float2bfloat16(v - __bfloat162float(h));
}

// ---------------- causal depthwise conv1d (width 4) + SiLU -----------------
__global__ void conv_silu_kernel(const float* __restrict__ conv_w,
                                 const float* __restrict__ conv_b)
{
    int idx = blockIdx.x * blockDim.x + threadIdx.x;
    if (idx >= ROWS * CONVDIM) return;
    int c   = idx % CONVDIM;
    int row = idx / CONVDIM;
    int l   = row & (SEQLEN - 1);
    const float* base = g_zxbcdt + (size_t)row * DPROJ + DINNER + c;
    float acc = conv_b[c];
#pragma unroll
    for (int j = 0; j < DCONV; j++) {
        int ls = l - (DCONV - 1) + j;
        if (ls >= 0) acc += base[(long)(j - (DCONV - 1)) * DPROJ] * conv_w[c * DCONV + j];
    }
    g_xBC[(size_t)row * CONVDIM + c] = acc / (1.f + expf(-acc));
}

// ---------------- dt = softplus(dt_raw + dt_bias) --------------------------
__global__ void dt_kernel(const float* __restrict__ dt_bias)
{
    int idx = blockIdx.x * blockDim.x + threadIdx.x;
    if (idx >= ROWS * NHEADS) return;
    int h   = idx & (NHEADS - 1);
    int row = idx >> 5;
    float v = g_zxbcdt[(size_t)row * DPROJ + DT_OFF + h] + dt_bias[h];
    g_dt[idx] = (v > 20.f) ? v : log1pf(expf(v));
}

// ---------------- per-chunk inclusive cumsum of a = A*dt -------------------
__global__ void ascan_kernel(const float* __restrict__ A_log)
{
    int bc = blockIdx.x;
    int h  = blockIdx.y;
    int t  = threadIdx.x;
    int b = bc >> 4, c = bc & 15;
    __shared__ float sa[CHUNK];
    int row = b * SEQLEN + c * CHUNK + t;
    float A = -expf(A_log[h]);
    sa[t] = A * g_dt[row * NHEADS + h];
    __syncthreads();
    for (int off = 1; off < CHUNK; off <<= 1) {
        float v = (t >= off) ? sa[t - off] : 0.f;
        __syncthreads();
        sa[t] += v;
        __syncthreads();
    }
    g_acs[(bc * NHEADS + h) * CHUNK + t] = sa[t];
    if (t == CHUNK - 1) g_asum[bc * NHEADS + h] = sa[t];
}

// ---------------- CB[l,s] = sum_n C[l,n] * B[s,n]  (head-independent) ------
__global__ __launch_bounds__(256) void cb_kernel()
{
    int bc = blockIdx.x;
    int lt = blockIdx.y;
    int st = blockIdx.z;
    if (st > lt) return;
    int b = bc >> 4, c = bc & 15;
    int t = threadIdx.x;
    int ty = t >> 4, tx = t & 15;
    __shared__ float Ct[32][68];
    __shared__ float Bt[32][68];
    size_t rowB = (size_t)b * SEQLEN + c * CHUNK;
    float acc[4][4];
#pragma unroll
    for (int i = 0; i < 4; i++)
#pragma unroll
        for (int j = 0; j < 4; j++) acc[i][j] = 0.f;

    for (int n0 = 0; n0 < DSTATE; n0 += 32) {
        for (int v = t; v < 512; v += 256) {
            int r = v >> 3, n4 = v & 7;
            float4 cv = *(const float4*)(g_xBC + (rowB + lt*64 + r) * CONVDIM
                                         + (DINNER + DSTATE) + n0 + n4*4);
            Ct[n4*4+0][r]=cv.x; Ct[n4*4+1][r]=cv.y; Ct[n4*4+2][r]=cv.z; Ct[n4*4+3][r]=cv.w;
            float4 bvv = *(const float4*)(g_xBC + (rowB + st*64 + r) * CONVDIM
                                          + DINNER + n0 + n4*4);
            Bt[n4*4+0][r]=bvv.x; Bt[n4*4+1][r]=bvv.y; Bt[n4*4+2][r]=bvv.z; Bt[n4*4+3][r]=bvv.w;
        }
        __syncthreads();
#pragma unroll
        for (int n = 0; n < 32; n++) {
            float4 ca = *(const float4*)&Ct[n][ty*4];
            float4 bb = *(const float4*)&Bt[n][tx*4];
            float ra[4] = {ca.x, ca.y, ca.z, ca.w};
            float rb[4] = {bb.x, bb.y, bb.z, bb.w};
#pragma unroll
            for (int i = 0; i < 4; i++)
#pragma unroll
                for (int j = 0; j < 4; j++) acc[i][j] += ra[i] * rb[j];
        }
        __syncthreads();
    }
#pragma unroll
    for (int i = 0; i < 4; i++) {
        int l = lt*64 + ty*4 + i;
        float4 o = make_float4(acc[i][0], acc[i][1], acc[i][2], acc[i][3]);
        *(float4*)(g_CB + ((size_t)bc * CHUNK + l) * CHUNK + st*64 + tx*4) = o;
    }
}

// ---------------- Y_diag per (b,c,h) ---------------------------------------
__global__ __launch_bounds__(256, 1) void ydiag_kernel()
{
    int bc = blockIdx.x, h = blockIdx.y;
    int b = bc >> 4, c = bc & 15;
    int t = threadIdx.x;
    __shared__ float Xw[128][68];
    __shared__ float sacs[CHUNK];
    __shared__ float sdt[CHUNK];
    size_t rowB = (size_t)b * SEQLEN + c * CHUNK;
    sacs[t] = g_acs[((size_t)bc * NHEADS + h) * CHUNK + t];
    sdt[t]  = g_dt[(rowB + t) * NHEADS + h];
    float acc[64];
#pragma unroll
    for (int i = 0; i < 64; i++) acc[i] = 0.f;
    const float* CBrow = g_CB + ((size_t)bc * CHUNK + t) * CHUNK;
    __syncthreads();
    float acs_l = sacs[t];

    for (int stile = 0; stile < CHUNK; stile += 128) {
        int r  = t >> 1;
        int f0 = (t & 1) * 8;
        const float4* src = (const float4*)(g_xBC + (rowB + stile + r) * CONVDIM
                                            + h * HEADDIM) + f0;
        float dts = sdt[stile + r];
#pragma unroll
        for (int i = 0; i < 8; i++) {
            float4 v = src[i];
            int cc = (f0 + i) * 4;
            Xw[r][cc+0] = v.x * dts;
            Xw[r][cc+1] = v.y * dts;
            Xw[r][cc+2] = v.z * dts;
            Xw[r][cc+3] = v.w * dts;
        }
        __syncthreads();
        int smax = t - stile + 1;
        if (smax > 128) smax = 128;
        for (int s = 0; s < smax; s++) {
            float coef = __ldg(CBrow + stile + s) * __expf(acs_l - sacs[stile + s]);
            const float4* xr = (const float4*)&Xw[s][0];
#pragma unroll
            for (int i = 0; i < 16; i++) {
                float4 xv = xr[i];
                acc[4*i+0] += coef * xv.x;
                acc[4*i+1] += coef * xv.y;
                acc[4*i+2] += coef * xv.z;
                acc[4*i+3] += coef * xv.w;
            }
        }
        __syncthreads();
    }
    float* yout = g_Y + (rowB + t) * DINNER + h * HEADDIM;
#pragma unroll
    for (int i = 0; i < 16; i++)
        *(float4*)(yout + 4*i) = make_float4(acc[4*i], acc[4*i+1], acc[4*i+2], acc[4*i+3]);
}

// ---------------- per-chunk state S[p,n] -----------------------------------
__global__ __launch_bounds__(256, 1) void state_kernel()
{
    int bc = blockIdx.x, h = blockIdx.y;
    int b = bc >> 4, c = bc & 15;
    int t = threadIdx.x;
    __shared__ float Bs[64][132];
    __shared__ float warr[64];
    size_t rowB = (size_t)b * SEQLEN + c * CHUNK;
    float asum = g_asum[bc * NHEADS + h];
    int p  = t >> 2;
    int nq = (t & 3) * 4;
    const float* xptr = g_xBC + rowB * CONVDIM + h * HEADDIM + p;
    float4 acc4[8];
#pragma unroll
    for (int i = 0; i < 8; i++) acc4[i] = make_float4(0.f, 0.f, 0.f, 0.f);

    for (int stile = 0; stile < CHUNK; stile += 64) {
        {
            int r = t >> 2, qq = (t & 3) * 32;
            const float4* src = (const float4*)(g_xBC + (rowB + stile + r) * CONVDIM
                                                + DINNER + qq);
#pragma unroll
            for (int i = 0; i < 8; i++)
                *(float4*)&Bs[r][qq + i*4] = src[i];
        }
        if (t < 64) {
            int gl = stile + t;
            warr[t] = g_dt[(rowB + gl) * NHEADS + h] *
                      __expf(asum - g_acs[((size_t)bc * NHEADS + h) * CHUNK + gl]);
        }
        __syncthreads();
        for (int s = 0; s < 64; s++) {
            float xv = __ldg(xptr + (size_t)(stile + s) * CONVDIM) * warr[s];
#pragma unroll
            for (int i = 0; i < 8; i++) {
                float4 bv = *(const float4*)&Bs[s][nq + 16*i];
                acc4[i].x += xv * bv.x;
                acc4[i].y += xv * bv.y;
                acc4[i].z += xv * bv.z;
                acc4[i].w += xv * bv.w;
            }
        }
        __syncthreads();
    }
    float* Sout = g_S + (((size_t)bc * NHEADS + h) * HEADDIM + p) * DSTATE;
#pragma unroll
    for (int i = 0; i < 8; i++)
        *(float4*)(Sout + nq + 16*i) = acc4[i];
}

// ---------------- sequential inter-chunk recurrence ------------------------
__global__ void chunkrec_kernel()
{
    int b = blockIdx.x, h = blockIdx.y;
    int t = threadIdx.x;
    float cur[32];
#pragma unroll
    for (int k = 0; k < 32; k++) cur[k] = 0.f;
    for (int c = 0; c < NCHUNK; c++) {
        int bc = b * NCHUNK + c;
        size_t base = ((size_t)bc * NHEADS + h) * (HEADDIM * DSTATE);
        float dd = __expf(g_asum[bc * NHEADS + h]);
#pragma unroll
        for (int k = 0; k < 32; k++) {
            size_t e = base + t + 256 * k;
            g_Sinit[e] = cur[k];
            cur[k] = cur[k] * dd + g_S[e];
        }
    }
}

// ---------------- Y += exp(acs[l]) * C[l,:] . Sinit ------------------------
__global__ __launch_bounds__(256, 1) void yoff_kernel()
{
    int bc = blockIdx.x, h = blockIdx.y;
    int b = bc >> 4, c = bc & 15;
    int t = threadIdx.x;
    __shared__ float St[DSTATE][68];
    __shared__ float sacs[CHUNK];
    sacs[t] = g_acs[((size_t)bc * NHEADS + h) * CHUNK + t];
    const float* S0 = g_Sinit + ((size_t)bc * NHEADS + h) * (HEADDIM * DSTATE);
    {
        int p = t >> 2, nb = (t & 3) * 32;
#pragma unroll
        for (int i = 0; i < 32; i += 4) {
            float4 v = *(const float4*)(S0 + p * DSTATE + nb + i);
            St[nb+i+0][p] = v.x;
            St[nb+i+1][p] = v.y;
            St[nb+i+2][p] = v.z;
            St[nb+i+3][p] = v.w;
        }
    }
    __syncthreads();
    float off[64];
#pragma unroll
    for (int i = 0; i < 64; i++) off[i] = 0.f;
    size_t rowI = (size_t)b * SEQLEN + c * CHUNK + t;
    const float* Crow = g_xBC + rowI * CONVDIM + (DINNER + DSTATE);
    for (int n = 0; n < DSTATE; n++) {
        float cl = __ldg(Crow + n);
        const float4* sr = (const float4*)&St[n][0];
#pragma unroll
        for (int i = 0; i < 16; i++) {
            float4 sv = sr[i];
            off[4*i+0] += cl * sv.x;
            off[4*i+1] += cl * sv.y;
            off[4*i+2] += cl * sv.z;
            off[4*i+3] += cl * sv.w;
        }
    }
    float el = __expf(sacs[t]);
    float* yout = g_Y + rowI * DINNER + h * HEADDIM;
#pragma unroll
    for (int i = 0; i < 16; i++) {
        float4 yd = *(const float4*)(yout + 4*i);
        yd.x += el * off[4*i+0];
        yd.y += el * off[4*i+1];
        yd.z += el * off[4*i+2];
        yd.w += el * off[4*i+3];
        *(float4*)(yout + 4*i) = yd;
    }
}

// ---------------- layernorm + z-gate -> split bf16 yg ----------------------
__global__ __launch_bounds__(256) void normgate_kernel(const float* __restrict__ norm_w)
{
    int row = blockIdx.x;
    int t = threadIdx.x;
    const float* yrow = g_Y + (size_t)row * DINNER;
    const float* zrow = g_zxbcdt + (size_t)row * DPROJ;
    float v[8];
    float s = 0.f;
#pragma unroll
    for (int i = 0; i < 8; i++) { v[i] = yrow[t + 256*i]; s += v[i]; }
    __shared__ float red[256];
    red[t] = s; __syncthreads();
    for (int o = 128; o > 0; o >>= 1) { if (t < o) red[t] += red[t+o]; __syncthreads(); }
    float mu = red[0] * (1.f / DINNER);
    __syncthreads();
    float s2 = 0.f;
#pragma unroll
    for (int i = 0; i < 8; i++) { float dv = v[i] - mu; s2 += dv * dv; }
    red[t] = s2; __syncthreads();
    for (int o = 128; o > 0; o >>= 1) { if (t < o) red[t] += red[t+o]; __syncthreads(); }
    float inv = rsqrtf(red[0] * (1.f / DINNER) + 1e-5f);
    __nv_bfloat16* oh = g_ygh + (size_t)row * DINNER;
    __nv_bfloat16* ol = g_ygl + (size_t)row * DINNER;
#pragma unroll
    for (int i = 0; i < 8; i++) {
        int idx = t + 256*i;
        float z = zrow[idx];
        float g = z / (1.f + expf(-z));
        float o = (v[i] - mu) * inv * norm_w[idx] * g;
        __nv_bfloat16 h = __float2bfloat16(o);
        oh[idx] = h;
        ol[idx] = __float2bfloat16(o - __bfloat162float(h));
    }
}

// ---------------- launch ---------------------------------------------------
extern "C" void kernel_launch(void* const* d_in, const int* in_sizes, int n_in,
                              void* d_out, int out_size)
{
    const float* u       = (const float*)d_in[0];
    const float* W_in    = (const float*)d_in[1];
    const float* conv_w  = (const float*)d_in[2];
    const float* conv_b  = (const float*)d_in[3];
    const float* dt_bias = (const float*)d_in[4];
    const float* A_log   = (const float*)d_in[5];
    const float* norm_w  = (const float*)d_in[6];
    const float* W_out   = (const float*)d_in[7];
    float* out = (float*)d_out;

    float* p_zx = nullptr;
    __nv_bfloat16 *p_uh, *p_ul, *p_wih, *p_wil, *p_woh, *p_wol, *p_ygh, *p_ygl;
    cudaGetSymbolAddress((void**)&p_zx,  g_zxbcdt);
    cudaGetSymbolAddress((void**)&p_uh,  g_uh);
    cudaGetSymbolAddress((void**)&p_ul,  g_ul);
    cudaGetSymbolAddress((void**)&p_wih, g_wih);
    cudaGetSymbolAddress((void**)&p_wil, g_wil);
    cudaGetSymbolAddress((void**)&p_woh, g_woh);
    cudaGetSymbolAddress((void**)&p_wol, g_wol);
    cudaGetSymbolAddress((void**)&p_ygh, g_ygh);
    cudaGetSymbolAddress((void**)&p_ygl, g_ygl);

    cudaFuncSetAttribute(mma_gemm, cudaFuncAttributeMaxDynamicSharedMemorySize, GEMM_SMEM);

    // 0. split-bf16 conversions
    {
        size_t n = (size_t)ROWS * DMODEL;
        split_kernel<<<(unsigned)((n + 255) / 256), 256>>>(u, p_uh, p_ul, n);
    }
    split_pad_kernel<<<(unsigned)(((size_t)DMODEL * NPAD1 + 255) / 256), 256>>>(
        W_in, p_wih, p_wil, DMODEL, DPROJ, NPAD1);
    {
        size_t n = (size_t)DINNER * DMODEL;
        split_kernel<<<(unsigned)((n + 255) / 256), 256>>>(W_out, p_woh, p_wol, n);
    }

    // 1. zxbcdt = u @ W_in  (8192 x 4384 x 1024)
    mma_gemm<<<dim3(NPAD1 / 64, ROWS / 128), 256, GEMM_SMEM>>>(
        p_uh, p_ul, p_wih, p_wil, p_zx, ROWS, DPROJ, DMODEL, NPAD1, DPROJ);
    // 2. causal conv1d + SiLU
    conv_silu_kernel<<<(ROWS * CONVDIM + 255) / 256, 256>>>(conv_w, conv_b);
    // 3. dt softplus
    dt_kernel<<<(ROWS * NHEADS + 255) / 256, 256>>>(dt_bias);
    // 4. per-chunk cumsum of A*dt
    ascan_kernel<<<dim3(NBC, NHEADS), CHUNK>>>(A_log);
    // 5. head-independent CB gram matrices
    cb_kernel<<<dim3(NBC, 4, 4), 256>>>();
    // 6. intra-chunk causal Y_diag
    ydiag_kernel<<<dim3(NBC, NHEADS), 256>>>();
    // 7. per-chunk end states
    state_kernel<<<dim3(NBC, NHEADS), 256>>>();
    // 8. inter-chunk recurrence
    chunkrec_kernel<<<dim3(BATCH, NHEADS), 256>>>();
    // 9. inter-chunk contribution Y_off
    yoff_kernel<<<dim3(NBC, NHEADS), 256>>>();
    // 10. layernorm + silu(z) gate -> split bf16
    normgate_kernel<<<ROWS, 256>>>(norm_w);
    // 11. out = yg @ W_out  (8192 x 1024 x 2048)
    mma_gemm<<<dim3(DMODEL / 64, ROWS / 128), 256, GEMM_SMEM>>>(
        p_ygh, p_ygl, p_woh, p_wol, out, ROWS, DMODEL, DINNER, DMODEL, DMODEL);
}

// round 6
// speedup vs baseline: 1.7726x; 1.0188x over previous
#include <cuda_runtime.h>
#include <cuda_bf16.h>
#include <math.h>
#include <stdint.h>

#define BATCH   2
#define SEQLEN  4096
#define DMODEL  1024
#define DINNER  2048
#define HEADDIM 64
#define NHEADS  32
#define DSTATE  128
#define DCONV   4
#define CHUNK   256
#define NCHUNK  (SEQLEN / CHUNK)   // 16
#define NBC     (BATCH * NCHUNK)   // 32
#define DPROJ   4384               // 2*DINNER + 2*DSTATE + NHEADS
#define CONVDIM 2304               // DINNER + 2*DSTATE
#define DT_OFF  4352               // 2*DINNER + 2*DSTATE
#define ROWS    (BATCH * SEQLEN)   // 8192
#define NPAD1   4480               // DPROJ padded to multiple of 64

// ---------------- scratch (device globals; no allocation allowed) ----------
__device__ float g_zxbcdt[(size_t)ROWS * DPROJ];
__device__ float g_xBC[(size_t)ROWS * CONVDIM];
__device__ float g_dt[ROWS * NHEADS];
__device__ float g_acs[NBC * NHEADS * CHUNK];
__device__ float g_asum[NBC * NHEADS];
__device__ float g_CB[(size_t)NBC * CHUNK * CHUNK];
__device__ float g_Y[(size_t)ROWS * DINNER];
__device__ float g_S[(size_t)NBC * NHEADS * HEADDIM * DSTATE];
__device__ float g_Sinit[(size_t)NBC * NHEADS * HEADDIM * DSTATE];

// split bf16 operands
__device__ __nv_bfloat16 g_uh[(size_t)ROWS * DMODEL];
__device__ __nv_bfloat16 g_ul[(size_t)ROWS * DMODEL];
__device__ __nv_bfloat16 g_wih[(size_t)DMODEL * NPAD1];
__device__ __nv_bfloat16 g_wil[(size_t)DMODEL * NPAD1];
__device__ __nv_bfloat16 g_woh[(size_t)DINNER * DMODEL];
__device__ __nv_bfloat16 g_wol[(size_t)DINNER * DMODEL];
__device__ __nv_bfloat16 g_ygh[(size_t)ROWS * DINNER];
__device__ __nv_bfloat16 g_ygl[(size_t)ROWS * DINNER];

// ---------------- helpers ---------------------------------------------------
__device__ __forceinline__ uint32_t s2u(const void* p) {
    return (uint32_t)__cvta_generic_to_shared(p);
}
#define CP16(dst, src) \
    asm volatile("cp.async.cg.shared.global [%0], [%1], 16;\n" :: "r"(dst), "l"(src))
#define CP_COMMIT() asm volatile("cp.async.commit_group;\n")
#define CP_WAIT1()  asm volatile("cp.async.wait_group 1;\n")

__device__ __forceinline__ void ldsm4(uint32_t& r0, uint32_t& r1, uint32_t& r2,
                                      uint32_t& r3, uint32_t addr) {
    asm volatile("ldmatrix.sync.aligned.m8n8.x4.shared.b16 {%0,%1,%2,%3}, [%4];"
                 : "=r"(r0), "=r"(r1), "=r"(r2), "=r"(r3) : "r"(addr));
}
__device__ __forceinline__ void ldsm4t(uint32_t& r0, uint32_t& r1, uint32_t& r2,
                                       uint32_t& r3, uint32_t addr) {
    asm volatile("ldmatrix.sync.aligned.m8n8.x4.trans.shared.b16 {%0,%1,%2,%3}, [%4];"
                 : "=r"(r0), "=r"(r1), "=r"(r2), "=r"(r3) : "r"(addr));
}
__device__ __forceinline__ void mma16816(float* d, const uint32_t* a, const uint32_t* b) {
    asm volatile(
        "mma.sync.aligned.m16n8k16.row.col.f32.bf16.bf16.f32 "
        "{%0,%1,%2,%3}, {%4,%5,%6,%7}, {%8,%9}, {%0,%1,%2,%3};"
        : "+f"(d[0]), "+f"(d[1]), "+f"(d[2]), "+f"(d[3])
        : "r"(a[0]), "r"(a[1]), "r"(a[2]), "r"(a[3]), "r"(b[0]), "r"(b[1]));
}

// ---------------- smem layout (bytes), tile 128x64, BK=32 -------------------
// per stage: Ah[128][40] | Al[128][40] | Bh[32][72] | Bl[32][72]
#define A_HALF_B   10240         // 128*40*2
#define B_HALF_B   4608          // 32*72*2
#define OFF_AL     A_HALF_B
#define OFF_BH     (2 * A_HALF_B)
#define OFF_BL     (2 * A_HALF_B + B_HALF_B)
#define STAGE_B    (2 * A_HALF_B + 2 * B_HALF_B)   // 29696
#define NSTAGE     3
#define GEMM_SMEM  (NSTAGE * STAGE_B)              // 89088

// ---------------- split-bf16 tensor-core GEMM (2 CTAs/SM, BK=32) ------------
// C[M,N] = (Ah+Al)[M,K] * (Bh+Bl)[K,N] (3-term). 128x64 block, BK=32,
// 256 threads (8 warps, 4x2), warp tile 32x32, 3-stage cp.async ring.
__global__ __launch_bounds__(256, 2) void mma_gemm(
    const __nv_bfloat16* __restrict__ Ah, const __nv_bfloat16* __restrict__ Al,
    const __nv_bfloat16* __restrict__ Bh, const __nv_bfloat16* __restrict__ Bl,
    float* __restrict__ C, int M, int N, int K, int ldb, int ldc)
{
    extern __shared__ __nv_bfloat16 smem[];
    const uint32_t sbase = s2u(smem);
    const int rowBase = blockIdx.y * 128;
    const int colBase = blockIdx.x * 64;
    const int t = threadIdx.x;

    // A mapping: chunks t and t+256 of 512 (row = c>>2, 8-col quad = c&3)
    const int ar = t >> 2, aq = t & 3;
    const __nv_bfloat16* aSh = Ah + (size_t)(rowBase + ar) * K + aq * 8;
    const __nv_bfloat16* aSl = Al + (size_t)(rowBase + ar) * K + aq * 8;
    const uint32_t aDh = sbase + (ar * 40 + aq * 8) * 2;
    // B mapping: chunk t of 256 (row = t>>3, 8-col group = t&7), hi+lo
    const int brr = t >> 3, bq = t & 7;
    const __nv_bfloat16* bSh = Bh + (size_t)brr * ldb + colBase + bq * 8;
    const __nv_bfloat16* bSl = Bl + (size_t)brr * ldb + colBase + bq * 8;
    const uint32_t bDh = sbase + OFF_BH + (brr * 72 + bq * 8) * 2;

    const int lane = t & 31, warp = t >> 5;
    const int wm = warp >> 1, wn = warp & 1;
    const int grp = lane >> 3, rr = lane & 7;

    uint32_t aAddr[2], bAddr[2];
#pragma unroll
    for (int mi = 0; mi < 2; mi++)
        aAddr[mi] = sbase + ((wm * 32 + mi * 16 + (grp & 1) * 8 + rr) * 40
                             + (grp >> 1) * 8) * 2;
#pragma unroll
    for (int pi = 0; pi < 2; pi++)
        bAddr[pi] = sbase + OFF_BH + (((grp & 1) * 8 + rr) * 72
                             + wn * 32 + pi * 16 + (grp >> 1) * 8) * 2;

    float d[2][4][4];
#pragma unroll
    for (int mi = 0; mi < 2; mi++)
#pragma unroll
        for (int ni = 0; ni < 4; ni++)
#pragma unroll
            for (int k = 0; k < 4; k++) d[mi][ni][k] = 0.f;

    const int nk = K / 32;

#define LOAD_SLAB(st, kt) do {                                                  \
    const uint32_t _d = (st) * STAGE_B;                                         \
    const int _k = (kt) * 32;                                                   \
    CP16(aDh + _d, aSh + _k);                                                   \
    CP16(aDh + _d + 64 * 40 * 2, aSh + (size_t)64 * K + _k);                    \
    CP16(aDh + _d + OFF_AL, aSl + _k);                                          \
    CP16(aDh + _d + OFF_AL + 64 * 40 * 2, aSl + (size_t)64 * K + _k);           \
    CP16(bDh + _d, bSh + (size_t)_k * ldb);                                     \
    CP16(bDh + _d + B_HALF_B, bSl + (size_t)_k * ldb);                          \
} while (0)

#define FRAGS_MMA(sd, koff_a, koff_b) do {                                      \
    uint32_t a_h[2][4], a_l[2][4], b_h[4][2], b_l[4][2];                        \
    _Pragma("unroll")                                                           \
    for (int mi = 0; mi < 2; mi++) {                                            \
        ldsm4(a_h[mi][0], a_h[mi][1], a_h[mi][2], a_h[mi][3],                   \
              aAddr[mi] + (sd) + (koff_a));                                     \
        ldsm4(a_l[mi][0], a_l[mi][1], a_l[mi][2], a_l[mi][3],                   \
              aAddr[mi] + (sd) + (koff_a) + A_HALF_B);                          \
    }                                                                           \
    _Pragma("unroll")                                                           \
    for (int pi = 0; pi < 2; pi++) {                                            \
        ldsm4t(b_h[2*pi][0], b_h[2*pi][1], b_h[2*pi+1][0], b_h[2*pi+1][1],      \
               bAddr[pi] + (sd) + (koff_b));                                    \
        ldsm4t(b_l[2*pi][0], b_l[2*pi][1], b_l[2*pi+1][0], b_l[2*pi+1][1],      \
               bAddr[pi] + (sd) + (koff_b) + B_HALF_B);                         \
    }                                                                           \
    _Pragma("unroll")                                                           \
    for (int mi = 0; mi < 2; mi++)                                              \
        _Pragma("unroll")                                                       \
        for (int ni = 0; ni < 4; ni++) {                                        \
            mma16816(d[mi][ni], a_h[mi], b_h[ni]);                              \
            mma16816(d[mi][ni], a_h[mi], b_l[ni]);                              \
            mma16816(d[mi][ni], a_l[mi], b_h[ni]);                              \
        }                                                                       \
} while (0)

    // prologue: slabs 0,1 -> stages 0,1
    LOAD_SLAB(0, 0); CP_COMMIT();
    LOAD_SLAB(1, 1); CP_COMMIT();
    CP_WAIT1();
    __syncthreads();

    for (int kt = 0; kt < nk; kt++) {
        const uint32_t sd = (uint32_t)(kt % 3) * STAGE_B;
        // prefetch slab kt+2 into the stage vacated by slab kt-1
        if (kt + 2 < nk) LOAD_SLAB((kt + 2) % 3, kt + 2);
        CP_COMMIT();
        // k16 half 0
        FRAGS_MMA(sd, 0, 0);
        // k16 half 1
        FRAGS_MMA(sd, 32, 16 * 72 * 2);
        if (kt + 1 < nk) {
            CP_WAIT1();
            __syncthreads();
        }
    }

    // epilogue
    const int r0 = rowBase + wm * 32 + (lane >> 2);
    const int c0 = colBase + wn * 32 + (lane & 3) * 2;
#pragma unroll
    for (int mi = 0; mi < 2; mi++)
#pragma unroll
        for (int ni = 0; ni < 4; ni++) {
            int col = c0 + ni * 8;
            if (col < N) {
                float2 v0 = make_float2(d[mi][ni][0], d[mi][ni][1]);
                float2 v1 = make_float2(d[mi][ni][2], d[mi][ni][3]);
                *(float2*)&C[(size_t)(r0 + mi * 16) * ldc + col] = v0;
                *(float2*)&C[(size_t)(r0 + mi * 16 + 8) * ldc + col] = v1;
            }
        }
#undef LOAD_SLAB
#undef FRAGS_MMA
}

// ---------------- split-bf16 convert kernels --------------------------------
__global__ void split_kernel(const float* __restrict__ x, __nv_bfloat16* __restrict__ hi,
                             __nv_bfloat16* __restrict__ lo, size_t n)
{
    size_t i = (size_t)blockIdx.x * blockDim.x + threadIdx.x;
    if (i >= n) return;
    float v = x[i];
    __nv_bfloat16 h = __float2bfloat16(v);
    hi[i] = h;
    lo[i] = __float2bfloat16(v - __bfloat162float(h));
}

__global__ void split_pad_kernel(const float* __restrict__ x, __nv_bfloat16* __restrict__ hi,
                                 __nv_bfloat16* __restrict__ lo, int K, int N, int Np)
{
    size_t i = (size_t)blockIdx.x * blockDim.x + threadIdx.x;
    if (i >= (size_t)K * Np) return;
    int r = (int)(i / Np), c = (int)(i % Np);
    float v = (c < N) ? x[(size_t)r * N + c] : 0.f;
    __nv_bfloat16 h = __float2bfloat16(v);
    hi[i] = h;
    lo[i] = __float2bfloat16(v - __bfloat162float(h));
}

// ---------------- causal depthwise conv1d (width 4) + SiLU -----------------
__global__ void conv_silu_kernel(const float* __restrict__ conv_w,
                                 const float* __restrict__ conv_b)
{
    int idx = blockIdx.x * blockDim.x + threadIdx.x;
    if (idx >= ROWS * CONVDIM) return;
    int c   = idx % CONVDIM;
    int row = idx / CONVDIM;
    int l   = row & (SEQLEN - 1);
    const float* base = g_zxbcdt + (size_t)row * DPROJ + DINNER + c;
    float acc = conv_b[c];
#pragma unroll
    for (int j = 0; j < DCONV; j++) {
        int ls = l - (DCONV - 1) + j;
        if (ls >= 0) acc += base[(long)(j - (DCONV - 1)) * DPROJ] * conv_w[c * DCONV + j];
    }
    g_xBC[(size_t)row * CONVDIM + c] = acc / (1.f + __expf(-acc));
}

// ---------------- dt = softplus(dt_raw + dt_bias) --------------------------
__global__ void dt_kernel(const float* __restrict__ dt_bias)
{
    int idx = blockIdx.x * blockDim.x + threadIdx.x;
    if (idx >= ROWS * NHEADS) return;
    int h   = idx & (NHEADS - 1);
    int row = idx >> 5;
    float v = g_zxbcdt[(size_t)row * DPROJ + DT_OFF + h] + dt_bias[h];
    g_dt[idx] = (v > 20.f) ? v : log1pf(expf(v));
}

// ---------------- per-chunk inclusive cumsum of a = A*dt -------------------
__global__ void ascan_kernel(const float* __restrict__ A_log)
{
    int bc = blockIdx.x;
    int h  = blockIdx.y;
    int t  = threadIdx.x;
    int b = bc >> 4, c = bc & 15;
    __shared__ float sa[CHUNK];
    int row = b * SEQLEN + c * CHUNK + t;
    float A = -expf(A_log[h]);
    sa[t] = A * g_dt[row * NHEADS + h];
    __syncthreads();
    for (int off = 1; off < CHUNK; off <<= 1) {
        float v = (t >= off) ? sa[t - off] : 0.f;
        __syncthreads();
        sa[t] += v;
        __syncthreads();
    }
    g_acs[(bc * NHEADS + h) * CHUNK + t] = sa[t];
    if (t == CHUNK - 1) g_asum[bc * NHEADS + h] = sa[t];
}

// ---------------- CB[l,s] = sum_n C[l,n] * B[s,n]  (head-independent) ------
__global__ __launch_bounds__(256) void cb_kernel()
{
    int bc = blockIdx.x;
    int lt = blockIdx.y;
    int st = blockIdx.z;
    if (st > lt) return;
    int b = bc >> 4, c = bc & 15;
    int t = threadIdx.x;
    int ty = t >> 4, tx = t & 15;
    __shared__ float Ct[32][68];
    __shared__ float Bt[32][68];
    size_t rowB = (size_t)b * SEQLEN + c * CHUNK;
    float acc[4][4];
#pragma unroll
    for (int i = 0; i < 4; i++)
#pragma unroll
        for (int j = 0; j < 4; j++) acc[i][j] = 0.f;

    for (int n0 = 0; n0 < DSTATE; n0 += 32) {
        for (int v = t; v < 512; v += 256) {
            int r = v >> 3, n4 = v & 7;
            float4 cv = *(const float4*)(g_xBC + (rowB + lt*64 + r) * CONVDIM
                                         + (DINNER + DSTATE) + n0 + n4*4);
            Ct[n4*4+0][r]=cv.x; Ct[n4*4+1][r]=cv.y; Ct[n4*4+2][r]=cv.z; Ct[n4*4+3][r]=cv.w;
            float4 bvv = *(const float4*)(g_xBC + (rowB + st*64 + r) * CONVDIM
                                          + DINNER + n0 + n4*4);
            Bt[n4*4+0][r]=bvv.x; Bt[n4*4+1][r]=bvv.y; Bt[n4*4+2][r]=bvv.z; Bt[n4*4+3][r]=bvv.w;
        }
        __syncthreads();
#pragma unroll
        for (int n = 0; n < 32; n++) {
            float4 ca = *(const float4*)&Ct[n][ty*4];
            float4 bb = *(const float4*)&Bt[n][tx*4];
            float ra[4] = {ca.x, ca.y, ca.z, ca.w};
            float rb[4] = {bb.x, bb.y, bb.z, bb.w};
#pragma unroll
            for (int i = 0; i < 4; i++)
#pragma unroll
                for (int j = 0; j < 4; j++) acc[i][j] += ra[i] * rb[j];
        }
        __syncthreads();
    }
#pragma unroll
    for (int i = 0; i < 4; i++) {
        int l = lt*64 + ty*4 + i;
        float4 o = make_float4(acc[i][0], acc[i][1], acc[i][2], acc[i][3]);
        *(float4*)(g_CB + ((size_t)bc * CHUNK + l) * CHUNK + st*64 + tx*4) = o;
    }
}

// ---------------- Y_diag per (b,c,h) ---------------------------------------
__global__ __launch_bounds__(256, 1) void ydiag_kernel()
{
    int bc = blockIdx.x, h = blockIdx.y;
    int b = bc >> 4, c = bc & 15;
    int t = threadIdx.x;
    __shared__ float Xw[128][68];
    __shared__ float sacs[CHUNK];
    __shared__ float sdt[CHUNK];
    size_t rowB = (size_t)b * SEQLEN + c * CHUNK;
    sacs[t] = g_acs[((size_t)bc * NHEADS + h) * CHUNK + t];
    sdt[t]  = g_dt[(rowB + t) * NHEADS + h];
    float acc[64];
#pragma unroll
    for (int i = 0; i < 64; i++) acc[i] = 0.f;
    const float* CBrow = g_CB + ((size_t)bc * CHUNK + t) * CHUNK;
    __syncthreads();
    float acs_l = sacs[t];

    for (int stile = 0; stile < CHUNK; stile += 128) {
        int r  = t >> 1;
        int f0 = (t & 1) * 8;
        const float4* src = (const float4*)(g_xBC + (rowB + stile + r) * CONVDIM
                                            + h * HEADDIM) + f0;
        float dts = sdt[stile + r];
#pragma unroll
        for (int i = 0; i < 8; i++) {
            float4 v = src[i];
            int cc = (f0 + i) * 4;
            Xw[r][cc+0] = v.x * dts;
            Xw[r][cc+1] = v.y * dts;
            Xw[r][cc+2] = v.z * dts;
            Xw[r][cc+3] = v.w * dts;
        }
        __syncthreads();
        int smax = t - stile + 1;
        if (smax > 128) smax = 128;
        for (int s = 0; s < smax; s++) {
            float coef = __ldg(CBrow + stile + s) * __expf(acs_l - sacs[stile + s]);
            const float4* xr = (const float4*)&Xw[s][0];
#pragma unroll
            for (int i = 0; i < 16; i++) {
                float4 xv = xr[i];
                acc[4*i+0] += coef * xv.x;
                acc[4*i+1] += coef * xv.y;
                acc[4*i+2] += coef * xv.z;
                acc[4*i+3] += coef * xv.w;
            }
        }
        __syncthreads();
    }
    float* yout = g_Y + (rowB + t) * DINNER + h * HEADDIM;
#pragma unroll
    for (int i = 0; i < 16; i++)
        *(float4*)(yout + 4*i) = make_float4(acc[4*i], acc[4*i+1], acc[4*i+2], acc[4*i+3]);
}

// ---------------- per-chunk state S[p,n] -----------------------------------
__global__ __launch_bounds__(256, 1) void state_kernel()
{
    int bc = blockIdx.x, h = blockIdx.y;
    int b = bc >> 4, c = bc & 15;
    int t = threadIdx.x;
    __shared__ float Bs[64][132];
    __shared__ float warr[64];
    size_t rowB = (size_t)b * SEQLEN + c * CHUNK;
    float asum = g_asum[bc * NHEADS + h];
    int p  = t >> 2;
    int nq = (t & 3) * 4;
    const float* xptr = g_xBC + rowB * CONVDIM + h * HEADDIM + p;
    float4 acc4[8];
#pragma unroll
    for (int i = 0; i < 8; i++) acc4[i] = make_float4(0.f, 0.f, 0.f, 0.f);

    for (int stile = 0; stile < CHUNK; stile += 64) {
        {
            int r = t >> 2, qq = (t & 3) * 32;
            const float4* src = (const float4*)(g_xBC + (rowB + stile + r) * CONVDIM
                                                + DINNER + qq);
#pragma unroll
            for (int i = 0; i < 8; i++)
                *(float4*)&Bs[r][qq + i*4] = src[i];
        }
        if (t < 64) {
            int gl = stile + t;
            warr[t] = g_dt[(rowB + gl) * NHEADS + h] *
                      __expf(asum - g_acs[((size_t)bc * NHEADS + h) * CHUNK + gl]);
        }
        __syncthreads();
        for (int s = 0; s < 64; s++) {
            float xv = __ldg(xptr + (size_t)(stile + s) * CONVDIM) * warr[s];
#pragma unroll
            for (int i = 0; i < 8; i++) {
                float4 bv = *(const float4*)&Bs[s][nq + 16*i];
                acc4[i].x += xv * bv.x;
                acc4[i].y += xv * bv.y;
                acc4[i].z += xv * bv.z;
                acc4[i].w += xv * bv.w;
            }
        }
        __syncthreads();
    }
    float* Sout = g_S + (((size_t)bc * NHEADS + h) * HEADDIM + p) * DSTATE;
#pragma unroll
    for (int i = 0; i < 8; i++)
        *(float4*)(Sout + nq + 16*i) = acc4[i];
}

// ---------------- sequential inter-chunk recurrence ------------------------
__global__ void chunkrec_kernel()
{
    int b = blockIdx.x, h = blockIdx.y;
    int t = threadIdx.x;
    float cur[32];
#pragma unroll
    for (int k = 0; k < 32; k++) cur[k] = 0.f;
    for (int c = 0; c < NCHUNK; c++) {
        int bc = b * NCHUNK + c;
        size_t base = ((size_t)bc * NHEADS + h) * (HEADDIM * DSTATE);
        float dd = __expf(g_asum[bc * NHEADS + h]);
#pragma unroll
        for (int k = 0; k < 32; k++) {
            size_t e = base + t + 256 * k;
            g_Sinit[e] = cur[k];
            cur[k] = cur[k] * dd + g_S[e];
        }
    }
}

// ---------------- Y += exp(acs[l]) * C[l,:] . Sinit ------------------------
__global__ __launch_bounds__(256, 1) void yoff_kernel()
{
    int bc = blockIdx.x, h = blockIdx.y;
    int b = bc >> 4, c = bc & 15;
    int t = threadIdx.x;
    __shared__ float St[DSTATE][68];
    __shared__ float sacs[CHUNK];
    sacs[t] = g_acs[((size_t)bc * NHEADS + h) * CHUNK + t];
    const float* S0 = g_Sinit + ((size_t)bc * NHEADS + h) * (HEADDIM * DSTATE);
    {
        int p = t >> 2, nb = (t & 3) * 32;
#pragma unroll
        for (int i = 0; i < 32; i += 4) {
            float4 v = *(const float4*)(S0 + p * DSTATE + nb + i);
            St[nb+i+0][p] = v.x;
            St[nb+i+1][p] = v.y;
            St[nb+i+2][p] = v.z;
            St[nb+i+3][p] = v.w;
        }
    }
    __syncthreads();
    float off[64];
#pragma unroll
    for (int i = 0; i < 64; i++) off[i] = 0.f;
    size_t rowI = (size_t)b * SEQLEN + c * CHUNK + t;
    const float* Crow = g_xBC + rowI * CONVDIM + (DINNER + DSTATE);
    for (int n = 0; n < DSTATE; n++) {
        float cl = __ldg(Crow + n);
        const float4* sr = (const float4*)&St[n][0];
#pragma unroll
        for (int i = 0; i < 16; i++) {
            float4 sv = sr[i];
            off[4*i+0] += cl * sv.x;
            off[4*i+1] += cl * sv.y;
            off[4*i+2] += cl * sv.z;
            off[4*i+3] += cl * sv.w;
        }
    }
    float el = __expf(sacs[t]);
    float* yout = g_Y + rowI * DINNER + h * HEADDIM;
#pragma unroll
    for (int i = 0; i < 16; i++) {
        float4 yd = *(const float4*)(yout + 4*i);
        yd.x += el * off[4*i+0];
        yd.y += el * off[4*i+1];
        yd.z += el * off[4*i+2];
        yd.w += el * off[4*i+3];
        *(float4*)(yout + 4*i) = yd;
    }
}

// ---------------- layernorm + z-gate -> split bf16 yg ----------------------
__global__ __launch_bounds__(256) void normgate_kernel(const float* __restrict__ norm_w)
{
    int row = blockIdx.x;
    int t = threadIdx.x;
    const float* yrow = g_Y + (size_t)row * DINNER;
    const float* zrow = g_zxbcdt + (size_t)row * DPROJ;
    float v[8];
    float s = 0.f;
#pragma unroll
    for (int i = 0; i < 8; i++) { v[i] = yrow[t + 256*i]; s += v[i]; }
    __shared__ float red[256];
    red[t] = s; __syncthreads();
    for (int o = 128; o > 0; o >>= 1) { if (t < o) red[t] += red[t+o]; __syncthreads(); }
    float mu = red[0] * (1.f / DINNER);
    __syncthreads();
    float s2 = 0.f;
#pragma unroll
    for (int i = 0; i < 8; i++) { float dv = v[i] - mu; s2 += dv * dv; }
    red[t] = s2; __syncthreads();
    for (int o = 128; o > 0; o >>= 1) { if (t < o) red[t] += red[t+o]; __syncthreads(); }
    float inv = rsqrtf(red[0] * (1.f / DINNER) + 1e-5f);
    __nv_bfloat16* oh = g_ygh + (size_t)row * DINNER;
    __nv_bfloat16* ol = g_ygl + (size_t)row * DINNER;
#pragma unroll
    for (int i = 0; i < 8; i++) {
        int idx = t + 256*i;
        float z = zrow[idx];
        float g = z / (1.f + __expf(-z));
        float o = (v[i] - mu) * inv * norm_w[idx] * g;
        __nv_bfloat16 h = __float2bfloat16(o);
        oh[idx] = h;
        ol[idx] = __float2bfloat16(o - __bfloat162float(h));
    }
}

// ---------------- launch ---------------------------------------------------
extern "C" void kernel_launch(void* const* d_in, const int* in_sizes, int n_in,
                              void* d_out, int out_size)
{
    const float* u       = (const float*)d_in[0];
    const float* W_in    = (const float*)d_in[1];
    const float* conv_w  = (const float*)d_in[2];
    const float* conv_b  = (const float*)d_in[3];
    const float* dt_bias = (const float*)d_in[4];
    const float* A_log   = (const float*)d_in[5];
    const float* norm_w  = (const float*)d_in[6];
    const float* W_out   = (const float*)d_in[7];
    float* out = (float*)d_out;

    float* p_zx = nullptr;
    __nv_bfloat16 *p_uh, *p_ul, *p_wih, *p_wil, *p_woh, *p_wol, *p_ygh, *p_ygl;
    cudaGetSymbolAddress((void**)&p_zx,  g_zxbcdt);
    cudaGetSymbolAddress((void**)&p_uh,  g_uh);
    cudaGetSymbolAddress((void**)&p_ul,  g_ul);
    cudaGetSymbolAddress((void**)&p_wih, g_wih);
    cudaGetSymbolAddress((void**)&p_wil, g_wil);
    cudaGetSymbolAddress((void**)&p_woh, g_woh);
    cudaGetSymbolAddress((void**)&p_wol, g_wol);
    cudaGetSymbolAddress((void**)&p_ygh, g_ygh);
    cudaGetSymbolAddress((void**)&p_ygl, g_ygl);

    cudaFuncSetAttribute(mma_gemm, cudaFuncAttributeMaxDynamicSharedMemorySize, GEMM_SMEM);

    // 0. split-bf16 conversions
    {
        size_t n = (size_t)ROWS * DMODEL;
        split_kernel<<<(unsigned)((n + 255) / 256), 256>>>(u, p_uh, p_ul, n);
    }
    split_pad_kernel<<<(unsigned)(((size_t)DMODEL * NPAD1 + 255) / 256), 256>>>(
        W_in, p_wih, p_wil, DMODEL, DPROJ, NPAD1);
    {
        size_t n = (size_t)DINNER * DMODEL;
        split_kernel<<<(unsigned)((n + 255) / 256), 256>>>(W_out, p_woh, p_wol, n);
    }

    // 1. zxbcdt = u @ W_in  (8192 x 4384 x 1024)
    mma_gemm<<<dim3(NPAD1 / 64, ROWS / 128), 256, GEMM_SMEM>>>(
        p_uh, p_ul, p_wih, p_wil, p_zx, ROWS, DPROJ, DMODEL, NPAD1, DPROJ);
    // 2. causal conv1d + SiLU
    conv_silu_kernel<<<(ROWS * CONVDIM + 255) / 256, 256>>>(conv_w, conv_b);
    // 3. dt softplus
    dt_kernel<<<(ROWS * NHEADS + 255) / 256, 256>>>(dt_bias);
    // 4. per-chunk cumsum of A*dt
    ascan_kernel<<<dim3(NBC, NHEADS), CHUNK>>>(A_log);
    // 5. head-independent CB gram matrices
    cb_kernel<<<dim3(NBC, 4, 4), 256>>>();
    // 6. intra-chunk causal Y_diag
    ydiag_kernel<<<dim3(NBC, NHEADS), 256>>>();
    // 7. per-chunk end states
    state_kernel<<<dim3(NBC, NHEADS), 256>>>();
    // 8. inter-chunk recurrence
    chunkrec_kernel<<<dim3(BATCH, NHEADS), 256>>>();
    // 9. inter-chunk contribution Y_off
    yoff_kernel<<<dim3(NBC, NHEADS), 256>>>();
    // 10. layernorm + silu(z) gate -> split bf16
    normgate_kernel<<<ROWS, 256>>>(norm_w);
    // 11. out = yg @ W_out  (8192 x 1024 x 2048)
    mma_gemm<<<dim3(DMODEL / 64, ROWS / 128), 256, GEMM_SMEM>>>(
        p_ygh, p_ygl, p_woh, p_wol, out, ROWS, DMODEL, DINNER, DMODEL, DMODEL);
}

// round 7
// speedup vs baseline: 2.0340x; 1.1475x over previous
#include <cuda_runtime.h>
#include <cuda_bf16.h>
#include <math.h>
#include <stdint.h>

#define BATCH   2
#define SEQLEN  4096
#define DMODEL  1024
#define DINNER  2048
#define HEADDIM 64
#define NHEADS  32
#define DSTATE  128
#define DCONV   4
#define CHUNK   256
#define NCHUNK  (SEQLEN / CHUNK)   // 16
#define NBC     (BATCH * NCHUNK)   // 32
#define DPROJ   4384               // 2*DINNER + 2*DSTATE + NHEADS
#define CONVDIM 2304               // DINNER + 2*DSTATE
#define DT_OFF  4352               // 2*DINNER + 2*DSTATE
#define ROWS    (BATCH * SEQLEN)   // 8192
#define NPAD1   4480               // DPROJ padded to multiple of 64

// ---------------- scratch (device globals; no allocation allowed) ----------
__device__ float g_zxbcdt[(size_t)ROWS * DPROJ];
__device__ float g_xBC[(size_t)ROWS * CONVDIM];
__device__ float g_dt[ROWS * NHEADS];
__device__ float g_acs[NBC * NHEADS * CHUNK];
__device__ float g_asum[NBC * NHEADS];
__device__ float g_CB[(size_t)NBC * CHUNK * CHUNK];
__device__ float g_Y[(size_t)ROWS * DINNER];
__device__ float g_S[(size_t)NBC * NHEADS * HEADDIM * DSTATE];
__device__ float g_Sinit[(size_t)NBC * NHEADS * HEADDIM * DSTATE];

// split bf16 operands
__device__ __nv_bfloat16 g_uh[(size_t)ROWS * DMODEL];
__device__ __nv_bfloat16 g_ul[(size_t)ROWS * DMODEL];
__device__ __nv_bfloat16 g_wih[(size_t)DMODEL * NPAD1];
__device__ __nv_bfloat16 g_wil[(size_t)DMODEL * NPAD1];
__device__ __nv_bfloat16 g_woh[(size_t)DINNER * DMODEL];
__device__ __nv_bfloat16 g_wol[(size_t)DINNER * DMODEL];
__device__ __nv_bfloat16 g_ygh[(size_t)ROWS * DINNER];
__device__ __nv_bfloat16 g_ygl[(size_t)ROWS * DINNER];

// ---------------- helpers ---------------------------------------------------
__device__ __forceinline__ uint32_t s2u(const void* p) {
    return (uint32_t)__cvta_generic_to_shared(p);
}
#define CP16(dst, src) \
    asm volatile("cp.async.cg.shared.global [%0], [%1], 16;\n" :: "r"(dst), "l"(src))
#define CP_COMMIT() asm volatile("cp.async.commit_group;\n")
#define CP_WAIT1()  asm volatile("cp.async.wait_group 1;\n")

__device__ __forceinline__ void ldsm4(uint32_t& r0, uint32_t& r1, uint32_t& r2,
                                      uint32_t& r3, uint32_t addr) {
    asm volatile("ldmatrix.sync.aligned.m8n8.x4.shared.b16 {%0,%1,%2,%3}, [%4];"
                 : "=r"(r0), "=r"(r1), "=r"(r2), "=r"(r3) : "r"(addr));
}
__device__ __forceinline__ void ldsm4t(uint32_t& r0, uint32_t& r1, uint32_t& r2,
                                       uint32_t& r3, uint32_t addr) {
    asm volatile("ldmatrix.sync.aligned.m8n8.x4.trans.shared.b16 {%0,%1,%2,%3}, [%4];"
                 : "=r"(r0), "=r"(r1), "=r"(r2), "=r"(r3) : "r"(addr));
}
__device__ __forceinline__ void mma16816(float* d, const uint32_t* a, const uint32_t* b) {
    asm volatile(
        "mma.sync.aligned.m16n8k16.row.col.f32.bf16.bf16.f32 "
        "{%0,%1,%2,%3}, {%4,%5,%6,%7}, {%8,%9}, {%0,%1,%2,%3};"
        : "+f"(d[0]), "+f"(d[1]), "+f"(d[2]), "+f"(d[3])
        : "r"(a[0]), "r"(a[1]), "r"(a[2]), "r"(a[3]), "r"(b[0]), "r"(b[1]));
}
__device__ __forceinline__ void split2(float a, float b,
                                       __nv_bfloat162& h, __nv_bfloat162& l) {
    __nv_bfloat16 ha = __float2bfloat16(a), hb = __float2bfloat16(b);
    h = __halves2bfloat162(ha, hb);
    l = __halves2bfloat162(__float2bfloat16(a - __bfloat162float(ha)),
                           __float2bfloat16(b - __bfloat162float(hb)));
}

// ---------------- GEMM smem layout (bytes), tile 128x64, BK=32 --------------
#define A_HALF_B   10240         // 128*40*2
#define B_HALF_B   4608          // 32*72*2
#define OFF_AL     A_HALF_B
#define OFF_BH     (2 * A_HALF_B)
#define OFF_BL     (2 * A_HALF_B + B_HALF_B)
#define STAGE_B    (2 * A_HALF_B + 2 * B_HALF_B)   // 29696
#define NSTAGE     3
#define GEMM_SMEM  (NSTAGE * STAGE_B)              // 89088

// ---------------- split-bf16 tensor-core GEMM (2 CTAs/SM, BK=32) ------------
__global__ __launch_bounds__(256, 2) void mma_gemm(
    const __nv_bfloat16* __restrict__ Ah, const __nv_bfloat16* __restrict__ Al,
    const __nv_bfloat16* __restrict__ Bh, const __nv_bfloat16* __restrict__ Bl,
    float* __restrict__ C, int M, int N, int K, int ldb, int ldc)
{
    extern __shared__ __nv_bfloat16 smem[];
    const uint32_t sbase = s2u(smem);
    const int rowBase = blockIdx.y * 128;
    const int colBase = blockIdx.x * 64;
    const int t = threadIdx.x;

    const int ar = t >> 2, aq = t & 3;
    const __nv_bfloat16* aSh = Ah + (size_t)(rowBase + ar) * K + aq * 8;
    const __nv_bfloat16* aSl = Al + (size_t)(rowBase + ar) * K + aq * 8;
    const uint32_t aDh = sbase + (ar * 40 + aq * 8) * 2;
    const int brr = t >> 3, bq = t & 7;
    const __nv_bfloat16* bSh = Bh + (size_t)brr * ldb + colBase + bq * 8;
    const __nv_bfloat16* bSl = Bl + (size_t)brr * ldb + colBase + bq * 8;
    const uint32_t bDh = sbase + OFF_BH + (brr * 72 + bq * 8) * 2;

    const int lane = t & 31, warp = t >> 5;
    const int wm = warp >> 1, wn = warp & 1;
    const int grp = lane >> 3, rr = lane & 7;

    uint32_t aAddr[2], bAddr[2];
#pragma unroll
    for (int mi = 0; mi < 2; mi++)
        aAddr[mi] = sbase + ((wm * 32 + mi * 16 + (grp & 1) * 8 + rr) * 40
                             + (grp >> 1) * 8) * 2;
#pragma unroll
    for (int pi = 0; pi < 2; pi++)
        bAddr[pi] = sbase + OFF_BH + (((grp & 1) * 8 + rr) * 72
                             + wn * 32 + pi * 16 + (grp >> 1) * 8) * 2;

    float d[2][4][4];
#pragma unroll
    for (int mi = 0; mi < 2; mi++)
#pragma unroll
        for (int ni = 0; ni < 4; ni++)
#pragma unroll
            for (int k = 0; k < 4; k++) d[mi][ni][k] = 0.f;

    const int nk = K / 32;

#define LOAD_SLAB(st, kt) do {                                                  \
    const uint32_t _d = (st) * STAGE_B;                                         \
    const int _k = (kt) * 32;                                                   \
    CP16(aDh + _d, aSh + _k);                                                   \
    CP16(aDh + _d + 64 * 40 * 2, aSh + (size_t)64 * K + _k);                    \
    CP16(aDh + _d + OFF_AL, aSl + _k);                                          \
    CP16(aDh + _d + OFF_AL + 64 * 40 * 2, aSl + (size_t)64 * K + _k);           \
    CP16(bDh + _d, bSh + (size_t)_k * ldb);                                     \
    CP16(bDh + _d + B_HALF_B, bSl + (size_t)_k * ldb);                          \
} while (0)

#define FRAGS_MMA(sd, koff_a, koff_b) do {                                      \
    uint32_t a_h[2][4], a_l[2][4], b_h[4][2], b_l[4][2];                        \
    _Pragma("unroll")                                                           \
    for (int mi = 0; mi < 2; mi++) {                                            \
        ldsm4(a_h[mi][0], a_h[mi][1], a_h[mi][2], a_h[mi][3],                   \
              aAddr[mi] + (sd) + (koff_a));                                     \
        ldsm4(a_l[mi][0], a_l[mi][1], a_l[mi][2], a_l[mi][3],                   \
              aAddr[mi] + (sd) + (koff_a) + A_HALF_B);                          \
    }                                                                           \
    _Pragma("unroll")                                                           \
    for (int pi = 0; pi < 2; pi++) {                                            \
        ldsm4t(b_h[2*pi][0], b_h[2*pi][1], b_h[2*pi+1][0], b_h[2*pi+1][1],      \
               bAddr[pi] + (sd) + (koff_b));                                    \
        ldsm4t(b_l[2*pi][0], b_l[2*pi][1], b_l[2*pi+1][0], b_l[2*pi+1][1],      \
               bAddr[pi] + (sd) + (koff_b) + B_HALF_B);                         \
    }                                                                           \
    _Pragma("unroll")                                                           \
    for (int mi = 0; mi < 2; mi++)                                              \
        _Pragma("unroll")                                                       \
        for (int ni = 0; ni < 4; ni++) {                                        \
            mma16816(d[mi][ni], a_h[mi], b_h[ni]);                              \
            mma16816(d[mi][ni], a_h[mi], b_l[ni]);                              \
            mma16816(d[mi][ni], a_l[mi], b_h[ni]);                              \
        }                                                                       \
} while (0)

    LOAD_SLAB(0, 0); CP_COMMIT();
    LOAD_SLAB(1, 1); CP_COMMIT();
    CP_WAIT1();
    __syncthreads();

    for (int kt = 0; kt < nk; kt++) {
        const uint32_t sd = (uint32_t)(kt % 3) * STAGE_B;
        if (kt + 2 < nk) LOAD_SLAB((kt + 2) % 3, kt + 2);
        CP_COMMIT();
        FRAGS_MMA(sd, 0, 0);
        FRAGS_MMA(sd, 32, 16 * 72 * 2);
        if (kt + 1 < nk) {
            CP_WAIT1();
            __syncthreads();
        }
    }

    const int r0 = rowBase + wm * 32 + (lane >> 2);
    const int c0 = colBase + wn * 32 + (lane & 3) * 2;
#pragma unroll
    for (int mi = 0; mi < 2; mi++)
#pragma unroll
        for (int ni = 0; ni < 4; ni++) {
            int col = c0 + ni * 8;
            if (col < N) {
                float2 v0 = make_float2(d[mi][ni][0], d[mi][ni][1]);
                float2 v1 = make_float2(d[mi][ni][2], d[mi][ni][3]);
                *(float2*)&C[(size_t)(r0 + mi * 16) * ldc + col] = v0;
                *(float2*)&C[(size_t)(r0 + mi * 16 + 8) * ldc + col] = v1;
            }
        }
#undef LOAD_SLAB
#undef FRAGS_MMA
}

// ---------------- fused Y = (CB.L)X + exp(acs) C Sinit (tensor cores) -------
// per (bc,h): M=256 (l), N=64 (p), K = 4x64 (s) + 2x64 (n). 256 threads,
// 8 warps each 32 M-rows. W/X split hi/lo bf16 built in smem per k-tile.
#define YF_WH    0
#define YF_WL    36864               // 256*72*2
#define YF_XH    73728
#define YF_XL    82944               // + 64*72*2
#define YF_ACS   92160
#define YF_DT    93184
#define YF_SMEM  94208

__global__ __launch_bounds__(256, 2) void yfused_kernel()
{
    extern __shared__ char ysm[];
    __nv_bfloat16* Wh = (__nv_bfloat16*)(ysm + YF_WH);
    __nv_bfloat16* Wl = (__nv_bfloat16*)(ysm + YF_WL);
    __nv_bfloat16* Xh = (__nv_bfloat16*)(ysm + YF_XH);
    __nv_bfloat16* Xl = (__nv_bfloat16*)(ysm + YF_XL);
    float* sacs = (float*)(ysm + YF_ACS);
    float* sdt  = (float*)(ysm + YF_DT);

    const int bc = blockIdx.x, h = blockIdx.y;
    const int b = bc >> 4, c = bc & 15;
    const int t = threadIdx.x;
    const size_t rowB = (size_t)b * SEQLEN + c * CHUNK;

    sacs[t] = g_acs[((size_t)bc * NHEADS + h) * CHUNK + t];
    sdt[t]  = g_dt[(rowB + t) * NHEADS + h];
    __syncthreads();
    const float acs_l = sacs[t];

    const int lane = t & 31, warp = t >> 5;
    const int grp = lane >> 3, rr = lane & 7;
    const uint32_t whB = s2u(Wh), wlB = s2u(Wl), xhB = s2u(Xh), xlB = s2u(Xl);

    uint32_t aOff[2], bOff[4];
#pragma unroll
    for (int mi = 0; mi < 2; mi++)
        aOff[mi] = ((warp * 32 + mi * 16 + (grp & 1) * 8 + rr) * 72
                    + (grp >> 1) * 8) * 2;
#pragma unroll
    for (int pi = 0; pi < 4; pi++)
        bOff[pi] = (((grp & 1) * 8 + rr) * 72 + pi * 16 + (grp >> 1) * 8) * 2;

    float d[2][8][4];
#pragma unroll
    for (int mi = 0; mi < 2; mi++)
#pragma unroll
        for (int ni = 0; ni < 8; ni++)
#pragma unroll
            for (int k = 0; k < 4; k++) d[mi][ni][k] = 0.f;

#define YF_MMA() do {                                                           \
    _Pragma("unroll")                                                           \
    for (int k = 0; k < 4; k++) {                                               \
        const uint32_t ka = k * 32;                                             \
        const uint32_t kb = k * 16 * 144;                                       \
        uint32_t a_h[2][4], a_l[2][4];                                          \
        _Pragma("unroll")                                                       \
        for (int mi = 0; mi < 2; mi++) {                                        \
            ldsm4(a_h[mi][0], a_h[mi][1], a_h[mi][2], a_h[mi][3],               \
                  whB + aOff[mi] + ka);                                         \
            ldsm4(a_l[mi][0], a_l[mi][1], a_l[mi][2], a_l[mi][3],               \
                  wlB + aOff[mi] + ka);                                         \
        }                                                                       \
        _Pragma("unroll")                                                       \
        for (int pi = 0; pi < 4; pi++) {                                        \
            uint32_t bh[2][2], bl[2][2];                                        \
            ldsm4t(bh[0][0], bh[0][1], bh[1][0], bh[1][1],                      \
                   xhB + bOff[pi] + kb);                                        \
            ldsm4t(bl[0][0], bl[0][1], bl[1][0], bl[1][1],                      \
                   xlB + bOff[pi] + kb);                                        \
            _Pragma("unroll")                                                   \
            for (int mi = 0; mi < 2; mi++)                                      \
                _Pragma("unroll")                                               \
                for (int q = 0; q < 2; q++) {                                   \
                    mma16816(d[mi][2*pi+q], a_h[mi], bh[q]);                    \
                    mma16816(d[mi][2*pi+q], a_h[mi], bl[q]);                    \
                    mma16816(d[mi][2*pi+q], a_l[mi], bh[q]);                    \
                }                                                               \
        }                                                                       \
    }                                                                           \
} while (0)

    // ---- part 1: Y_diag, 4 s-tiles of 64 ----
    const float* CBrow = g_CB + ((size_t)bc * CHUNK + t) * CHUNK;
    for (int st = 0; st < 4; st++) {
        const int s0 = st * 64;
        // W tile (thread t = row l)
        __nv_bfloat162* wh2 = (__nv_bfloat162*)(Wh + t * 72);
        __nv_bfloat162* wl2 = (__nv_bfloat162*)(Wl + t * 72);
#pragma unroll
        for (int j = 0; j < 64; j += 4) {
            float4 cb4 = *(const float4*)(CBrow + s0 + j);
            float w[4];
            const float* cbp = (const float*)&cb4;
#pragma unroll
            for (int e = 0; e < 4; e++) {
                int s = s0 + j + e;
                float arg = fminf(acs_l - sacs[s], 0.f);
                w[e] = (s <= t) ? cbp[e] * __expf(arg) : 0.f;
            }
            __nv_bfloat162 h01, l01, h23, l23;
            split2(w[0], w[1], h01, l01);
            split2(w[2], w[3], h23, l23);
            wh2[(j >> 1) + 0] = h01; wh2[(j >> 1) + 1] = h23;
            wl2[(j >> 1) + 0] = l01; wl2[(j >> 1) + 1] = l23;
        }
        // X tile: X[s'][p] = x * dt
        {
            const int r = t >> 2, c16 = (t & 3) * 16;
            const float dts = sdt[s0 + r];
            const float* xr = g_xBC + (rowB + s0 + r) * CONVDIM + h * HEADDIM + c16;
            __nv_bfloat162* xh2 = (__nv_bfloat162*)(Xh + r * 72 + c16);
            __nv_bfloat162* xl2 = (__nv_bfloat162*)(Xl + r * 72 + c16);
#pragma unroll
            for (int j = 0; j < 16; j += 4) {
                float4 v = *(const float4*)(xr + j);
                __nv_bfloat162 h01, l01, h23, l23;
                split2(v.x * dts, v.y * dts, h01, l01);
                split2(v.z * dts, v.w * dts, h23, l23);
                xh2[(j >> 1) + 0] = h01; xh2[(j >> 1) + 1] = h23;
                xl2[(j >> 1) + 0] = l01; xl2[(j >> 1) + 1] = l23;
            }
        }
        __syncthreads();
        YF_MMA();
        __syncthreads();
    }

    // ---- part 2: Y_off, 2 n-tiles of 64 ----
    const float el = __expf(acs_l);
    const float* Crow = g_xBC + (rowB + t) * CONVDIM + DINNER + DSTATE;
    const float* S0p = g_Sinit + ((size_t)bc * NHEADS + h) * (HEADDIM * DSTATE);
    for (int nt = 0; nt < 2; nt++) {
        const int n0 = nt * 64;
        __nv_bfloat162* wh2 = (__nv_bfloat162*)(Wh + t * 72);
        __nv_bfloat162* wl2 = (__nv_bfloat162*)(Wl + t * 72);
#pragma unroll
        for (int j = 0; j < 64; j += 4) {
            float4 c4 = *(const float4*)(Crow + n0 + j);
            __nv_bfloat162 h01, l01, h23, l23;
            split2(c4.x * el, c4.y * el, h01, l01);
            split2(c4.z * el, c4.w * el, h23, l23);
            wh2[(j >> 1) + 0] = h01; wh2[(j >> 1) + 1] = h23;
            wl2[(j >> 1) + 0] = l01; wl2[(j >> 1) + 1] = l23;
        }
        // B tile: [n'][p] = Sinit[p][n0+n'] (transpose + split)
        {
            const int p = t >> 2, nb = (t & 3) * 16;
            const float* sp = S0p + (size_t)p * DSTATE + n0 + nb;
#pragma unroll
            for (int j = 0; j < 16; j++) {
                float v = sp[j];
                __nv_bfloat16 hh = __float2bfloat16(v);
                Xh[(nb + j) * 72 + p] = hh;
                Xl[(nb + j) * 72 + p] = __float2bfloat16(v - __bfloat162float(hh));
            }
        }
        __syncthreads();
        YF_MMA();
        __syncthreads();
    }
#undef YF_MMA

    // ---- epilogue: write Y once (no RMW) ----
    const int c0 = (lane & 3) * 2;
#pragma unroll
    for (int mi = 0; mi < 2; mi++) {
        const size_t gr0 = (rowB + warp * 32 + (lane >> 2) + mi * 16) * DINNER + h * HEADDIM;
#pragma unroll
        for (int ni = 0; ni < 8; ni++) {
            int col = c0 + ni * 8;
            *(float2*)&g_Y[gr0 + col] = make_float2(d[mi][ni][0], d[mi][ni][1]);
            *(float2*)&g_Y[gr0 + 8 * DINNER + col] = make_float2(d[mi][ni][2], d[mi][ni][3]);
        }
    }
}

// ---------------- split-bf16 convert kernels --------------------------------
__global__ void split_kernel(const float* __restrict__ x, __nv_bfloat16* __restrict__ hi,
                             __nv_bfloat16* __restrict__ lo, size_t n)
{
    size_t i = (size_t)blockIdx.x * blockDim.x + threadIdx.x;
    if (i >= n) return;
    float v = x[i];
    __nv_bfloat16 h = __float2bfloat16(v);
    hi[i] = h;
    lo[i] = __float2bfloat16(v - __bfloat162float(h));
}

__global__ void split_pad_kernel(const float* __restrict__ x, __nv_bfloat16* __restrict__ hi,
                                 __nv_bfloat16* __restrict__ lo, int K, int N, int Np)
{
    size_t i = (size_t)blockIdx.x * blockDim.x + threadIdx.x;
    if (i >= (size_t)K * Np) return;
    int r = (int)(i / Np), c = (int)(i % Np);
    float v = (c < N) ? x[(size_t)r * N + c] : 0.f;
    __nv_bfloat16 h = __float2bfloat16(v);
    hi[i] = h;
    lo[i] = __float2bfloat16(v - __bfloat162float(h));
}

// ---------------- causal depthwise conv1d (width 4) + SiLU -----------------
__global__ void conv_silu_kernel(const float* __restrict__ conv_w,
                                 const float* __restrict__ conv_b)
{
    int idx = blockIdx.x * blockDim.x + threadIdx.x;
    if (idx >= ROWS * CONVDIM) return;
    int c   = idx % CONVDIM;
    int row = idx / CONVDIM;
    int l   = row & (SEQLEN - 1);
    const float* base = g_zxbcdt + (size_t)row * DPROJ + DINNER + c;
    float acc = conv_b[c];
#pragma unroll
    for (int j = 0; j < DCONV; j++) {
        int ls = l - (DCONV - 1) + j;
        if (ls >= 0) acc += base[(long)(j - (DCONV - 1)) * DPROJ] * conv_w[c * DCONV + j];
    }
    g_xBC[(size_t)row * CONVDIM + c] = acc / (1.f + __expf(-acc));
}

// ---------------- dt = softplus(dt_raw + dt_bias) --------------------------
__global__ void dt_kernel(const float* __restrict__ dt_bias)
{
    int idx = blockIdx.x * blockDim.x + threadIdx.x;
    if (idx >= ROWS * NHEADS) return;
    int h   = idx & (NHEADS - 1);
    int row = idx >> 5;
    float v = g_zxbcdt[(size_t)row * DPROJ + DT_OFF + h] + dt_bias[h];
    g_dt[idx] = (v > 20.f) ? v : log1pf(expf(v));
}

// ---------------- per-chunk inclusive cumsum of a = A*dt -------------------
__global__ void ascan_kernel(const float* __restrict__ A_log)
{
    int bc = blockIdx.x;
    int h  = blockIdx.y;
    int t  = threadIdx.x;
    int b = bc >> 4, c = bc & 15;
    __shared__ float sa[CHUNK];
    int row = b * SEQLEN + c * CHUNK + t;
    float A = -expf(A_log[h]);
    sa[t] = A * g_dt[row * NHEADS + h];
    __syncthreads();
    for (int off = 1; off < CHUNK; off <<= 1) {
        float v = (t >= off) ? sa[t - off] : 0.f;
        __syncthreads();
        sa[t] += v;
        __syncthreads();
    }
    g_acs[(bc * NHEADS + h) * CHUNK + t] = sa[t];
    if (t == CHUNK - 1) g_asum[bc * NHEADS + h] = sa[t];
}

// ---------------- CB[l,s] = sum_n C[l,n] * B[s,n]  (head-independent) ------
__global__ __launch_bounds__(256) void cb_kernel()
{
    int bc = blockIdx.x;
    int lt = blockIdx.y;
    int st = blockIdx.z;
    if (st > lt) return;
    int b = bc >> 4, c = bc & 15;
    int t = threadIdx.x;
    int ty = t >> 4, tx = t & 15;
    __shared__ float Ct[32][68];
    __shared__ float Bt[32][68];
    size_t rowB = (size_t)b * SEQLEN + c * CHUNK;
    float acc[4][4];
#pragma unroll
    for (int i = 0; i < 4; i++)
#pragma unroll
        for (int j = 0; j < 4; j++) acc[i][j] = 0.f;

    for (int n0 = 0; n0 < DSTATE; n0 += 32) {
        for (int v = t; v < 512; v += 256) {
            int r = v >> 3, n4 = v & 7;
            float4 cv = *(const float4*)(g_xBC + (rowB + lt*64 + r) * CONVDIM
                                         + (DINNER + DSTATE) + n0 + n4*4);
            Ct[n4*4+0][r]=cv.x; Ct[n4*4+1][r]=cv.y; Ct[n4*4+2][r]=cv.z; Ct[n4*4+3][r]=cv.w;
            float4 bvv = *(const float4*)(g_xBC + (rowB + st*64 + r) * CONVDIM
                                          + DINNER + n0 + n4*4);
            Bt[n4*4+0][r]=bvv.x; Bt[n4*4+1][r]=bvv.y; Bt[n4*4+2][r]=bvv.z; Bt[n4*4+3][r]=bvv.w;
        }
        __syncthreads();
#pragma unroll
        for (int n = 0; n < 32; n++) {
            float4 ca = *(const float4*)&Ct[n][ty*4];
            float4 bb = *(const float4*)&Bt[n][tx*4];
            float ra[4] = {ca.x, ca.y, ca.z, ca.w};
            float rb[4] = {bb.x, bb.y, bb.z, bb.w};
#pragma unroll
            for (int i = 0; i < 4; i++)
#pragma unroll
                for (int j = 0; j < 4; j++) acc[i][j] += ra[i] * rb[j];
        }
        __syncthreads();
    }
#pragma unroll
    for (int i = 0; i < 4; i++) {
        int l = lt*64 + ty*4 + i;
        float4 o = make_float4(acc[i][0], acc[i][1], acc[i][2], acc[i][3]);
        *(float4*)(g_CB + ((size_t)bc * CHUNK + l) * CHUNK + st*64 + tx*4) = o;
    }
}

// ---------------- per-chunk state S[p,n] -----------------------------------
__global__ __launch_bounds__(256, 1) void state_kernel()
{
    int bc = blockIdx.x, h = blockIdx.y;
    int b = bc >> 4, c = bc & 15;
    int t = threadIdx.x;
    __shared__ float Bs[64][132];
    __shared__ float warr[64];
    size_t rowB = (size_t)b * SEQLEN + c * CHUNK;
    float asum = g_asum[bc * NHEADS + h];
    int p  = t >> 2;
    int nq = (t & 3) * 4;
    const float* xptr = g_xBC + rowB * CONVDIM + h * HEADDIM + p;
    float4 acc4[8];
#pragma unroll
    for (int i = 0; i < 8; i++) acc4[i] = make_float4(0.f, 0.f, 0.f, 0.f);

    for (int stile = 0; stile < CHUNK; stile += 64) {
        {
            int r = t >> 2, qq = (t & 3) * 32;
            const float4* src = (const float4*)(g_xBC + (rowB + stile + r) * CONVDIM
                                                + DINNER + qq);
#pragma unroll
            for (int i = 0; i < 8; i++)
                *(float4*)&Bs[r][qq + i*4] = src[i];
        }
        if (t < 64) {
            int gl = stile + t;
            warr[t] = g_dt[(rowB + gl) * NHEADS + h] *
                      __expf(asum - g_acs[((size_t)bc * NHEADS + h) * CHUNK + gl]);
        }
        __syncthreads();
        for (int s = 0; s < 64; s++) {
            float xv = __ldg(xptr + (size_t)(stile + s) * CONVDIM) * warr[s];
#pragma unroll
            for (int i = 0; i < 8; i++) {
                float4 bv = *(const float4*)&Bs[s][nq + 16*i];
                acc4[i].x += xv * bv.x;
                acc4[i].y += xv * bv.y;
                acc4[i].z += xv * bv.z;
                acc4[i].w += xv * bv.w;
            }
        }
        __syncthreads();
    }
    float* Sout = g_S + (((size_t)bc * NHEADS + h) * HEADDIM + p) * DSTATE;
#pragma unroll
    for (int i = 0; i < 8; i++)
        *(float4*)(Sout + nq + 16*i) = acc4[i];
}

// ---------------- sequential inter-chunk recurrence ------------------------
__global__ void chunkrec_kernel()
{
    int b = blockIdx.x, h = blockIdx.y;
    int t = threadIdx.x;
    float cur[32];
#pragma unroll
    for (int k = 0; k < 32; k++) cur[k] = 0.f;
    for (int c = 0; c < NCHUNK; c++) {
        int bc = b * NCHUNK + c;
        size_t base = ((size_t)bc * NHEADS + h) * (HEADDIM * DSTATE);
        float dd = __expf(g_asum[bc * NHEADS + h]);
#pragma unroll
        for (int k = 0; k < 32; k++) {
            size_t e = base + t + 256 * k;
            g_Sinit[e] = cur[k];
            cur[k] = cur[k] * dd + g_S[e];
        }
    }
}

// ---------------- layernorm + z-gate -> split bf16 yg ----------------------
__global__ __launch_bounds__(256) void normgate_kernel(const float* __restrict__ norm_w)
{
    int row = blockIdx.x;
    int t = threadIdx.x;
    const float* yrow = g_Y + (size_t)row * DINNER;
    const float* zrow = g_zxbcdt + (size_t)row * DPROJ;
    float v[8];
    float s = 0.f;
#pragma unroll
    for (int i = 0; i < 8; i++) { v[i] = yrow[t + 256*i]; s += v[i]; }
    __shared__ float red[256];
    red[t] = s; __syncthreads();
    for (int o = 128; o > 0; o >>= 1) { if (t < o) red[t] += red[t+o]; __syncthreads(); }
    float mu = red[0] * (1.f / DINNER);
    __syncthreads();
    float s2 = 0.f;
#pragma unroll
    for (int i = 0; i < 8; i++) { float dv = v[i] - mu; s2 += dv * dv; }
    red[t] = s2; __syncthreads();
    for (int o = 128; o > 0; o >>= 1) { if (t < o) red[t] += red[t+o]; __syncthreads(); }
    float inv = rsqrtf(red[0] * (1.f / DINNER) + 1e-5f);
    __nv_bfloat16* oh = g_ygh + (size_t)row * DINNER;
    __nv_bfloat16* ol = g_ygl + (size_t)row * DINNER;
#pragma unroll
    for (int i = 0; i < 8; i++) {
        int idx = t + 256*i;
        float z = zrow[idx];
        float g = z / (1.f + __expf(-z));
        float o = (v[i] - mu) * inv * norm_w[idx] * g;
        __nv_bfloat16 h = __float2bfloat16(o);
        oh[idx] = h;
        ol[idx] = __float2bfloat16(o - __bfloat162float(h));
    }
}

// ---------------- launch ---------------------------------------------------
extern "C" void kernel_launch(void* const* d_in, const int* in_sizes, int n_in,
                              void* d_out, int out_size)
{
    const float* u       = (const float*)d_in[0];
    const float* W_in    = (const float*)d_in[1];
    const float* conv_w  = (const float*)d_in[2];
    const float* conv_b  = (const float*)d_in[3];
    const float* dt_bias = (const float*)d_in[4];
    const float* A_log   = (const float*)d_in[5];
    const float* norm_w  = (const float*)d_in[6];
    const float* W_out   = (const float*)d_in[7];
    float* out = (float*)d_out;

    float* p_zx = nullptr;
    __nv_bfloat16 *p_uh, *p_ul, *p_wih, *p_wil, *p_woh, *p_wol, *p_ygh, *p_ygl;
    cudaGetSymbolAddress((void**)&p_zx,  g_zxbcdt);
    cudaGetSymbolAddress((void**)&p_uh,  g_uh);
    cudaGetSymbolAddress((void**)&p_ul,  g_ul);
    cudaGetSymbolAddress((void**)&p_wih, g_wih);
    cudaGetSymbolAddress((void**)&p_wil, g_wil);
    cudaGetSymbolAddress((void**)&p_woh, g_woh);
    cudaGetSymbolAddress((void**)&p_wol, g_wol);
    cudaGetSymbolAddress((void**)&p_ygh, g_ygh);
    cudaGetSymbolAddress((void**)&p_ygl, g_ygl);

    cudaFuncSetAttribute(mma_gemm, cudaFuncAttributeMaxDynamicSharedMemorySize, GEMM_SMEM);
    cudaFuncSetAttribute(yfused_kernel, cudaFuncAttributeMaxDynamicSharedMemorySize, YF_SMEM);

    // 0. split-bf16 conversions
    {
        size_t n = (size_t)ROWS * DMODEL;
        split_kernel<<<(unsigned)((n + 255) / 256), 256>>>(u, p_uh, p_ul, n);
    }
    split_pad_kernel<<<(unsigned)(((size_t)DMODEL * NPAD1 + 255) / 256), 256>>>(
        W_in, p_wih, p_wil, DMODEL, DPROJ, NPAD1);
    {
        size_t n = (size_t)DINNER * DMODEL;
        split_kernel<<<(unsigned)((n + 255) / 256), 256>>>(W_out, p_woh, p_wol, n);
    }

    // 1. zxbcdt = u @ W_in  (8192 x 4384 x 1024)
    mma_gemm<<<dim3(NPAD1 / 64, ROWS / 128), 256, GEMM_SMEM>>>(
        p_uh, p_ul, p_wih, p_wil, p_zx, ROWS, DPROJ, DMODEL, NPAD1, DPROJ);
    // 2. causal conv1d + SiLU
    conv_silu_kernel<<<(ROWS * CONVDIM + 255) / 256, 256>>>(conv_w, conv_b);
    // 3. dt softplus
    dt_kernel<<<(ROWS * NHEADS + 255) / 256, 256>>>(dt_bias);
    // 4. per-chunk cumsum of A*dt
    ascan_kernel<<<dim3(NBC, NHEADS), CHUNK>>>(A_log);
    // 5. head-independent CB gram matrices
    cb_kernel<<<dim3(NBC, 4, 4), 256>>>();
    // 6. per-chunk end states
    state_kernel<<<dim3(NBC, NHEADS), 256>>>();
    // 7. inter-chunk recurrence
    chunkrec_kernel<<<dim3(BATCH, NHEADS), 256>>>();
    // 8. fused Y_diag + Y_off (tensor cores)
    yfused_kernel<<<dim3(NBC, NHEADS), 256, YF_SMEM>>>();
    // 9. layernorm + silu(z) gate -> split bf16
    normgate_kernel<<<ROWS, 256>>>(norm_w);
    // 10. out = yg @ W_out  (8192 x 1024 x 2048)
    mma_gemm<<<dim3(DMODEL / 64, ROWS / 128), 256, GEMM_SMEM>>>(
        p_ygh, p_ygl, p_woh, p_wol, out, ROWS, DMODEL, DINNER, DMODEL, DMODEL);
}

// round 8
// speedup vs baseline: 2.5370x; 1.2473x over previous
#include <cuda_runtime.h>
#include <cuda_bf16.h>
#include <cuda_fp16.h>
#include <math.h>
#include <stdint.h>

#define BATCH   2
#define SEQLEN  4096
#define DMODEL  1024
#define DINNER  2048
#define HEADDIM 64
#define NHEADS  32
#define DSTATE  128
#define DCONV   4
#define CHUNK   256
#define NCHUNK  (SEQLEN / CHUNK)   // 16
#define NBC     (BATCH * NCHUNK)   // 32
#define DPROJ   4384               // 2*DINNER + 2*DSTATE + NHEADS
#define CONVDIM 2304               // DINNER + 2*DSTATE
#define DT_OFF  4352               // 2*DINNER + 2*DSTATE
#define ROWS    (BATCH * SEQLEN)   // 8192
#define NPAD1   4480               // DPROJ padded to multiple of 64

// ---------------- scratch (device globals; no allocation allowed) ----------
__device__ float g_zxbcdt[(size_t)ROWS * DPROJ];
__device__ float g_xBC[(size_t)ROWS * CONVDIM];
__device__ float g_dt[ROWS * NHEADS];
__device__ float g_acs[NBC * NHEADS * CHUNK];
__device__ float g_asum[NBC * NHEADS];
__device__ float g_CB[(size_t)NBC * CHUNK * CHUNK];
__device__ float g_Y[(size_t)ROWS * DINNER];
__device__ float g_S[(size_t)NBC * NHEADS * HEADDIM * DSTATE];
__device__ float g_Sinit[(size_t)NBC * NHEADS * HEADDIM * DSTATE];

// fp16 GEMM operands: activations single, weights hi/lo split
__device__ __half g_uf[(size_t)ROWS * DMODEL];
__device__ __half g_wih[(size_t)DMODEL * NPAD1];
__device__ __half g_wil[(size_t)DMODEL * NPAD1];
__device__ __half g_woh[(size_t)DINNER * DMODEL];
__device__ __half g_wol[(size_t)DINNER * DMODEL];
__device__ __half g_yg[(size_t)ROWS * DINNER];

// ---------------- helpers ---------------------------------------------------
__device__ __forceinline__ uint32_t s2u(const void* p) {
    return (uint32_t)__cvta_generic_to_shared(p);
}
#define CP16(dst, src) \
    asm volatile("cp.async.cg.shared.global [%0], [%1], 16;\n" :: "r"(dst), "l"(src))
#define CP_COMMIT() asm volatile("cp.async.commit_group;\n")
#define CP_WAIT1()  asm volatile("cp.async.wait_group 1;\n")

__device__ __forceinline__ void ldsm4(uint32_t& r0, uint32_t& r1, uint32_t& r2,
                                      uint32_t& r3, uint32_t addr) {
    asm volatile("ldmatrix.sync.aligned.m8n8.x4.shared.b16 {%0,%1,%2,%3}, [%4];"
                 : "=r"(r0), "=r"(r1), "=r"(r2), "=r"(r3) : "r"(addr));
}
__device__ __forceinline__ void ldsm4t(uint32_t& r0, uint32_t& r1, uint32_t& r2,
                                       uint32_t& r3, uint32_t addr) {
    asm volatile("ldmatrix.sync.aligned.m8n8.x4.trans.shared.b16 {%0,%1,%2,%3}, [%4];"
                 : "=r"(r0), "=r"(r1), "=r"(r2), "=r"(r3) : "r"(addr));
}
// fp16 mma
__device__ __forceinline__ void mma16816h(float* d, const uint32_t* a, const uint32_t* b) {
    asm volatile(
        "mma.sync.aligned.m16n8k16.row.col.f32.f16.f16.f32 "
        "{%0,%1,%2,%3}, {%4,%5,%6,%7}, {%8,%9}, {%0,%1,%2,%3};"
        : "+f"(d[0]), "+f"(d[1]), "+f"(d[2]), "+f"(d[3])
        : "r"(a[0]), "r"(a[1]), "r"(a[2]), "r"(a[3]), "r"(b[0]), "r"(b[1]));
}
// bf16 mma (yfused)
__device__ __forceinline__ void mma16816(float* d, const uint32_t* a, const uint32_t* b) {
    asm volatile(
        "mma.sync.aligned.m16n8k16.row.col.f32.bf16.bf16.f32 "
        "{%0,%1,%2,%3}, {%4,%5,%6,%7}, {%8,%9}, {%0,%1,%2,%3};"
        : "+f"(d[0]), "+f"(d[1]), "+f"(d[2]), "+f"(d[3])
        : "r"(a[0]), "r"(a[1]), "r"(a[2]), "r"(a[3]), "r"(b[0]), "r"(b[1]));
}
__device__ __forceinline__ void split2(float a, float b,
                                       __nv_bfloat162& h, __nv_bfloat162& l) {
    __nv_bfloat16 ha = __float2bfloat16(a), hb = __float2bfloat16(b);
    h = __halves2bfloat162(ha, hb);
    l = __halves2bfloat162(__float2bfloat16(a - __bfloat162float(ha)),
                           __float2bfloat16(b - __bfloat162float(hb)));
}

// ---------------- GEMM smem layout (bytes), tile 128x64, BK=32 --------------
// per stage: A[128][40] | Bh[32][72] | Bl[32][72]   (fp16)
#define A_B        10240         // 128*40*2
#define B_HALF_B   4608          // 32*72*2
#define OFF_BH     A_B
#define OFF_BL     (A_B + B_HALF_B)
#define STAGE_B    (A_B + 2 * B_HALF_B)            // 19456
#define NSTAGE     3
#define GEMM_SMEM  (NSTAGE * STAGE_B)              // 58368

// ---------------- fp16 2-term tensor-core GEMM (2 CTAs/SM, BK=32) -----------
// C[M,N] = A[M,K] * (Bh+Bl)[K,N]. 128x64 block, BK=32, 256 threads
// (8 warps, 4x2), warp tile 32x32, 3-stage cp.async ring.
__global__ __launch_bounds__(256, 2) void mma_gemm(
    const __half* __restrict__ A,
    const __half* __restrict__ Bh, const __half* __restrict__ Bl,
    float* __restrict__ C, int M, int N, int K, int ldb, int ldc)
{
    extern __shared__ __half smem[];
    const uint32_t sbase = s2u(smem);
    const int rowBase = blockIdx.y * 128;
    const int colBase = blockIdx.x * 64;
    const int t = threadIdx.x;

    const int ar = t >> 2, aq = t & 3;
    const __half* aS = A + (size_t)(rowBase + ar) * K + aq * 8;
    const uint32_t aD = sbase + (ar * 40 + aq * 8) * 2;
    const int brr = t >> 3, bq = t & 7;
    const __half* bSh = Bh + (size_t)brr * ldb + colBase + bq * 8;
    const __half* bSl = Bl + (size_t)brr * ldb + colBase + bq * 8;
    const uint32_t bD = sbase + OFF_BH + (brr * 72 + bq * 8) * 2;

    const int lane = t & 31, warp = t >> 5;
    const int wm = warp >> 1, wn = warp & 1;
    const int grp = lane >> 3, rr = lane & 7;

    uint32_t aAddr[2], bAddr[2];
#pragma unroll
    for (int mi = 0; mi < 2; mi++)
        aAddr[mi] = sbase + ((wm * 32 + mi * 16 + (grp & 1) * 8 + rr) * 40
                             + (grp >> 1) * 8) * 2;
#pragma unroll
    for (int pi = 0; pi < 2; pi++)
        bAddr[pi] = sbase + OFF_BH + (((grp & 1) * 8 + rr) * 72
                             + wn * 32 + pi * 16 + (grp >> 1) * 8) * 2;

    float d[2][4][4];
#pragma unroll
    for (int mi = 0; mi < 2; mi++)
#pragma unroll
        for (int ni = 0; ni < 4; ni++)
#pragma unroll
            for (int k = 0; k < 4; k++) d[mi][ni][k] = 0.f;

    const int nk = K / 32;

#define LOAD_SLAB(st, kt) do {                                                  \
    const uint32_t _d = (st) * STAGE_B;                                         \
    const int _k = (kt) * 32;                                                   \
    CP16(aD + _d, aS + _k);                                                     \
    CP16(aD + _d + 64 * 40 * 2, aS + (size_t)64 * K + _k);                      \
    CP16(bD + _d, bSh + (size_t)_k * ldb);                                      \
    CP16(bD + _d + B_HALF_B, bSl + (size_t)_k * ldb);                           \
} while (0)

#define FRAGS_MMA(sd, koff_a, koff_b) do {                                      \
    uint32_t a_f[2][4], b_h[4][2], b_l[4][2];                                   \
    _Pragma("unroll")                                                           \
    for (int mi = 0; mi < 2; mi++)                                              \
        ldsm4(a_f[mi][0], a_f[mi][1], a_f[mi][2], a_f[mi][3],                   \
              aAddr[mi] + (sd) + (koff_a));                                     \
    _Pragma("unroll")                                                           \
    for (int pi = 0; pi < 2; pi++) {                                            \
        ldsm4t(b_h[2*pi][0], b_h[2*pi][1], b_h[2*pi+1][0], b_h[2*pi+1][1],      \
               bAddr[pi] + (sd) + (koff_b));                                    \
        ldsm4t(b_l[2*pi][0], b_l[2*pi][1], b_l[2*pi+1][0], b_l[2*pi+1][1],      \
               bAddr[pi] + (sd) + (koff_b) + B_HALF_B);                         \
    }                                                                           \
    _Pragma("unroll")                                                           \
    for (int mi = 0; mi < 2; mi++)                                              \
        _Pragma("unroll")                                                       \
        for (int ni = 0; ni < 4; ni++) {                                        \
            mma16816h(d[mi][ni], a_f[mi], b_h[ni]);                             \
            mma16816h(d[mi][ni], a_f[mi], b_l[ni]);                             \
        }                                                                       \
} while (0)

    LOAD_SLAB(0, 0); CP_COMMIT();
    LOAD_SLAB(1, 1); CP_COMMIT();
    CP_WAIT1();
    __syncthreads();

    for (int kt = 0; kt < nk; kt++) {
        const uint32_t sd = (uint32_t)(kt % 3) * STAGE_B;
        if (kt + 2 < nk) LOAD_SLAB((kt + 2) % 3, kt + 2);
        CP_COMMIT();
        FRAGS_MMA(sd, 0, 0);
        FRAGS_MMA(sd, 32, 16 * 72 * 2);
        if (kt + 1 < nk) {
            CP_WAIT1();
            __syncthreads();
        }
    }

    const int r0 = rowBase + wm * 32 + (lane >> 2);
    const int c0 = colBase + wn * 32 + (lane & 3) * 2;
#pragma unroll
    for (int mi = 0; mi < 2; mi++)
#pragma unroll
        for (int ni = 0; ni < 4; ni++) {
            int col = c0 + ni * 8;
            if (col < N) {
                float2 v0 = make_float2(d[mi][ni][0], d[mi][ni][1]);
                float2 v1 = make_float2(d[mi][ni][2], d[mi][ni][3]);
                *(float2*)&C[(size_t)(r0 + mi * 16) * ldc + col] = v0;
                *(float2*)&C[(size_t)(r0 + mi * 16 + 8) * ldc + col] = v1;
            }
        }
#undef LOAD_SLAB
#undef FRAGS_MMA
}

// ---------------- fused Y = (CB.L)X + exp(acs) C Sinit (bf16 3-term) --------
#define YF_WH    0
#define YF_WL    36864               // 256*72*2
#define YF_XH    73728
#define YF_XL    82944               // + 64*72*2
#define YF_ACS   92160
#define YF_DT    93184
#define YF_SMEM  94208

__global__ __launch_bounds__(256, 2) void yfused_kernel()
{
    extern __shared__ char ysm[];
    __nv_bfloat16* Wh = (__nv_bfloat16*)(ysm + YF_WH);
    __nv_bfloat16* Wl = (__nv_bfloat16*)(ysm + YF_WL);
    __nv_bfloat16* Xh = (__nv_bfloat16*)(ysm + YF_XH);
    __nv_bfloat16* Xl = (__nv_bfloat16*)(ysm + YF_XL);
    float* sacs = (float*)(ysm + YF_ACS);
    float* sdt  = (float*)(ysm + YF_DT);

    const int bc = blockIdx.x, h = blockIdx.y;
    const int b = bc >> 4, c = bc & 15;
    const int t = threadIdx.x;
    const size_t rowB = (size_t)b * SEQLEN + c * CHUNK;

    sacs[t] = g_acs[((size_t)bc * NHEADS + h) * CHUNK + t];
    sdt[t]  = g_dt[(rowB + t) * NHEADS + h];
    __syncthreads();
    const float acs_l = sacs[t];

    const int lane = t & 31, warp = t >> 5;
    const int grp = lane >> 3, rr = lane & 7;
    const uint32_t whB = s2u(Wh), wlB = s2u(Wl), xhB = s2u(Xh), xlB = s2u(Xl);

    uint32_t aOff[2], bOff[4];
#pragma unroll
    for (int mi = 0; mi < 2; mi++)
        aOff[mi] = ((warp * 32 + mi * 16 + (grp & 1) * 8 + rr) * 72
                    + (grp >> 1) * 8) * 2;
#pragma unroll
    for (int pi = 0; pi < 4; pi++)
        bOff[pi] = (((grp & 1) * 8 + rr) * 72 + pi * 16 + (grp >> 1) * 8) * 2;

    float d[2][8][4];
#pragma unroll
    for (int mi = 0; mi < 2; mi++)
#pragma unroll
        for (int ni = 0; ni < 8; ni++)
#pragma unroll
            for (int k = 0; k < 4; k++) d[mi][ni][k] = 0.f;

#define YF_MMA() do {                                                           \
    _Pragma("unroll")                                                           \
    for (int k = 0; k < 4; k++) {                                               \
        const uint32_t ka = k * 32;                                             \
        const uint32_t kb = k * 16 * 144;                                       \
        uint32_t a_h[2][4], a_l[2][4];                                          \
        _Pragma("unroll")                                                       \
        for (int mi = 0; mi < 2; mi++) {                                        \
            ldsm4(a_h[mi][0], a_h[mi][1], a_h[mi][2], a_h[mi][3],               \
                  whB + aOff[mi] + ka);                                         \
            ldsm4(a_l[mi][0], a_l[mi][1], a_l[mi][2], a_l[mi][3],               \
                  wlB + aOff[mi] + ka);                                         \
        }                                                                       \
        _Pragma("unroll")                                                       \
        for (int pi = 0; pi < 4; pi++) {                                        \
            uint32_t bh[2][2], bl[2][2];                                        \
            ldsm4t(bh[0][0], bh[0][1], bh[1][0], bh[1][1],                      \
                   xhB + bOff[pi] + kb);                                        \
            ldsm4t(bl[0][0], bl[0][1], bl[1][0], bl[1][1],                      \
                   xlB + bOff[pi] + kb);                                        \
            _Pragma("unroll")                                                   \
            for (int mi = 0; mi < 2; mi++)                                      \
                _Pragma("unroll")                                               \
                for (int q = 0; q < 2; q++) {                                   \
                    mma16816(d[mi][2*pi+q], a_h[mi], bh[q]);                    \
                    mma16816(d[mi][2*pi+q], a_h[mi], bl[q]);                    \
                    mma16816(d[mi][2*pi+q], a_l[mi], bh[q]);                    \
                }                                                               \
        }                                                                       \
    }                                                                           \
} while (0)

    // ---- part 1: Y_diag, 4 s-tiles of 64 ----
    const float* CBrow = g_CB + ((size_t)bc * CHUNK + t) * CHUNK;
    for (int st = 0; st < 4; st++) {
        const int s0 = st * 64;
        __nv_bfloat162* wh2 = (__nv_bfloat162*)(Wh + t * 72);
        __nv_bfloat162* wl2 = (__nv_bfloat162*)(Wl + t * 72);
#pragma unroll
        for (int j = 0; j < 64; j += 4) {
            float4 cb4 = *(const float4*)(CBrow + s0 + j);
            float w[4];
            const float* cbp = (const float*)&cb4;
#pragma unroll
            for (int e = 0; e < 4; e++) {
                int s = s0 + j + e;
                float arg = fminf(acs_l - sacs[s], 0.f);
                w[e] = (s <= t) ? cbp[e] * __expf(arg) : 0.f;
            }
            __nv_bfloat162 h01, l01, h23, l23;
            split2(w[0], w[1], h01, l01);
            split2(w[2], w[3], h23, l23);
            wh2[(j >> 1) + 0] = h01; wh2[(j >> 1) + 1] = h23;
            wl2[(j >> 1) + 0] = l01; wl2[(j >> 1) + 1] = l23;
        }
        {
            const int r = t >> 2, c16 = (t & 3) * 16;
            const float dts = sdt[s0 + r];
            const float* xr = g_xBC + (rowB + s0 + r) * CONVDIM + h * HEADDIM + c16;
            __nv_bfloat162* xh2 = (__nv_bfloat162*)(Xh + r * 72 + c16);
            __nv_bfloat162* xl2 = (__nv_bfloat162*)(Xl + r * 72 + c16);
#pragma unroll
            for (int j = 0; j < 16; j += 4) {
                float4 v = *(const float4*)(xr + j);
                __nv_bfloat162 h01, l01, h23, l23;
                split2(v.x * dts, v.y * dts, h01, l01);
                split2(v.z * dts, v.w * dts, h23, l23);
                xh2[(j >> 1) + 0] = h01; xh2[(j >> 1) + 1] = h23;
                xl2[(j >> 1) + 0] = l01; xl2[(j >> 1) + 1] = l23;
            }
        }
        __syncthreads();
        YF_MMA();
        __syncthreads();
    }

    // ---- part 2: Y_off, 2 n-tiles of 64 ----
    const float el = __expf(acs_l);
    const float* Crow = g_xBC + (rowB + t) * CONVDIM + DINNER + DSTATE;
    const float* S0p = g_Sinit + ((size_t)bc * NHEADS + h) * (HEADDIM * DSTATE);
    for (int nt = 0; nt < 2; nt++) {
        const int n0 = nt * 64;
        __nv_bfloat162* wh2 = (__nv_bfloat162*)(Wh + t * 72);
        __nv_bfloat162* wl2 = (__nv_bfloat162*)(Wl + t * 72);
#pragma unroll
        for (int j = 0; j < 64; j += 4) {
            float4 c4 = *(const float4*)(Crow + n0 + j);
            __nv_bfloat162 h01, l01, h23, l23;
            split2(c4.x * el, c4.y * el, h01, l01);
            split2(c4.z * el, c4.w * el, h23, l23);
            wh2[(j >> 1) + 0] = h01; wh2[(j >> 1) + 1] = h23;
            wl2[(j >> 1) + 0] = l01; wl2[(j >> 1) + 1] = l23;
        }
        {
            const int p = t >> 2, nb = (t & 3) * 16;
            const float* sp = S0p + (size_t)p * DSTATE + n0 + nb;
#pragma unroll
            for (int j = 0; j < 16; j++) {
                float v = sp[j];
                __nv_bfloat16 hh = __float2bfloat16(v);
                Xh[(nb + j) * 72 + p] = hh;
                Xl[(nb + j) * 72 + p] = __float2bfloat16(v - __bfloat162float(hh));
            }
        }
        __syncthreads();
        YF_MMA();
        __syncthreads();
    }
#undef YF_MMA

    const int c0 = (lane & 3) * 2;
#pragma unroll
    for (int mi = 0; mi < 2; mi++) {
        const size_t gr0 = (rowB + warp * 32 + (lane >> 2) + mi * 16) * DINNER + h * HEADDIM;
#pragma unroll
        for (int ni = 0; ni < 8; ni++) {
            int col = c0 + ni * 8;
            *(float2*)&g_Y[gr0 + col] = make_float2(d[mi][ni][0], d[mi][ni][1]);
            *(float2*)&g_Y[gr0 + 8 * DINNER + col] = make_float2(d[mi][ni][2], d[mi][ni][3]);
        }
    }
}

// ---------------- convert kernels -------------------------------------------
__global__ void tofp16_kernel(const float* __restrict__ x, __half* __restrict__ o, size_t n)
{
    size_t i = (size_t)blockIdx.x * blockDim.x + threadIdx.x;
    if (i >= n) return;
    o[i] = __float2half(x[i]);
}

__global__ void splitf16_kernel(const float* __restrict__ x, __half* __restrict__ hi,
                                __half* __restrict__ lo, size_t n)
{
    size_t i = (size_t)blockIdx.x * blockDim.x + threadIdx.x;
    if (i >= n) return;
    float v = x[i];
    __half h = __float2half(v);
    hi[i] = h;
    lo[i] = __float2half(v - __half2float(h));
}

__global__ void splitf16_pad_kernel(const float* __restrict__ x, __half* __restrict__ hi,
                                    __half* __restrict__ lo, int K, int N, int Np)
{
    size_t i = (size_t)blockIdx.x * blockDim.x + threadIdx.x;
    if (i >= (size_t)K * Np) return;
    int r = (int)(i / Np), c = (int)(i % Np);
    float v = (c < N) ? x[(size_t)r * N + c] : 0.f;
    __half h = __float2half(v);
    hi[i] = h;
    lo[i] = __float2half(v - __half2float(h));
}

// ---------------- causal depthwise conv1d (width 4) + SiLU -----------------
__global__ void conv_silu_kernel(const float* __restrict__ conv_w,
                                 const float* __restrict__ conv_b)
{
    int idx = blockIdx.x * blockDim.x + threadIdx.x;
    if (idx >= ROWS * CONVDIM) return;
    int c   = idx % CONVDIM;
    int row = idx / CONVDIM;
    int l   = row & (SEQLEN - 1);
    const float* base = g_zxbcdt + (size_t)row * DPROJ + DINNER + c;
    float acc = conv_b[c];
#pragma unroll
    for (int j = 0; j < DCONV; j++) {
        int ls = l - (DCONV - 1) + j;
        if (ls >= 0) acc += base[(long)(j - (DCONV - 1)) * DPROJ] * conv_w[c * DCONV + j];
    }
    g_xBC[(size_t)row * CONVDIM + c] = acc / (1.f + __expf(-acc));
}

// ---------------- dt = softplus(dt_raw + dt_bias) --------------------------
__global__ void dt_kernel(const float* __restrict__ dt_bias)
{
    int idx = blockIdx.x * blockDim.x + threadIdx.x;
    if (idx >= ROWS * NHEADS) return;
    int h   = idx & (NHEADS - 1);
    int row = idx >> 5;
    float v = g_zxbcdt[(size_t)row * DPROJ + DT_OFF + h] + dt_bias[h];
    g_dt[idx] = (v > 20.f) ? v : log1pf(expf(v));
}

// ---------------- per-chunk inclusive cumsum of a = A*dt -------------------
__global__ void ascan_kernel(const float* __restrict__ A_log)
{
    int bc = blockIdx.x;
    int h  = blockIdx.y;
    int t  = threadIdx.x;
    int b = bc >> 4, c = bc & 15;
    __shared__ float sa[CHUNK];
    int row = b * SEQLEN + c * CHUNK + t;
    float A = -expf(A_log[h]);
    sa[t] = A * g_dt[row * NHEADS + h];
    __syncthreads();
    for (int off = 1; off < CHUNK; off <<= 1) {
        float v = (t >= off) ? sa[t - off] : 0.f;
        __syncthreads();
        sa[t] += v;
        __syncthreads();
    }
    g_acs[(bc * NHEADS + h) * CHUNK + t] = sa[t];
    if (t == CHUNK - 1) g_asum[bc * NHEADS + h] = sa[t];
}

// ---------------- CB[l,s] = sum_n C[l,n] * B[s,n]  (head-independent) ------
__global__ __launch_bounds__(256) void cb_kernel()
{
    int bc = blockIdx.x;
    int lt = blockIdx.y;
    int st = blockIdx.z;
    if (st > lt) return;
    int b = bc >> 4, c = bc & 15;
    int t = threadIdx.x;
    int ty = t >> 4, tx = t & 15;
    __shared__ float Ct[32][68];
    __shared__ float Bt[32][68];
    size_t rowB = (size_t)b * SEQLEN + c * CHUNK;
    float acc[4][4];
#pragma unroll
    for (int i = 0; i < 4; i++)
#pragma unroll
        for (int j = 0; j < 4; j++) acc[i][j] = 0.f;

    for (int n0 = 0; n0 < DSTATE; n0 += 32) {
        for (int v = t; v < 512; v += 256) {
            int r = v >> 3, n4 = v & 7;
            float4 cv = *(const float4*)(g_xBC + (rowB + lt*64 + r) * CONVDIM
                                         + (DINNER + DSTATE) + n0 + n4*4);
            Ct[n4*4+0][r]=cv.x; Ct[n4*4+1][r]=cv.y; Ct[n4*4+2][r]=cv.z; Ct[n4*4+3][r]=cv.w;
            float4 bvv = *(const float4*)(g_xBC + (rowB + st*64 + r) * CONVDIM
                                          + DINNER + n0 + n4*4);
            Bt[n4*4+0][r]=bvv.x; Bt[n4*4+1][r]=bvv.y; Bt[n4*4+2][r]=bvv.z; Bt[n4*4+3][r]=bvv.w;
        }
        __syncthreads();
#pragma unroll
        for (int n = 0; n < 32; n++) {
            float4 ca = *(const float4*)&Ct[n][ty*4];
            float4 bb = *(const float4*)&Bt[n][tx*4];
            float ra[4] = {ca.x, ca.y, ca.z, ca.w};
            float rb[4] = {bb.x, bb.y, bb.z, bb.w};
#pragma unroll
            for (int i = 0; i < 4; i++)
#pragma unroll
                for (int j = 0; j < 4; j++) acc[i][j] += ra[i] * rb[j];
        }
        __syncthreads();
    }
#pragma unroll
    for (int i = 0; i < 4; i++) {
        int l = lt*64 + ty*4 + i;
        float4 o = make_float4(acc[i][0], acc[i][1], acc[i][2], acc[i][3]);
        *(float4*)(g_CB + ((size_t)bc * CHUNK + l) * CHUNK + st*64 + tx*4) = o;
    }
}

// ---------------- per-chunk state S[p,n] -----------------------------------
__global__ __launch_bounds__(256, 1) void state_kernel()
{
    int bc = blockIdx.x, h = blockIdx.y;
    int b = bc >> 4, c = bc & 15;
    int t = threadIdx.x;
    __shared__ float Bs[64][132];
    __shared__ float warr[64];
    size_t rowB = (size_t)b * SEQLEN + c * CHUNK;
    float asum = g_asum[bc * NHEADS + h];
    int p  = t >> 2;
    int nq = (t & 3) * 4;
    const float* xptr = g_xBC + rowB * CONVDIM + h * HEADDIM + p;
    float4 acc4[8];
#pragma unroll
    for (int i = 0; i < 8; i++) acc4[i] = make_float4(0.f, 0.f, 0.f, 0.f);

    for (int stile = 0; stile < CHUNK; stile += 64) {
        {
            int r = t >> 2, qq = (t & 3) * 32;
            const float4* src = (const float4*)(g_xBC + (rowB + stile + r) * CONVDIM
                                                + DINNER + qq);
#pragma unroll
            for (int i = 0; i < 8; i++)
                *(float4*)&Bs[r][qq + i*4] = src[i];
        }
        if (t < 64) {
            int gl = stile + t;
            warr[t] = g_dt[(rowB + gl) * NHEADS + h] *
                      __expf(asum - g_acs[((size_t)bc * NHEADS + h) * CHUNK + gl]);
        }
        __syncthreads();
        for (int s = 0; s < 64; s++) {
            float xv = __ldg(xptr + (size_t)(stile + s) * CONVDIM) * warr[s];
#pragma unroll
            for (int i = 0; i < 8; i++) {
                float4 bv = *(const float4*)&Bs[s][nq + 16*i];
                acc4[i].x += xv * bv.x;
                acc4[i].y += xv * bv.y;
                acc4[i].z += xv * bv.z;
                acc4[i].w += xv * bv.w;
            }
        }
        __syncthreads();
    }
    float* Sout = g_S + (((size_t)bc * NHEADS + h) * HEADDIM + p) * DSTATE;
#pragma unroll
    for (int i = 0; i < 8; i++)
        *(float4*)(Sout + nq + 16*i) = acc4[i];
}

// ---------------- sequential inter-chunk recurrence ------------------------
__global__ void chunkrec_kernel()
{
    int b = blockIdx.x, h = blockIdx.y;
    int t = threadIdx.x;
    float cur[32];
#pragma unroll
    for (int k = 0; k < 32; k++) cur[k] = 0.f;
    for (int c = 0; c < NCHUNK; c++) {
        int bc = b * NCHUNK + c;
        size_t base = ((size_t)bc * NHEADS + h) * (HEADDIM * DSTATE);
        float dd = __expf(g_asum[bc * NHEADS + h]);
#pragma unroll
        for (int k = 0; k < 32; k++) {
            size_t e = base + t + 256 * k;
            g_Sinit[e] = cur[k];
            cur[k] = cur[k] * dd + g_S[e];
        }
    }
}

// ---------------- layernorm + z-gate -> fp16 yg ----------------------------
__global__ __launch_bounds__(256) void normgate_kernel(const float* __restrict__ norm_w)
{
    int row = blockIdx.x;
    int t = threadIdx.x;
    const float* yrow = g_Y + (size_t)row * DINNER;
    const float* zrow = g_zxbcdt + (size_t)row * DPROJ;
    float v[8];
    float s = 0.f;
#pragma unroll
    for (int i = 0; i < 8; i++) { v[i] = yrow[t + 256*i]; s += v[i]; }
    __shared__ float red[256];
    red[t] = s; __syncthreads();
    for (int o = 128; o > 0; o >>= 1) { if (t < o) red[t] += red[t+o]; __syncthreads(); }
    float mu = red[0] * (1.f / DINNER);
    __syncthreads();
    float s2 = 0.f;
#pragma unroll
    for (int i = 0; i < 8; i++) { float dv = v[i] - mu; s2 += dv * dv; }
    red[t] = s2; __syncthreads();
    for (int o = 128; o > 0; o >>= 1) { if (t < o) red[t] += red[t+o]; __syncthreads(); }
    float inv = rsqrtf(red[0] * (1.f / DINNER) + 1e-5f);
    __half* orow = g_yg + (size_t)row * DINNER;
#pragma unroll
    for (int i = 0; i < 8; i++) {
        int idx = t + 256*i;
        float z = zrow[idx];
        float g = z / (1.f + __expf(-z));
        orow[idx] = __float2half((v[i] - mu) * inv * norm_w[idx] * g);
    }
}

// ---------------- launch ---------------------------------------------------
extern "C" void kernel_launch(void* const* d_in, const int* in_sizes, int n_in,
                              void* d_out, int out_size)
{
    const float* u       = (const float*)d_in[0];
    const float* W_in    = (const float*)d_in[1];
    const float* conv_w  = (const float*)d_in[2];
    const float* conv_b  = (const float*)d_in[3];
    const float* dt_bias = (const float*)d_in[4];
    const float* A_log   = (const float*)d_in[5];
    const float* norm_w  = (const float*)d_in[6];
    const float* W_out   = (const float*)d_in[7];
    float* out = (float*)d_out;

    float* p_zx = nullptr;
    __half *p_uf, *p_wih, *p_wil, *p_woh, *p_wol, *p_yg;
    cudaGetSymbolAddress((void**)&p_zx,  g_zxbcdt);
    cudaGetSymbolAddress((void**)&p_uf,  g_uf);
    cudaGetSymbolAddress((void**)&p_wih, g_wih);
    cudaGetSymbolAddress((void**)&p_wil, g_wil);
    cudaGetSymbolAddress((void**)&p_woh, g_woh);
    cudaGetSymbolAddress((void**)&p_wol, g_wol);
    cudaGetSymbolAddress((void**)&p_yg,  g_yg);

    cudaFuncSetAttribute(mma_gemm, cudaFuncAttributeMaxDynamicSharedMemorySize, GEMM_SMEM);
    cudaFuncSetAttribute(yfused_kernel, cudaFuncAttributeMaxDynamicSharedMemorySize, YF_SMEM);

    // 0. fp16 conversions
    {
        size_t n = (size_t)ROWS * DMODEL;
        tofp16_kernel<<<(unsigned)((n + 255) / 256), 256>>>(u, p_uf, n);
    }
    splitf16_pad_kernel<<<(unsigned)(((size_t)DMODEL * NPAD1 + 255) / 256), 256>>>(
        W_in, p_wih, p_wil, DMODEL, DPROJ, NPAD1);
    {
        size_t n = (size_t)DINNER * DMODEL;
        splitf16_kernel<<<(unsigned)((n + 255) / 256), 256>>>(W_out, p_woh, p_wol, n);
    }

    // 1. zxbcdt = u @ W_in  (8192 x 4384 x 1024)
    mma_gemm<<<dim3(NPAD1 / 64, ROWS / 128), 256, GEMM_SMEM>>>(
        p_uf, p_wih, p_wil, p_zx, ROWS, DPROJ, DMODEL, NPAD1, DPROJ);
    // 2. causal conv1d + SiLU
    conv_silu_kernel<<<(ROWS * CONVDIM + 255) / 256, 256>>>(conv_w, conv_b);
    // 3. dt softplus
    dt_kernel<<<(ROWS * NHEADS + 255) / 256, 256>>>(dt_bias);
    // 4. per-chunk cumsum of A*dt
    ascan_kernel<<<dim3(NBC, NHEADS), CHUNK>>>(A_log);
    // 5. head-independent CB gram matrices
    cb_kernel<<<dim3(NBC, 4, 4), 256>>>();
    // 6. per-chunk end states
    state_kernel<<<dim3(NBC, NHEADS), 256>>>();
    // 7. inter-chunk recurrence
    chunkrec_kernel<<<dim3(BATCH, NHEADS), 256>>>();
    // 8. fused Y_diag + Y_off (tensor cores)
    yfused_kernel<<<dim3(NBC, NHEADS), 256, YF_SMEM>>>();
    // 9. layernorm + silu(z) gate -> fp16
    normgate_kernel<<<ROWS, 256>>>(norm_w);
    // 10. out = yg @ W_out  (8192 x 1024 x 2048)
    mma_gemm<<<dim3(DMODEL / 64, ROWS / 128), 256, GEMM_SMEM>>>(
        p_yg, p_woh, p_wol, out, ROWS, DMODEL, DINNER, DMODEL, DMODEL);
}